// round 5
// baseline (speedup 1.0000x reference)
#include <cuda_runtime.h>
#include <cuda_bf16.h>
#include <cstdint>

// ---------------------------------------------------------------------------
// AttentionOverride, round 5: HMMA bf16 hi/lo everywhere (GEMMs + attention
// QK^T + AV); fp32 softmax/override. Output: [a | presentK | presentV].
// ---------------------------------------------------------------------------

namespace {
constexpr int kB  = 4;
constexpr int kS  = 1024;
constexpr int kD  = 1024;
constexpr int kH  = 16;
constexpr int kHD = 64;
constexpr int kM  = kB * kS;  // 4096

constexpr int kSTR = 40;  // GEMM smem stride (bf16)

// attention smem plan (bytes / elems)
constexpr int SST_STRIDE = 33;            // fp32 scores [1024][33]
constexpr int SST_BYTES  = kS * SST_STRIDE * 4;  // 135168
constexpr int KQ_STR = 72;                // K and Q bf16 row stride
constexpr int VP_STR = 134;               // Vt and P bf16 row stride
// bf16 region offsets (elems)
constexpr int OFF_KH = 0;                 // [128*72]=9216 (reused as sVth 64*134=8576)
constexpr int OFF_KL = 9216;              //               (reused as sVtl)
constexpr int OFF_QH = 18432;             // [32*72]=2304
constexpr int OFF_QL = 20736;
constexpr int OFF_PH = 23040;             // [32*134]=4288
constexpr int OFF_PL = 27328;
constexpr int BF_ELEMS = 31616;
constexpr int ATT_SMEM_BYTES = SST_BYTES + BF_ELEMS * 2;  // 198400
}  // namespace

// scratch (device globals; no allocation allowed)
__device__ float g_a[(size_t)kM * kD];
__device__ int   g_mask_kind;
__device__ __nv_bfloat16 g_qh[(size_t)kM * kD], g_ql[(size_t)kM * kD];
__device__ __nv_bfloat16 g_kh[(size_t)kM * kD], g_kl[(size_t)kM * kD];
__device__ __nv_bfloat16 g_vh[(size_t)kM * kD], g_vl[(size_t)kM * kD];
__device__ __nv_bfloat16 g_xh[(size_t)kM * kD], g_xl[(size_t)kM * kD];
__device__ __nv_bfloat16 g_ah[(size_t)kM * kD], g_al[(size_t)kM * kD];
__device__ __nv_bfloat16 g_wth[(size_t)3 * kD * kD], g_wtl[(size_t)3 * kD * kD];
__device__ __nv_bfloat16 g_pth[(size_t)kD * kD], g_ptl[(size_t)kD * kD];

// ---------------------------------------------------------------------------
__device__ __forceinline__ void mma16816(float* c, const uint32_t* a,
                                         uint32_t b0, uint32_t b1) {
    asm volatile(
        "mma.sync.aligned.m16n8k16.row.col.f32.bf16.bf16.f32 "
        "{%0,%1,%2,%3}, {%4,%5,%6,%7}, {%8,%9}, {%0,%1,%2,%3};"
        : "+f"(c[0]), "+f"(c[1]), "+f"(c[2]), "+f"(c[3])
        : "r"(a[0]), "r"(a[1]), "r"(a[2]), "r"(a[3]), "r"(b0), "r"(b1));
}

__device__ __forceinline__ void split2(float x, __nv_bfloat16& h, __nv_bfloat16& l) {
    h = __float2bfloat16(x);
    l = __float2bfloat16(x - __bfloat162float(h));
}

__global__ void split_kernel(const float* __restrict__ X,
                             __nv_bfloat16* __restrict__ H,
                             __nv_bfloat16* __restrict__ L, int n) {
    int i = blockIdx.x * 256 + threadIdx.x;
    if (i < n) split2(X[i], H[i], L[i]);
}

__global__ void transpose_split_kernel(const float* __restrict__ W,
                                       __nv_bfloat16* __restrict__ Th,
                                       __nv_bfloat16* __restrict__ Tl,
                                       int K, int N) {
    __shared__ float t[32][33];
    int n0 = blockIdx.x * 32, k0 = blockIdx.y * 32;
    int tx = threadIdx.x, ty = threadIdx.y;
#pragma unroll
    for (int j = 0; j < 4; ++j)
        t[ty + j * 8][tx] = W[(size_t)(k0 + ty + j * 8) * N + n0 + tx];
    __syncthreads();
#pragma unroll
    for (int j = 0; j < 4; ++j) {
        float v = t[tx][ty + j * 8];
        __nv_bfloat16 h, l;
        split2(v, h, l);
        size_t o = (size_t)(n0 + ty + j * 8) * K + k0 + tx;
        Th[o] = h;
        Tl[o] = l;
    }
}

__global__ void detect_mask_kind_kernel(const unsigned int* __restrict__ m) {
    __shared__ int any_gt1, any_not_f32;
    if (threadIdx.x == 0) { any_gt1 = 0; any_not_f32 = 0; }
    __syncthreads();
    int gt1 = 0, nf32 = 0;
    for (int i = threadIdx.x; i < 16384; i += 256) {
        unsigned int w = m[i];
        if (w > 1u) gt1 = 1;
        if (w != 0u && w != 0x3F800000u) nf32 = 1;
    }
    if (gt1)  atomicOr(&any_gt1, 1);
    if (nf32) atomicOr(&any_not_f32, 1);
    __syncthreads();
    if (threadIdx.x == 0)
        g_mask_kind = (!any_gt1) ? 1 : ((!any_not_f32) ? 2 : 0);
}

__device__ __forceinline__ bool mask_at(const void* __restrict__ mask,
                                        size_t idx, int kind) {
    if (kind == 1) return ((const int*)mask)[idx] != 0;
    if (kind == 2) return ((const float*)mask)[idx] != 0.0f;
    return ((const unsigned char*)mask)[idx] != 0;
}

// ---------------------------------------------------------------------------
// HMMA GEMM (as R4): C = Ahl @ Bhl^T + bias.
// mode 0: row-major C.  mode 1: QKV scatter into bf16 hi/lo (+fp32 present).
// ---------------------------------------------------------------------------
__global__ __launch_bounds__(256, 2) void mma_gemm_kernel(
    const __nv_bfloat16* __restrict__ Ah, const __nv_bfloat16* __restrict__ Al,
    const __nv_bfloat16* __restrict__ Bh, const __nv_bfloat16* __restrict__ Bl,
    const float* __restrict__ bias, float* __restrict__ C,
    int M, int N, int K, int mode,
    float* __restrict__ kout, float* __restrict__ vout)
{
    __shared__ __nv_bfloat16 sAh[128 * kSTR], sAl[128 * kSTR];
    __shared__ __nv_bfloat16 sBh[128 * kSTR], sBl[128 * kSTR];

    const int tid = threadIdx.x;
    const int lane = tid & 31;
    const int wid = tid >> 5;
    const int wm = (wid & 3) * 32;
    const int wn = (wid >> 2) * 64;
    const int m0 = blockIdx.y * 128;
    const int n0 = blockIdx.x * 128;
    const int gID = lane >> 2;
    const int tig2 = (lane & 3) * 2;

    float acc[2][8][4] = {};

    for (int c = 0; c < K / 32; ++c) {
#pragma unroll
        for (int j = 0; j < 2; ++j) {
            int unit = tid + j * 256;
            int rr = unit >> 2;
            int uu = unit & 3;
            size_t ga = (size_t)(m0 + rr) * K + c * 32 + uu * 8;
            size_t gb = (size_t)(n0 + rr) * K + c * 32 + uu * 8;
            int so = rr * kSTR + uu * 8;
            *(float4*)&sAh[so] = *(const float4*)&Ah[ga];
            *(float4*)&sAl[so] = *(const float4*)&Al[ga];
            *(float4*)&sBh[so] = *(const float4*)&Bh[gb];
            *(float4*)&sBl[so] = *(const float4*)&Bl[gb];
        }
        __syncthreads();

#pragma unroll
        for (int ks = 0; ks < 2; ++ks) {
            const int k0 = ks * 16;
            uint32_t ah[2][4], al[2][4];
#pragma unroll
            for (int mi = 0; mi < 2; ++mi) {
                int base = (wm + mi * 16 + gID) * kSTR + k0 + tig2;
                ah[mi][0] = *(const uint32_t*)&sAh[base];
                ah[mi][1] = *(const uint32_t*)&sAh[base + 8 * kSTR];
                ah[mi][2] = *(const uint32_t*)&sAh[base + 8];
                ah[mi][3] = *(const uint32_t*)&sAh[base + 8 * kSTR + 8];
                al[mi][0] = *(const uint32_t*)&sAl[base];
                al[mi][1] = *(const uint32_t*)&sAl[base + 8 * kSTR];
                al[mi][2] = *(const uint32_t*)&sAl[base + 8];
                al[mi][3] = *(const uint32_t*)&sAl[base + 8 * kSTR + 8];
            }
#pragma unroll
            for (int nt = 0; nt < 8; ++nt) {
                int nb = (wn + nt * 8 + gID) * kSTR + k0 + tig2;
                uint32_t bh0 = *(const uint32_t*)&sBh[nb];
                uint32_t bh1 = *(const uint32_t*)&sBh[nb + 8];
                mma16816(acc[0][nt], ah[0], bh0, bh1);
                mma16816(acc[1][nt], ah[1], bh0, bh1);
                mma16816(acc[0][nt], al[0], bh0, bh1);
                mma16816(acc[1][nt], al[1], bh0, bh1);
                uint32_t bl0 = *(const uint32_t*)&sBl[nb];
                uint32_t bl1 = *(const uint32_t*)&sBl[nb + 8];
                mma16816(acc[0][nt], ah[0], bl0, bl1);
                mma16816(acc[1][nt], ah[1], bl0, bl1);
            }
        }
        __syncthreads();
    }

#pragma unroll
    for (int mi = 0; mi < 2; ++mi) {
#pragma unroll
        for (int nt = 0; nt < 8; ++nt) {
            int m = m0 + wm + mi * 16 + gID;
            int n = n0 + wn + nt * 8 + tig2;
            float b0 = bias[n], b1 = bias[n + 1];
            float v0 = acc[mi][nt][0] + b0;
            float v1 = acc[mi][nt][1] + b1;
            float v2 = acc[mi][nt][2] + b0;
            float v3 = acc[mi][nt][3] + b1;
            if (mode == 0) {
                *(float2*)&C[(size_t)m * N + n] = make_float2(v0, v1);
                *(float2*)&C[(size_t)(m + 8) * N + n] = make_float2(v2, v3);
            } else {
                int sec = n >> 10;
                int e = n & 1023;
                int h = e >> 6;
                int d = e & 63;
#pragma unroll
                for (int rr = 0; rr < 2; ++rr) {
                    int mm = m + rr * 8;
                    int b = mm >> 10;
                    int s = mm & 1023;
                    size_t idx = (((size_t)(b * kH + h) * kS) + s) * kHD + d;
                    float p0 = rr ? v2 : v0, p1 = rr ? v3 : v1;
                    __nv_bfloat16 h0, l0, h1, l1;
                    split2(p0, h0, l0);
                    split2(p1, h1, l1);
                    __nv_bfloat162 hp = __nv_bfloat162(h0, h1);
                    __nv_bfloat162 lp = __nv_bfloat162(l0, l1);
                    if (sec == 0) {
                        *(__nv_bfloat162*)&g_qh[idx] = hp;
                        *(__nv_bfloat162*)&g_ql[idx] = lp;
                    } else if (sec == 1) {
                        *(float2*)&kout[idx] = make_float2(p0, p1);
                        *(__nv_bfloat162*)&g_kh[idx] = hp;
                        *(__nv_bfloat162*)&g_kl[idx] = lp;
                    } else {
                        *(float2*)&vout[idx] = make_float2(p0, p1);
                        *(__nv_bfloat162*)&g_vh[idx] = hp;
                        *(__nv_bfloat162*)&g_vl[idx] = lp;
                    }
                }
            }
        }
    }
}

// ---------------------------------------------------------------------------
// Fused attention v2 (HMMA): one CTA per (b, h, 32 q-rows).
// ---------------------------------------------------------------------------
__global__ __launch_bounds__(256) void attn_kernel(
    const float* __restrict__ ov, const void* __restrict__ mask,
    float* __restrict__ out)
{
    extern __shared__ char smraw[];
    float* sST = (float*)smraw;
    __nv_bfloat16* sb = (__nv_bfloat16*)(smraw + SST_BYTES);
    __nv_bfloat16* sKh = sb + OFF_KH;   // reused as sVth
    __nv_bfloat16* sKl = sb + OFF_KL;   // reused as sVtl
    __nv_bfloat16* sQh = sb + OFF_QH;
    __nv_bfloat16* sQl = sb + OFF_QL;
    __nv_bfloat16* sPh = sb + OFF_PH;
    __nv_bfloat16* sPl = sb + OFF_PL;

    const int tid = threadIdx.x;
    const int lane = tid & 31;
    const int wid = tid >> 5;
    const int gID = lane >> 2;
    const int tig2 = (lane & 3) * 2;
    const int b = blockIdx.z;
    const int h = blockIdx.y;
    const int q0 = blockIdx.x * 32;
    const int mkind = g_mask_kind;
    const float scale = 0.125f;

    const size_t bh = (size_t)(b * kH + h) * kS * kHD;
    const __nv_bfloat16* Qhb = g_qh + bh + (size_t)q0 * kHD;
    const __nv_bfloat16* Qlb = g_ql + bh + (size_t)q0 * kHD;
    const __nv_bfloat16* Khb = g_kh + bh;
    const __nv_bfloat16* Klb = g_kl + bh;
    const __nv_bfloat16* Vhb = g_vh + bh;
    const __nv_bfloat16* Vlb = g_vl + bh;

    // ---- load Q tile [32][64] -> stride 72 ----
    {
        int row = tid >> 3, u = (tid & 7) * 8;
        *(float4*)&sQh[row * KQ_STR + u] = *(const float4*)&Qhb[row * kHD + u];
        *(float4*)&sQl[row * KQ_STR + u] = *(const float4*)&Qlb[row * kHD + u];
    }
    __syncthreads();

    // ---- Phase 1: S^T[k][q] via HMMA; warp wid owns k rows wid*16..+15 ----
    const int wm = wid * 16;
    for (int kc = 0; kc < 8; ++kc) {
#pragma unroll
        for (int it = 0; it < 4; ++it) {
            int unit = tid + it * 256;     // 0..1023
            int row = unit >> 3, u = (unit & 7) * 8;
            size_t g = (size_t)(kc * 128 + row) * kHD + u;
            int so = row * KQ_STR + u;
            *(float4*)&sKh[so] = *(const float4*)&Khb[g];
            *(float4*)&sKl[so] = *(const float4*)&Klb[g];
        }
        __syncthreads();

        float acc[4][4] = {};
#pragma unroll
        for (int ks = 0; ks < 4; ++ks) {
            int ab = (wm + gID) * KQ_STR + ks * 16 + tig2;
            uint32_t ah[4] = {*(const uint32_t*)&sKh[ab],
                              *(const uint32_t*)&sKh[ab + 8 * KQ_STR],
                              *(const uint32_t*)&sKh[ab + 8],
                              *(const uint32_t*)&sKh[ab + 8 * KQ_STR + 8]};
            uint32_t al[4] = {*(const uint32_t*)&sKl[ab],
                              *(const uint32_t*)&sKl[ab + 8 * KQ_STR],
                              *(const uint32_t*)&sKl[ab + 8],
                              *(const uint32_t*)&sKl[ab + 8 * KQ_STR + 8]};
#pragma unroll
            for (int nt = 0; nt < 4; ++nt) {
                int bb = (nt * 8 + gID) * KQ_STR + ks * 16 + tig2;
                uint32_t bh0 = *(const uint32_t*)&sQh[bb];
                uint32_t bh1 = *(const uint32_t*)&sQh[bb + 8];
                mma16816(acc[nt], ah, bh0, bh1);
                mma16816(acc[nt], al, bh0, bh1);
                uint32_t bl0 = *(const uint32_t*)&sQl[bb];
                uint32_t bl1 = *(const uint32_t*)&sQl[bb + 8];
                mma16816(acc[nt], ah, bl0, bl1);
            }
        }
#pragma unroll
        for (int nt = 0; nt < 4; ++nt) {
            int kg = kc * 128 + wm + gID;
            int q = nt * 8 + tig2;
            int qg = q0 + q;
            sST[kg * SST_STRIDE + q] =
                (kg <= qg) ? acc[nt][0] * scale : -10000.0f;
            sST[kg * SST_STRIDE + q + 1] =
                (kg <= qg + 1) ? acc[nt][1] * scale : -10000.0f;
            sST[(kg + 8) * SST_STRIDE + q] =
                (kg + 8 <= qg) ? acc[nt][2] * scale : -10000.0f;
            sST[(kg + 8) * SST_STRIDE + q + 1] =
                (kg + 8 <= qg + 1) ? acc[nt][3] * scale : -10000.0f;
        }
        __syncthreads();
    }

    // ---- Phase 2: softmax over k + override (warp handles 4 q rows) ----
    {
#pragma unroll
        for (int rr = 0; rr < 4; ++rr) {
            int r = wid * 4 + rr;
            float mx = -1e30f;
#pragma unroll
            for (int t = 0; t < 32; ++t)
                mx = fmaxf(mx, sST[(lane + t * 32) * SST_STRIDE + r]);
#pragma unroll
            for (int o = 16; o; o >>= 1)
                mx = fmaxf(mx, __shfl_xor_sync(0xffffffffu, mx, o));
            float sum = 0.f;
#pragma unroll
            for (int t = 0; t < 32; ++t) {
                int k = lane + t * 32;
                float e = __expf(sST[k * SST_STRIDE + r] - mx);
                sST[k * SST_STRIDE + r] = e;
                sum += e;
            }
#pragma unroll
            for (int o = 16; o; o >>= 1)
                sum += __shfl_xor_sync(0xffffffffu, sum, o);
            float inv = 1.0f / sum;
            size_t base = ((size_t)h * kS + (size_t)(q0 + r)) * kS;
#pragma unroll
            for (int t = 0; t < 32; ++t) {
                int k = lane + t * 32;
                float p = sST[k * SST_STRIDE + r] * inv;
                if (mask_at(mask, base + k, mkind)) p = ov[base + k];
                sST[k * SST_STRIDE + r] = p;
            }
        }
    }

    // ---- Phase 3: O[32][64] = P @ V via HMMA ----
    const int wq = (wid & 1) * 16;   // q m-tile
    const int wd = (wid >> 1) * 16;  // d slice (2 n-tiles)
    float oa[2][4] = {};
    __nv_bfloat16* sVth = sKh;  // reuse
    __nv_bfloat16* sVtl = sKl;

    for (int kc = 0; kc < 8; ++kc) {
        __syncthreads();  // previous chunk fully consumed / phase2 done
        // transpose V chunk -> sVt[d][k], and split P chunk -> sP[q][k]
        for (int idx = tid; idx < 4096; idx += 256) {
            int dp = idx & 31, k = idx >> 5;
            uint32_t wv = *(const uint32_t*)&Vhb[(size_t)(kc * 128 + k) * kHD + dp * 2];
            __nv_bfloat162 v2 = *(__nv_bfloat162*)&wv;
            sVth[(dp * 2) * VP_STR + k] = v2.x;
            sVth[(dp * 2 + 1) * VP_STR + k] = v2.y;
            uint32_t wl = *(const uint32_t*)&Vlb[(size_t)(kc * 128 + k) * kHD + dp * 2];
            __nv_bfloat162 l2 = *(__nv_bfloat162*)&wl;
            sVtl[(dp * 2) * VP_STR + k] = l2.x;
            sVtl[(dp * 2 + 1) * VP_STR + k] = l2.y;

            int q = idx & 31, kk = idx >> 5;
            float p = sST[(kc * 128 + kk) * SST_STRIDE + q];
            __nv_bfloat16 ph, pl;
            split2(p, ph, pl);
            sPh[q * VP_STR + kk] = ph;
            sPl[q * VP_STR + kk] = pl;
        }
        __syncthreads();

#pragma unroll
        for (int ks = 0; ks < 8; ++ks) {
            int ab = (wq + gID) * VP_STR + ks * 16 + tig2;
            uint32_t ah[4] = {*(const uint32_t*)&sPh[ab],
                              *(const uint32_t*)&sPh[ab + 8 * VP_STR],
                              *(const uint32_t*)&sPh[ab + 8],
                              *(const uint32_t*)&sPh[ab + 8 * VP_STR + 8]};
            uint32_t al[4] = {*(const uint32_t*)&sPl[ab],
                              *(const uint32_t*)&sPl[ab + 8 * VP_STR],
                              *(const uint32_t*)&sPl[ab + 8],
                              *(const uint32_t*)&sPl[ab + 8 * VP_STR + 8]};
#pragma unroll
            for (int nt = 0; nt < 2; ++nt) {
                int bb = (wd + nt * 8 + gID) * VP_STR + ks * 16 + tig2;
                uint32_t bh0 = *(const uint32_t*)&sVth[bb];
                uint32_t bh1 = *(const uint32_t*)&sVth[bb + 8];
                mma16816(oa[nt], ah, bh0, bh1);
                mma16816(oa[nt], al, bh0, bh1);
                uint32_t bl0 = *(const uint32_t*)&sVtl[bb];
                uint32_t bl1 = *(const uint32_t*)&sVtl[bb + 8];
                mma16816(oa[nt], ah, bl0, bl1);
            }
        }
    }

    // ---- store O (merged-head layout) ----
#pragma unroll
    for (int nt = 0; nt < 2; ++nt) {
        int q = q0 + wq + gID;
        int d = h * kHD + wd + nt * 8 + tig2;
        *(float2*)&out[(size_t)(b * kS + q) * kD + d] =
            make_float2(oa[nt][0], oa[nt][1]);
        *(float2*)&out[(size_t)(b * kS + q + 8) * kD + d] =
            make_float2(oa[nt][2], oa[nt][3]);
    }
}

// ---------------------------------------------------------------------------
extern "C" void kernel_launch(void* const* d_in, const int* in_sizes, int n_in,
                              void* d_out, int out_size)
{
    const float* x       = (const float*)d_in[0];
    const float* w_attn  = (const float*)d_in[1];
    const float* b_attn  = (const float*)d_in[2];
    const float* w_proj  = (const float*)d_in[3];
    const float* b_proj  = (const float*)d_in[4];
    const float* ov      = (const float*)d_in[5];
    const void*  msk     = (const void*)d_in[6];

    float* out = (float*)d_out;
    float* presentK = out + (size_t)kM * kD;
    float* presentV = presentK + (size_t)kB * kH * kS * kHD;

    float* aptr = nullptr;
    __nv_bfloat16 *xh, *xl, *ah, *al, *wth, *wtl, *pth, *ptl;
    cudaGetSymbolAddress((void**)&aptr, g_a);
    cudaGetSymbolAddress((void**)&xh, g_xh);
    cudaGetSymbolAddress((void**)&xl, g_xl);
    cudaGetSymbolAddress((void**)&ah, g_ah);
    cudaGetSymbolAddress((void**)&al, g_al);
    cudaGetSymbolAddress((void**)&wth, g_wth);
    cudaGetSymbolAddress((void**)&wtl, g_wtl);
    cudaGetSymbolAddress((void**)&pth, g_pth);
    cudaGetSymbolAddress((void**)&ptl, g_ptl);

    cudaFuncSetAttribute(attn_kernel,
                         cudaFuncAttributeMaxDynamicSharedMemorySize, ATT_SMEM_BYTES);

    // 0) mask classification + operand prep
    detect_mask_kind_kernel<<<1, 256>>>((const unsigned int*)msk);
    split_kernel<<<kM * kD / 256, 256>>>(x, xh, xl, kM * kD);
    transpose_split_kernel<<<dim3(3 * kD / 32, kD / 32), dim3(32, 8)>>>(
        w_attn, wth, wtl, kD, 3 * kD);
    transpose_split_kernel<<<dim3(kD / 32, kD / 32), dim3(32, 8)>>>(
        w_proj, pth, ptl, kD, kD);

    // 1) QKV GEMM: scatter q/k/v as bf16 hi/lo (+ fp32 present)
    mma_gemm_kernel<<<dim3(3 * kD / 128, kM / 128), 256>>>(
        xh, xl, wth, wtl, b_attn, nullptr, kM, 3 * kD, kD, 1, presentK, presentV);

    // 2) fused attention (HMMA) -> g_a
    attn_kernel<<<dim3(kS / 32, kH, kB), 256, ATT_SMEM_BYTES>>>(ov, msk, aptr);

    // 3) split g_a, then output projection (HMMA)
    split_kernel<<<kM * kD / 256, 256>>>(aptr, ah, al, kM * kD);
    mma_gemm_kernel<<<dim3(kD / 128, kM / 128), 256>>>(
        ah, al, pth, ptl, b_proj, out, kM, kD, kD, 0, nullptr, nullptr);
}

// round 6
// speedup vs baseline: 1.7863x; 1.7863x over previous
#include <cuda_runtime.h>
#include <cuda_bf16.h>
#include <cstdint>

// ---------------------------------------------------------------------------
// AttentionOverride, round 6: HMMA GEMMs + one-pass flash attention with
// override decomposition:  O = (E_unmasked @ V)/Z + (mask?ov:0) @ V.
// Output layout: [ a (4M floats) | presentK (4M) | presentV (4M) ]
// ---------------------------------------------------------------------------

namespace {
constexpr int kB  = 4;
constexpr int kS  = 1024;
constexpr int kD  = 1024;
constexpr int kH  = 16;
constexpr int kHD = 64;
constexpr int kM  = kB * kS;  // 4096

constexpr int kSTR = 40;  // GEMM smem stride (bf16)

// flash smem (bf16 elems): K[128][72] hi/lo, Vt[64][136] hi/lo
constexpr int F_KH = 0;
constexpr int F_KL = 9216;
constexpr int F_VH = 18432;
constexpr int F_VL = 27136;
constexpr int FLASH_SMEM_BYTES = 35840 * 2;  // 71680
}  // namespace

// scratch (device globals; no allocation allowed)
__device__ float g_a[(size_t)kM * kD];
__device__ int   g_mask_kind;
__device__ __nv_bfloat16 g_qh[(size_t)kM * kD], g_ql[(size_t)kM * kD];
__device__ __nv_bfloat16 g_kh[(size_t)kM * kD], g_kl[(size_t)kM * kD];
__device__ __nv_bfloat16 g_vth[(size_t)kM * kD], g_vtl[(size_t)kM * kD];  // [BH][64][S]
__device__ __nv_bfloat16 g_xh[(size_t)kM * kD], g_xl[(size_t)kM * kD];
__device__ __nv_bfloat16 g_ah[(size_t)kM * kD], g_al[(size_t)kM * kD];
__device__ __nv_bfloat16 g_wth[(size_t)3 * kD * kD], g_wtl[(size_t)3 * kD * kD];
__device__ __nv_bfloat16 g_pth[(size_t)kD * kD], g_ptl[(size_t)kD * kD];

// ---------------------------------------------------------------------------
__device__ __forceinline__ void mma16816(float* c, const uint32_t* a,
                                         uint32_t b0, uint32_t b1) {
    asm volatile(
        "mma.sync.aligned.m16n8k16.row.col.f32.bf16.bf16.f32 "
        "{%0,%1,%2,%3}, {%4,%5,%6,%7}, {%8,%9}, {%0,%1,%2,%3};"
        : "+f"(c[0]), "+f"(c[1]), "+f"(c[2]), "+f"(c[3])
        : "r"(a[0]), "r"(a[1]), "r"(a[2]), "r"(a[3]), "r"(b0), "r"(b1));
}

__device__ __forceinline__ void split2(float x, __nv_bfloat16& h, __nv_bfloat16& l) {
    h = __float2bfloat16(x);
    l = __float2bfloat16(x - __bfloat162float(h));
}
__device__ __forceinline__ uint32_t packbf(__nv_bfloat16 a, __nv_bfloat16 b) {
    __nv_bfloat162 t(a, b);
    return *(uint32_t*)&t;
}
// split+pack a float pair into hi-word and lo-word fragments
__device__ __forceinline__ void packsplit(float x, float y,
                                          uint32_t& hw, uint32_t& lw) {
    __nv_bfloat16 hx, lx, hy, ly;
    split2(x, hx, lx);
    split2(y, hy, ly);
    hw = packbf(hx, hy);
    lw = packbf(lx, ly);
}

__device__ __forceinline__ uint2 mask2(const void* m, size_t i, int kind) {
    if (kind == 0) {
        const unsigned char* p = (const unsigned char*)m;
        return make_uint2(p[i], p[i + 1]);
    }
    // int32 {0,1} or float32 {0,1.0f}: nonzero bit test works for both
    return *(const uint2*)((const unsigned int*)m + i);
}

// ---------------------------------------------------------------------------
__global__ void split_kernel(const float* __restrict__ X,
                             __nv_bfloat16* __restrict__ H,
                             __nv_bfloat16* __restrict__ L, int n) {
    int i = blockIdx.x * 256 + threadIdx.x;
    if (i < n) split2(X[i], H[i], L[i]);
}

__global__ void transpose_split_kernel(const float* __restrict__ W,
                                       __nv_bfloat16* __restrict__ Th,
                                       __nv_bfloat16* __restrict__ Tl,
                                       int K, int N) {
    __shared__ float t[32][33];
    int n0 = blockIdx.x * 32, k0 = blockIdx.y * 32;
    int tx = threadIdx.x, ty = threadIdx.y;
#pragma unroll
    for (int j = 0; j < 4; ++j)
        t[ty + j * 8][tx] = W[(size_t)(k0 + ty + j * 8) * N + n0 + tx];
    __syncthreads();
#pragma unroll
    for (int j = 0; j < 4; ++j) {
        float v = t[tx][ty + j * 8];
        __nv_bfloat16 h, l;
        split2(v, h, l);
        size_t o = (size_t)(n0 + ty + j * 8) * K + k0 + tx;
        Th[o] = h;
        Tl[o] = l;
    }
}

// presentV fp32 [BH][S][64] -> g_vt hi/lo [BH][64][S]
__global__ void vtrans_kernel(const float* __restrict__ V) {
    __shared__ float t[32][33];
    int d0 = blockIdx.x * 32, s0 = blockIdx.y * 32, bh = blockIdx.z;
    int tx = threadIdx.x, ty = threadIdx.y;
#pragma unroll
    for (int j = 0; j < 4; ++j)
        t[ty + j * 8][tx] =
            V[(size_t)bh * (kS * kHD) + (size_t)(s0 + ty + j * 8) * kHD + d0 + tx];
    __syncthreads();
#pragma unroll
    for (int j = 0; j < 4; ++j) {
        float v = t[tx][ty + j * 8];
        __nv_bfloat16 h, l;
        split2(v, h, l);
        size_t o = ((size_t)bh * kHD + d0 + ty + j * 8) * kS + s0 + tx;
        g_vth[o] = h;
        g_vtl[o] = l;
    }
}

__global__ void detect_mask_kind_kernel(const unsigned int* __restrict__ m) {
    __shared__ int any_gt1, any_not_f32;
    if (threadIdx.x == 0) { any_gt1 = 0; any_not_f32 = 0; }
    __syncthreads();
    int gt1 = 0, nf32 = 0;
    for (int i = threadIdx.x; i < 16384; i += 256) {
        unsigned int w = m[i];
        if (w > 1u) gt1 = 1;
        if (w != 0u && w != 0x3F800000u) nf32 = 1;
    }
    if (gt1)  atomicOr(&any_gt1, 1);
    if (nf32) atomicOr(&any_not_f32, 1);
    __syncthreads();
    if (threadIdx.x == 0)
        g_mask_kind = (!any_gt1) ? 1 : ((!any_not_f32) ? 2 : 0);
}

// ---------------------------------------------------------------------------
// HMMA GEMM (proven R4 core). mode 0: row-major C. mode 1: QKV scatter:
// q -> bf16 hi/lo; k -> fp32 present + bf16 hi/lo; v -> fp32 present.
// ---------------------------------------------------------------------------
__global__ __launch_bounds__(256, 2) void mma_gemm_kernel(
    const __nv_bfloat16* __restrict__ Ah, const __nv_bfloat16* __restrict__ Al,
    const __nv_bfloat16* __restrict__ Bh, const __nv_bfloat16* __restrict__ Bl,
    const float* __restrict__ bias, float* __restrict__ C,
    int M, int N, int K, int mode,
    float* __restrict__ kout, float* __restrict__ vout)
{
    __shared__ __nv_bfloat16 sAh[128 * kSTR], sAl[128 * kSTR];
    __shared__ __nv_bfloat16 sBh[128 * kSTR], sBl[128 * kSTR];

    const int tid = threadIdx.x;
    const int lane = tid & 31;
    const int wid = tid >> 5;
    const int wm = (wid & 3) * 32;
    const int wn = (wid >> 2) * 64;
    const int m0 = blockIdx.y * 128;
    const int n0 = blockIdx.x * 128;
    const int gID = lane >> 2;
    const int tig2 = (lane & 3) * 2;

    float acc[2][8][4] = {};

    for (int c = 0; c < K / 32; ++c) {
#pragma unroll
        for (int j = 0; j < 2; ++j) {
            int unit = tid + j * 256;
            int rr = unit >> 2;
            int uu = unit & 3;
            size_t ga = (size_t)(m0 + rr) * K + c * 32 + uu * 8;
            size_t gb = (size_t)(n0 + rr) * K + c * 32 + uu * 8;
            int so = rr * kSTR + uu * 8;
            *(float4*)&sAh[so] = *(const float4*)&Ah[ga];
            *(float4*)&sAl[so] = *(const float4*)&Al[ga];
            *(float4*)&sBh[so] = *(const float4*)&Bh[gb];
            *(float4*)&sBl[so] = *(const float4*)&Bl[gb];
        }
        __syncthreads();

#pragma unroll
        for (int ks = 0; ks < 2; ++ks) {
            const int k0 = ks * 16;
            uint32_t ah[2][4], al[2][4];
#pragma unroll
            for (int mi = 0; mi < 2; ++mi) {
                int base = (wm + mi * 16 + gID) * kSTR + k0 + tig2;
                ah[mi][0] = *(const uint32_t*)&sAh[base];
                ah[mi][1] = *(const uint32_t*)&sAh[base + 8 * kSTR];
                ah[mi][2] = *(const uint32_t*)&sAh[base + 8];
                ah[mi][3] = *(const uint32_t*)&sAh[base + 8 * kSTR + 8];
                al[mi][0] = *(const uint32_t*)&sAl[base];
                al[mi][1] = *(const uint32_t*)&sAl[base + 8 * kSTR];
                al[mi][2] = *(const uint32_t*)&sAl[base + 8];
                al[mi][3] = *(const uint32_t*)&sAl[base + 8 * kSTR + 8];
            }
#pragma unroll
            for (int nt = 0; nt < 8; ++nt) {
                int nb = (wn + nt * 8 + gID) * kSTR + k0 + tig2;
                uint32_t bh0 = *(const uint32_t*)&sBh[nb];
                uint32_t bh1 = *(const uint32_t*)&sBh[nb + 8];
                mma16816(acc[0][nt], ah[0], bh0, bh1);
                mma16816(acc[1][nt], ah[1], bh0, bh1);
                mma16816(acc[0][nt], al[0], bh0, bh1);
                mma16816(acc[1][nt], al[1], bh0, bh1);
                uint32_t bl0 = *(const uint32_t*)&sBl[nb];
                uint32_t bl1 = *(const uint32_t*)&sBl[nb + 8];
                mma16816(acc[0][nt], ah[0], bl0, bl1);
                mma16816(acc[1][nt], ah[1], bl0, bl1);
            }
        }
        __syncthreads();
    }

#pragma unroll
    for (int mi = 0; mi < 2; ++mi) {
#pragma unroll
        for (int nt = 0; nt < 8; ++nt) {
            int m = m0 + wm + mi * 16 + gID;
            int n = n0 + wn + nt * 8 + tig2;
            float b0 = bias[n], b1 = bias[n + 1];
            float v0 = acc[mi][nt][0] + b0;
            float v1 = acc[mi][nt][1] + b1;
            float v2 = acc[mi][nt][2] + b0;
            float v3 = acc[mi][nt][3] + b1;
            if (mode == 0) {
                *(float2*)&C[(size_t)m * N + n] = make_float2(v0, v1);
                *(float2*)&C[(size_t)(m + 8) * N + n] = make_float2(v2, v3);
            } else {
                int sec = n >> 10;
                int e = n & 1023;
                int h = e >> 6;
                int d = e & 63;
#pragma unroll
                for (int rr = 0; rr < 2; ++rr) {
                    int mm = m + rr * 8;
                    int bb = mm >> 10;
                    int s = mm & 1023;
                    size_t idx = (((size_t)(bb * kH + h)) * kS + s) * kHD + d;
                    float p0 = rr ? v2 : v0, p1 = rr ? v3 : v1;
                    if (sec == 0) {
                        uint32_t hw, lw;
                        packsplit(p0, p1, hw, lw);
                        *(uint32_t*)&g_qh[idx] = hw;
                        *(uint32_t*)&g_ql[idx] = lw;
                    } else if (sec == 1) {
                        *(float2*)&kout[idx] = make_float2(p0, p1);
                        uint32_t hw, lw;
                        packsplit(p0, p1, hw, lw);
                        *(uint32_t*)&g_kh[idx] = hw;
                        *(uint32_t*)&g_kl[idx] = lw;
                    } else {
                        *(float2*)&vout[idx] = make_float2(p0, p1);
                    }
                }
            }
        }
    }
}

// ---------------------------------------------------------------------------
// OV kernel: g_a[b*S+q][h*64+d] = sum_k (mask? ov : 0)[h,q,k] * V[b,h,k,d]
// ---------------------------------------------------------------------------
__global__ __launch_bounds__(256, 2) void ov_kernel(
    const float* __restrict__ ov, const void* __restrict__ mask,
    float* __restrict__ out)
{
    __shared__ __nv_bfloat16 sVh[64 * 136], sVl[64 * 136];
    const int tid = threadIdx.x, lane = tid & 31, wid = tid >> 5;
    const int gID = lane >> 2, tig2 = (lane & 3) * 2;
    const int b = blockIdx.z, h = blockIdx.y, q0 = blockIdx.x * 128;
    const int wq = wid * 16;
    const int mkind = g_mask_kind;
    const size_t bhT = (size_t)(b * kH + h) * kHD;
    const int qr0 = q0 + wq + gID, qr1 = qr0 + 8;
    const size_t mr0 = ((size_t)h * kS + qr0) * kS;
    const size_t mr1 = ((size_t)h * kS + qr1) * kS;

    float o[8][4] = {};

    for (int kc = 0; kc < 8; ++kc) {
#pragma unroll
        for (int it = 0; it < 4; ++it) {
            int unit = tid + it * 256;
            int row = unit >> 4, u = (unit & 15) * 8;
            *(float4*)&sVh[row * 136 + u] =
                *(const float4*)&g_vth[(bhT + row) * kS + kc * 128 + u];
            *(float4*)&sVl[row * 136 + u] =
                *(const float4*)&g_vtl[(bhT + row) * kS + kc * 128 + u];
        }
        __syncthreads();

#pragma unroll
        for (int ks = 0; ks < 8; ++ks) {
            size_t kg = (size_t)kc * 128 + ks * 16 + tig2;
            // 4 positions x float2
            uint2 m00 = mask2(mask, mr0 + kg, mkind);
            uint2 m02 = mask2(mask, mr0 + kg + 8, mkind);
            uint2 m10 = mask2(mask, mr1 + kg, mkind);
            uint2 m12 = mask2(mask, mr1 + kg + 8, mkind);
            float2 v00 = *(const float2*)&ov[mr0 + kg];
            float2 v02 = *(const float2*)&ov[mr0 + kg + 8];
            float2 v10 = *(const float2*)&ov[mr1 + kg];
            float2 v12 = *(const float2*)&ov[mr1 + kg + 8];
            float f00x = m00.x ? v00.x : 0.f, f00y = m00.y ? v00.y : 0.f;
            float f02x = m02.x ? v02.x : 0.f, f02y = m02.y ? v02.y : 0.f;
            float f10x = m10.x ? v10.x : 0.f, f10y = m10.y ? v10.y : 0.f;
            float f12x = m12.x ? v12.x : 0.f, f12y = m12.y ? v12.y : 0.f;
            uint32_t ah[4], al[4];
            packsplit(f00x, f00y, ah[0], al[0]);  // row0, k..k+1
            packsplit(f10x, f10y, ah[1], al[1]);  // row1
            packsplit(f02x, f02y, ah[2], al[2]);  // row0, k+8..k+9
            packsplit(f12x, f12y, ah[3], al[3]);  // row1
#pragma unroll
            for (int dn = 0; dn < 8; ++dn) {
                int vb = (dn * 8 + gID) * 136 + ks * 16 + tig2;
                uint32_t b0 = *(const uint32_t*)&sVh[vb];
                uint32_t b1 = *(const uint32_t*)&sVh[vb + 8];
                mma16816(o[dn], ah, b0, b1);
                mma16816(o[dn], al, b0, b1);
                uint32_t c0 = *(const uint32_t*)&sVl[vb];
                uint32_t c1 = *(const uint32_t*)&sVl[vb + 8];
                mma16816(o[dn], ah, c0, c1);
            }
        }
        __syncthreads();
    }

#pragma unroll
    for (int dn = 0; dn < 8; ++dn) {
        int d = h * kHD + dn * 8 + tig2;
        *(float2*)&out[(size_t)(b * kS + qr0) * kD + d] =
            make_float2(o[dn][0], o[dn][1]);
        *(float2*)&out[(size_t)(b * kS + qr1) * kD + d] =
            make_float2(o[dn][2], o[dn][3]);
    }
}

// ---------------------------------------------------------------------------
// Flash kernel: O1 = (causal-exp, masked-zeroed) E @ V; g_a += O1 / Z.
// One CTA per (b, h, 128 q rows). Q fragments register-resident.
// ---------------------------------------------------------------------------
__global__ __launch_bounds__(256, 2) void flash_kernel(
    const void* __restrict__ mask, float* __restrict__ aio)
{
    extern __shared__ __nv_bfloat16 fsm[];
    __nv_bfloat16* sKh = fsm + F_KH;   // [128][72]
    __nv_bfloat16* sKl = fsm + F_KL;
    __nv_bfloat16* sVh = fsm + F_VH;   // [64][136]
    __nv_bfloat16* sVl = fsm + F_VL;

    const int tid = threadIdx.x, lane = tid & 31, wid = tid >> 5;
    const int gID = lane >> 2, tig2 = (lane & 3) * 2;
    const int b = blockIdx.z, h = blockIdx.y, q0 = blockIdx.x * 128;
    const int wq = wid * 16;
    const int mkind = g_mask_kind;
    const size_t bh = (size_t)(b * kH + h) * kS * kHD;
    const size_t bhT = (size_t)(b * kH + h) * kHD;

    // stage Q tile, load register fragments
#pragma unroll
    for (int it = 0; it < 4; ++it) {
        int unit = tid + it * 256;
        int row = unit >> 3, u = (unit & 7) * 8;
        *(float4*)&sKh[row * 72 + u] =
            *(const float4*)&g_qh[bh + (size_t)(q0 + row) * kHD + u];
        *(float4*)&sKl[row * 72 + u] =
            *(const float4*)&g_ql[bh + (size_t)(q0 + row) * kHD + u];
    }
    __syncthreads();
    uint32_t qfh[4][4], qfl[4][4];
#pragma unroll
    for (int ks = 0; ks < 4; ++ks) {
        int base = (wq + gID) * 72 + ks * 16 + tig2;
        qfh[ks][0] = *(const uint32_t*)&sKh[base];
        qfh[ks][1] = *(const uint32_t*)&sKh[base + 8 * 72];
        qfh[ks][2] = *(const uint32_t*)&sKh[base + 8];
        qfh[ks][3] = *(const uint32_t*)&sKh[base + 8 * 72 + 8];
        qfl[ks][0] = *(const uint32_t*)&sKl[base];
        qfl[ks][1] = *(const uint32_t*)&sKl[base + 8 * 72];
        qfl[ks][2] = *(const uint32_t*)&sKl[base + 8];
        qfl[ks][3] = *(const uint32_t*)&sKl[base + 8 * 72 + 8];
    }
    __syncthreads();

    float o[8][4] = {};
    float Z0 = 0.f, Z1 = 0.f;
    const int qr0 = q0 + wq + gID, qr1 = qr0 + 8;
    const size_t mr0 = ((size_t)h * kS + qr0) * kS;
    const size_t mr1 = ((size_t)h * kS + qr1) * kS;

    for (int kc = 0; kc < 8; ++kc) {
#pragma unroll
        for (int it = 0; it < 4; ++it) {
            int unit = tid + it * 256;
            int row = unit >> 3, u = (unit & 7) * 8;
            *(float4*)&sKh[row * 72 + u] =
                *(const float4*)&g_kh[bh + (size_t)(kc * 128 + row) * kHD + u];
            *(float4*)&sKl[row * 72 + u] =
                *(const float4*)&g_kl[bh + (size_t)(kc * 128 + row) * kHD + u];
        }
#pragma unroll
        for (int it = 0; it < 4; ++it) {
            int unit = tid + it * 256;
            int row = unit >> 4, u = (unit & 15) * 8;
            *(float4*)&sVh[row * 136 + u] =
                *(const float4*)&g_vth[(bhT + row) * kS + kc * 128 + u];
            *(float4*)&sVl[row * 136 + u] =
                *(const float4*)&g_vtl[(bhT + row) * kS + kc * 128 + u];
        }
        __syncthreads();

        for (int qq = 0; qq < 4; ++qq) {  // 32-key quarters of the chunk
            float sa[4][4] = {};
#pragma unroll
            for (int ks = 0; ks < 4; ++ks)
#pragma unroll
                for (int nt = 0; nt < 4; ++nt) {
                    int kb = (qq * 32 + nt * 8 + gID) * 72 + ks * 16 + tig2;
                    uint32_t b0 = *(const uint32_t*)&sKh[kb];
                    uint32_t b1 = *(const uint32_t*)&sKh[kb + 8];
                    mma16816(sa[nt], qfh[ks], b0, b1);
                    mma16816(sa[nt], qfl[ks], b0, b1);
                    uint32_t c0 = *(const uint32_t*)&sKl[kb];
                    uint32_t c1 = *(const uint32_t*)&sKl[kb + 8];
                    mma16816(sa[nt], qfh[ks], c0, c1);
                }

            uint32_t ehr0[4], ehr1[4], elr0[4], elr1[4];
#pragma unroll
            for (int nt = 0; nt < 4; ++nt) {
                int kg = kc * 128 + qq * 32 + nt * 8 + tig2;
                float e00 = (kg     <= qr0) ? __expf(sa[nt][0] * 0.125f) : 0.f;
                float e01 = (kg + 1 <= qr0) ? __expf(sa[nt][1] * 0.125f) : 0.f;
                float e10 = (kg     <= qr1) ? __expf(sa[nt][2] * 0.125f) : 0.f;
                float e11 = (kg + 1 <= qr1) ? __expf(sa[nt][3] * 0.125f) : 0.f;
                Z0 += e00 + e01;
                Z1 += e10 + e11;
                uint2 m0 = mask2(mask, mr0 + kg, mkind);
                uint2 m1 = mask2(mask, mr1 + kg, mkind);
                if (m0.x) e00 = 0.f;
                if (m0.y) e01 = 0.f;
                if (m1.x) e10 = 0.f;
                if (m1.y) e11 = 0.f;
                packsplit(e00, e01, ehr0[nt], elr0[nt]);
                packsplit(e10, e11, ehr1[nt], elr1[nt]);
            }
#pragma unroll
            for (int k2 = 0; k2 < 2; ++k2) {
                uint32_t ah[4] = {ehr0[2 * k2], ehr1[2 * k2],
                                  ehr0[2 * k2 + 1], ehr1[2 * k2 + 1]};
                uint32_t al[4] = {elr0[2 * k2], elr1[2 * k2],
                                  elr0[2 * k2 + 1], elr1[2 * k2 + 1]};
#pragma unroll
                for (int dn = 0; dn < 8; ++dn) {
                    int vb = (dn * 8 + gID) * 136 + qq * 32 + k2 * 16 + tig2;
                    uint32_t b0 = *(const uint32_t*)&sVh[vb];
                    uint32_t b1 = *(const uint32_t*)&sVh[vb + 8];
                    mma16816(o[dn], ah, b0, b1);
                    mma16816(o[dn], al, b0, b1);
                    uint32_t c0 = *(const uint32_t*)&sVl[vb];
                    uint32_t c1 = *(const uint32_t*)&sVl[vb + 8];
                    mma16816(o[dn], ah, c0, c1);
                }
            }
        }
        __syncthreads();
    }

    Z0 += __shfl_xor_sync(0xffffffffu, Z0, 1);
    Z0 += __shfl_xor_sync(0xffffffffu, Z0, 2);
    Z1 += __shfl_xor_sync(0xffffffffu, Z1, 1);
    Z1 += __shfl_xor_sync(0xffffffffu, Z1, 2);
    float i0 = 1.f / Z0, i1 = 1.f / Z1;

#pragma unroll
    for (int dn = 0; dn < 8; ++dn) {
        int d = h * kHD + dn * 8 + tig2;
        size_t r0 = (size_t)(b * kS + qr0) * kD + d;
        size_t r1 = (size_t)(b * kS + qr1) * kD + d;
        float2 p0 = *(float2*)&aio[r0];
        float2 p1 = *(float2*)&aio[r1];
        *(float2*)&aio[r0] =
            make_float2(p0.x + o[dn][0] * i0, p0.y + o[dn][1] * i0);
        *(float2*)&aio[r1] =
            make_float2(p1.x + o[dn][2] * i1, p1.y + o[dn][3] * i1);
    }
}

// ---------------------------------------------------------------------------
extern "C" void kernel_launch(void* const* d_in, const int* in_sizes, int n_in,
                              void* d_out, int out_size)
{
    const float* x       = (const float*)d_in[0];
    const float* w_attn  = (const float*)d_in[1];
    const float* b_attn  = (const float*)d_in[2];
    const float* w_proj  = (const float*)d_in[3];
    const float* b_proj  = (const float*)d_in[4];
    const float* ov      = (const float*)d_in[5];
    const void*  msk     = (const void*)d_in[6];

    float* out = (float*)d_out;
    float* presentK = out + (size_t)kM * kD;
    float* presentV = presentK + (size_t)kB * kH * kS * kHD;

    float* aptr = nullptr;
    __nv_bfloat16 *xh, *xl, *ah, *al, *wth, *wtl, *pth, *ptl;
    cudaGetSymbolAddress((void**)&aptr, g_a);
    cudaGetSymbolAddress((void**)&xh, g_xh);
    cudaGetSymbolAddress((void**)&xl, g_xl);
    cudaGetSymbolAddress((void**)&ah, g_ah);
    cudaGetSymbolAddress((void**)&al, g_al);
    cudaGetSymbolAddress((void**)&wth, g_wth);
    cudaGetSymbolAddress((void**)&wtl, g_wtl);
    cudaGetSymbolAddress((void**)&pth, g_pth);
    cudaGetSymbolAddress((void**)&ptl, g_ptl);

    cudaFuncSetAttribute(flash_kernel,
                         cudaFuncAttributeMaxDynamicSharedMemorySize,
                         FLASH_SMEM_BYTES);

    // 0) mask classification + operand prep
    detect_mask_kind_kernel<<<1, 256>>>((const unsigned int*)msk);
    split_kernel<<<kM * kD / 256, 256>>>(x, xh, xl, kM * kD);
    transpose_split_kernel<<<dim3(3 * kD / 32, kD / 32), dim3(32, 8)>>>(
        w_attn, wth, wtl, kD, 3 * kD);
    transpose_split_kernel<<<dim3(kD / 32, kD / 32), dim3(32, 8)>>>(
        w_proj, pth, ptl, kD, kD);

    // 1) QKV GEMM -> present fp32 + q/k bf16 hi/lo
    mma_gemm_kernel<<<dim3(3 * kD / 128, kM / 128), 256>>>(
        xh, xl, wth, wtl, b_attn, nullptr, kM, 3 * kD, kD, 1, presentK, presentV);

    // 2) V transpose+split -> g_vt
    vtrans_kernel<<<dim3(kHD / 32, kS / 32, kB * kH), dim3(32, 8)>>>(presentV);

    // 3) override term -> g_a (full overwrite)
    ov_kernel<<<dim3(kS / 128, kH, kB), 256>>>(ov, msk, aptr);

    // 4) flash attention adds softmax term -> g_a
    flash_kernel<<<dim3(kS / 128, kH, kB), 256, FLASH_SMEM_BYTES>>>(msk, aptr);

    // 5) split g_a, output projection
    split_kernel<<<kM * kD / 256, 256>>>(aptr, ah, al, kM * kD);
    mma_gemm_kernel<<<dim3(kD / 128, kM / 128), 256>>>(
        ah, al, pth, ptl, b_proj, out, kM, kD, kD, 0, nullptr, nullptr);
}

// round 7
// speedup vs baseline: 1.8902x; 1.0582x over previous
#include <cuda_runtime.h>
#include <cuda_bf16.h>
#include <cstdint>

// ---------------------------------------------------------------------------
// AttentionOverride, round 7: R6 + causal chunk skipping in the flash kernel.
// O = (E_unmasked @ V)/Z + (mask?ov:0) @ V ; E chunks with kc > q-tile are
// identically zero (causal) and are now skipped entirely.
// Output layout: [ a (4M floats) | presentK (4M) | presentV (4M) ]
// ---------------------------------------------------------------------------

namespace {
constexpr int kB  = 4;
constexpr int kS  = 1024;
constexpr int kD  = 1024;
constexpr int kH  = 16;
constexpr int kHD = 64;
constexpr int kM  = kB * kS;  // 4096

constexpr int kSTR = 40;  // GEMM smem stride (bf16)

// flash smem (bf16 elems): K[128][72] hi/lo, Vt[64][136] hi/lo
constexpr int F_KH = 0;
constexpr int F_KL = 9216;
constexpr int F_VH = 18432;
constexpr int F_VL = 27136;
constexpr int FLASH_SMEM_BYTES = 35840 * 2;  // 71680
}  // namespace

// scratch (device globals; no allocation allowed)
__device__ float g_a[(size_t)kM * kD];
__device__ int   g_mask_kind;
__device__ __nv_bfloat16 g_qh[(size_t)kM * kD], g_ql[(size_t)kM * kD];
__device__ __nv_bfloat16 g_kh[(size_t)kM * kD], g_kl[(size_t)kM * kD];
__device__ __nv_bfloat16 g_vth[(size_t)kM * kD], g_vtl[(size_t)kM * kD];  // [BH][64][S]
__device__ __nv_bfloat16 g_xh[(size_t)kM * kD], g_xl[(size_t)kM * kD];
__device__ __nv_bfloat16 g_ah[(size_t)kM * kD], g_al[(size_t)kM * kD];
__device__ __nv_bfloat16 g_wth[(size_t)3 * kD * kD], g_wtl[(size_t)3 * kD * kD];
__device__ __nv_bfloat16 g_pth[(size_t)kD * kD], g_ptl[(size_t)kD * kD];

// ---------------------------------------------------------------------------
__device__ __forceinline__ void mma16816(float* c, const uint32_t* a,
                                         uint32_t b0, uint32_t b1) {
    asm volatile(
        "mma.sync.aligned.m16n8k16.row.col.f32.bf16.bf16.f32 "
        "{%0,%1,%2,%3}, {%4,%5,%6,%7}, {%8,%9}, {%0,%1,%2,%3};"
        : "+f"(c[0]), "+f"(c[1]), "+f"(c[2]), "+f"(c[3])
        : "r"(a[0]), "r"(a[1]), "r"(a[2]), "r"(a[3]), "r"(b0), "r"(b1));
}

__device__ __forceinline__ void split2(float x, __nv_bfloat16& h, __nv_bfloat16& l) {
    h = __float2bfloat16(x);
    l = __float2bfloat16(x - __bfloat162float(h));
}
__device__ __forceinline__ uint32_t packbf(__nv_bfloat16 a, __nv_bfloat16 b) {
    __nv_bfloat162 t(a, b);
    return *(uint32_t*)&t;
}
__device__ __forceinline__ void packsplit(float x, float y,
                                          uint32_t& hw, uint32_t& lw) {
    __nv_bfloat16 hx, lx, hy, ly;
    split2(x, hx, lx);
    split2(y, hy, ly);
    hw = packbf(hx, hy);
    lw = packbf(lx, ly);
}

__device__ __forceinline__ uint2 mask2(const void* m, size_t i, int kind) {
    if (kind == 0) {
        const unsigned char* p = (const unsigned char*)m;
        return make_uint2(p[i], p[i + 1]);
    }
    return *(const uint2*)((const unsigned int*)m + i);
}

// ---------------------------------------------------------------------------
__global__ void split_kernel(const float* __restrict__ X,
                             __nv_bfloat16* __restrict__ H,
                             __nv_bfloat16* __restrict__ L, int n) {
    int i = blockIdx.x * 256 + threadIdx.x;
    if (i < n) split2(X[i], H[i], L[i]);
}

__global__ void transpose_split_kernel(const float* __restrict__ W,
                                       __nv_bfloat16* __restrict__ Th,
                                       __nv_bfloat16* __restrict__ Tl,
                                       int K, int N) {
    __shared__ float t[32][33];
    int n0 = blockIdx.x * 32, k0 = blockIdx.y * 32;
    int tx = threadIdx.x, ty = threadIdx.y;
#pragma unroll
    for (int j = 0; j < 4; ++j)
        t[ty + j * 8][tx] = W[(size_t)(k0 + ty + j * 8) * N + n0 + tx];
    __syncthreads();
#pragma unroll
    for (int j = 0; j < 4; ++j) {
        float v = t[tx][ty + j * 8];
        __nv_bfloat16 h, l;
        split2(v, h, l);
        size_t o = (size_t)(n0 + ty + j * 8) * K + k0 + tx;
        Th[o] = h;
        Tl[o] = l;
    }
}

// presentV fp32 [BH][S][64] -> g_vt hi/lo [BH][64][S]
__global__ void vtrans_kernel(const float* __restrict__ V) {
    __shared__ float t[32][33];
    int d0 = blockIdx.x * 32, s0 = blockIdx.y * 32, bh = blockIdx.z;
    int tx = threadIdx.x, ty = threadIdx.y;
#pragma unroll
    for (int j = 0; j < 4; ++j)
        t[ty + j * 8][tx] =
            V[(size_t)bh * (kS * kHD) + (size_t)(s0 + ty + j * 8) * kHD + d0 + tx];
    __syncthreads();
#pragma unroll
    for (int j = 0; j < 4; ++j) {
        float v = t[tx][ty + j * 8];
        __nv_bfloat16 h, l;
        split2(v, h, l);
        size_t o = ((size_t)bh * kHD + d0 + ty + j * 8) * kS + s0 + tx;
        g_vth[o] = h;
        g_vtl[o] = l;
    }
}

__global__ void detect_mask_kind_kernel(const unsigned int* __restrict__ m) {
    __shared__ int any_gt1, any_not_f32;
    if (threadIdx.x == 0) { any_gt1 = 0; any_not_f32 = 0; }
    __syncthreads();
    int gt1 = 0, nf32 = 0;
    for (int i = threadIdx.x; i < 16384; i += 256) {
        unsigned int w = m[i];
        if (w > 1u) gt1 = 1;
        if (w != 0u && w != 0x3F800000u) nf32 = 1;
    }
    if (gt1)  atomicOr(&any_gt1, 1);
    if (nf32) atomicOr(&any_not_f32, 1);
    __syncthreads();
    if (threadIdx.x == 0)
        g_mask_kind = (!any_gt1) ? 1 : ((!any_not_f32) ? 2 : 0);
}

// ---------------------------------------------------------------------------
// HMMA GEMM (proven R4 core). mode 0: row-major C. mode 1: QKV scatter:
// q -> bf16 hi/lo; k -> fp32 present + bf16 hi/lo; v -> fp32 present.
// ---------------------------------------------------------------------------
__global__ __launch_bounds__(256, 2) void mma_gemm_kernel(
    const __nv_bfloat16* __restrict__ Ah, const __nv_bfloat16* __restrict__ Al,
    const __nv_bfloat16* __restrict__ Bh, const __nv_bfloat16* __restrict__ Bl,
    const float* __restrict__ bias, float* __restrict__ C,
    int M, int N, int K, int mode,
    float* __restrict__ kout, float* __restrict__ vout)
{
    __shared__ __nv_bfloat16 sAh[128 * kSTR], sAl[128 * kSTR];
    __shared__ __nv_bfloat16 sBh[128 * kSTR], sBl[128 * kSTR];

    const int tid = threadIdx.x;
    const int lane = tid & 31;
    const int wid = tid >> 5;
    const int wm = (wid & 3) * 32;
    const int wn = (wid >> 2) * 64;
    const int m0 = blockIdx.y * 128;
    const int n0 = blockIdx.x * 128;
    const int gID = lane >> 2;
    const int tig2 = (lane & 3) * 2;

    float acc[2][8][4] = {};

    for (int c = 0; c < K / 32; ++c) {
#pragma unroll
        for (int j = 0; j < 2; ++j) {
            int unit = tid + j * 256;
            int rr = unit >> 2;
            int uu = unit & 3;
            size_t ga = (size_t)(m0 + rr) * K + c * 32 + uu * 8;
            size_t gb = (size_t)(n0 + rr) * K + c * 32 + uu * 8;
            int so = rr * kSTR + uu * 8;
            *(float4*)&sAh[so] = *(const float4*)&Ah[ga];
            *(float4*)&sAl[so] = *(const float4*)&Al[ga];
            *(float4*)&sBh[so] = *(const float4*)&Bh[gb];
            *(float4*)&sBl[so] = *(const float4*)&Bl[gb];
        }
        __syncthreads();

#pragma unroll
        for (int ks = 0; ks < 2; ++ks) {
            const int k0 = ks * 16;
            uint32_t ah[2][4], al[2][4];
#pragma unroll
            for (int mi = 0; mi < 2; ++mi) {
                int base = (wm + mi * 16 + gID) * kSTR + k0 + tig2;
                ah[mi][0] = *(const uint32_t*)&sAh[base];
                ah[mi][1] = *(const uint32_t*)&sAh[base + 8 * kSTR];
                ah[mi][2] = *(const uint32_t*)&sAh[base + 8];
                ah[mi][3] = *(const uint32_t*)&sAh[base + 8 * kSTR + 8];
                al[mi][0] = *(const uint32_t*)&sAl[base];
                al[mi][1] = *(const uint32_t*)&sAl[base + 8 * kSTR];
                al[mi][2] = *(const uint32_t*)&sAl[base + 8];
                al[mi][3] = *(const uint32_t*)&sAl[base + 8 * kSTR + 8];
            }
#pragma unroll
            for (int nt = 0; nt < 8; ++nt) {
                int nb = (wn + nt * 8 + gID) * kSTR + k0 + tig2;
                uint32_t bh0 = *(const uint32_t*)&sBh[nb];
                uint32_t bh1 = *(const uint32_t*)&sBh[nb + 8];
                mma16816(acc[0][nt], ah[0], bh0, bh1);
                mma16816(acc[1][nt], ah[1], bh0, bh1);
                mma16816(acc[0][nt], al[0], bh0, bh1);
                mma16816(acc[1][nt], al[1], bh0, bh1);
                uint32_t bl0 = *(const uint32_t*)&sBl[nb];
                uint32_t bl1 = *(const uint32_t*)&sBl[nb + 8];
                mma16816(acc[0][nt], ah[0], bl0, bl1);
                mma16816(acc[1][nt], ah[1], bl0, bl1);
            }
        }
        __syncthreads();
    }

#pragma unroll
    for (int mi = 0; mi < 2; ++mi) {
#pragma unroll
        for (int nt = 0; nt < 8; ++nt) {
            int m = m0 + wm + mi * 16 + gID;
            int n = n0 + wn + nt * 8 + tig2;
            float b0 = bias[n], b1 = bias[n + 1];
            float v0 = acc[mi][nt][0] + b0;
            float v1 = acc[mi][nt][1] + b1;
            float v2 = acc[mi][nt][2] + b0;
            float v3 = acc[mi][nt][3] + b1;
            if (mode == 0) {
                *(float2*)&C[(size_t)m * N + n] = make_float2(v0, v1);
                *(float2*)&C[(size_t)(m + 8) * N + n] = make_float2(v2, v3);
            } else {
                int sec = n >> 10;
                int e = n & 1023;
                int h = e >> 6;
                int d = e & 63;
#pragma unroll
                for (int rr = 0; rr < 2; ++rr) {
                    int mm = m + rr * 8;
                    int bb = mm >> 10;
                    int s = mm & 1023;
                    size_t idx = (((size_t)(bb * kH + h)) * kS + s) * kHD + d;
                    float p0 = rr ? v2 : v0, p1 = rr ? v3 : v1;
                    if (sec == 0) {
                        uint32_t hw, lw;
                        packsplit(p0, p1, hw, lw);
                        *(uint32_t*)&g_qh[idx] = hw;
                        *(uint32_t*)&g_ql[idx] = lw;
                    } else if (sec == 1) {
                        *(float2*)&kout[idx] = make_float2(p0, p1);
                        uint32_t hw, lw;
                        packsplit(p0, p1, hw, lw);
                        *(uint32_t*)&g_kh[idx] = hw;
                        *(uint32_t*)&g_kl[idx] = lw;
                    } else {
                        *(float2*)&vout[idx] = make_float2(p0, p1);
                    }
                }
            }
        }
    }
}

// ---------------------------------------------------------------------------
// OV kernel: g_a[b*S+q][h*64+d] = sum_k (mask? ov : 0)[h,q,k] * V[b,h,k,d]
// ---------------------------------------------------------------------------
__global__ __launch_bounds__(256, 2) void ov_kernel(
    const float* __restrict__ ov, const void* __restrict__ mask,
    float* __restrict__ out)
{
    __shared__ __nv_bfloat16 sVh[64 * 136], sVl[64 * 136];
    const int tid = threadIdx.x, lane = tid & 31, wid = tid >> 5;
    const int gID = lane >> 2, tig2 = (lane & 3) * 2;
    const int b = blockIdx.z, h = blockIdx.y, q0 = blockIdx.x * 128;
    const int wq = wid * 16;
    const int mkind = g_mask_kind;
    const size_t bhT = (size_t)(b * kH + h) * kHD;
    const int qr0 = q0 + wq + gID, qr1 = qr0 + 8;
    const size_t mr0 = ((size_t)h * kS + qr0) * kS;
    const size_t mr1 = ((size_t)h * kS + qr1) * kS;

    float o[8][4] = {};

    for (int kc = 0; kc < 8; ++kc) {
#pragma unroll
        for (int it = 0; it < 4; ++it) {
            int unit = tid + it * 256;
            int row = unit >> 4, u = (unit & 15) * 8;
            *(float4*)&sVh[row * 136 + u] =
                *(const float4*)&g_vth[(bhT + row) * kS + kc * 128 + u];
            *(float4*)&sVl[row * 136 + u] =
                *(const float4*)&g_vtl[(bhT + row) * kS + kc * 128 + u];
        }
        __syncthreads();

#pragma unroll
        for (int ks = 0; ks < 8; ++ks) {
            size_t kg = (size_t)kc * 128 + ks * 16 + tig2;
            uint2 m00 = mask2(mask, mr0 + kg, mkind);
            uint2 m02 = mask2(mask, mr0 + kg + 8, mkind);
            uint2 m10 = mask2(mask, mr1 + kg, mkind);
            uint2 m12 = mask2(mask, mr1 + kg + 8, mkind);
            float2 v00 = *(const float2*)&ov[mr0 + kg];
            float2 v02 = *(const float2*)&ov[mr0 + kg + 8];
            float2 v10 = *(const float2*)&ov[mr1 + kg];
            float2 v12 = *(const float2*)&ov[mr1 + kg + 8];
            float f00x = m00.x ? v00.x : 0.f, f00y = m00.y ? v00.y : 0.f;
            float f02x = m02.x ? v02.x : 0.f, f02y = m02.y ? v02.y : 0.f;
            float f10x = m10.x ? v10.x : 0.f, f10y = m10.y ? v10.y : 0.f;
            float f12x = m12.x ? v12.x : 0.f, f12y = m12.y ? v12.y : 0.f;
            uint32_t ah[4], al[4];
            packsplit(f00x, f00y, ah[0], al[0]);
            packsplit(f10x, f10y, ah[1], al[1]);
            packsplit(f02x, f02y, ah[2], al[2]);
            packsplit(f12x, f12y, ah[3], al[3]);
#pragma unroll
            for (int dn = 0; dn < 8; ++dn) {
                int vb = (dn * 8 + gID) * 136 + ks * 16 + tig2;
                uint32_t b0 = *(const uint32_t*)&sVh[vb];
                uint32_t b1 = *(const uint32_t*)&sVh[vb + 8];
                mma16816(o[dn], ah, b0, b1);
                mma16816(o[dn], al, b0, b1);
                uint32_t c0 = *(const uint32_t*)&sVl[vb];
                uint32_t c1 = *(const uint32_t*)&sVl[vb + 8];
                mma16816(o[dn], ah, c0, c1);
            }
        }
        __syncthreads();
    }

#pragma unroll
    for (int dn = 0; dn < 8; ++dn) {
        int d = h * kHD + dn * 8 + tig2;
        *(float2*)&out[(size_t)(b * kS + qr0) * kD + d] =
            make_float2(o[dn][0], o[dn][1]);
        *(float2*)&out[(size_t)(b * kS + qr1) * kD + d] =
            make_float2(o[dn][2], o[dn][3]);
    }
}

// ---------------------------------------------------------------------------
// Flash kernel: O1 = (causal-exp, masked-zeroed) E @ V; g_a += O1 / Z.
// One CTA per (b, h, 128 q rows). Chunks kc > q-tile are identically zero
// under the causal predicate and are skipped entirely.
// ---------------------------------------------------------------------------
__global__ __launch_bounds__(256, 2) void flash_kernel(
    const void* __restrict__ mask, float* __restrict__ aio)
{
    extern __shared__ __nv_bfloat16 fsm[];
    __nv_bfloat16* sKh = fsm + F_KH;   // [128][72]
    __nv_bfloat16* sKl = fsm + F_KL;
    __nv_bfloat16* sVh = fsm + F_VH;   // [64][136]
    __nv_bfloat16* sVl = fsm + F_VL;

    const int tid = threadIdx.x, lane = tid & 31, wid = tid >> 5;
    const int gID = lane >> 2, tig2 = (lane & 3) * 2;
    const int b = blockIdx.z, h = blockIdx.y;
    const int qt = blockIdx.x;           // q tile index
    const int q0 = qt * 128;
    const int wq = wid * 16;
    const int mkind = g_mask_kind;
    const size_t bh = (size_t)(b * kH + h) * kS * kHD;
    const size_t bhT = (size_t)(b * kH + h) * kHD;

    // stage Q tile, load register fragments
#pragma unroll
    for (int it = 0; it < 4; ++it) {
        int unit = tid + it * 256;
        int row = unit >> 3, u = (unit & 7) * 8;
        *(float4*)&sKh[row * 72 + u] =
            *(const float4*)&g_qh[bh + (size_t)(q0 + row) * kHD + u];
        *(float4*)&sKl[row * 72 + u] =
            *(const float4*)&g_ql[bh + (size_t)(q0 + row) * kHD + u];
    }
    __syncthreads();
    uint32_t qfh[4][4], qfl[4][4];
#pragma unroll
    for (int ks = 0; ks < 4; ++ks) {
        int base = (wq + gID) * 72 + ks * 16 + tig2;
        qfh[ks][0] = *(const uint32_t*)&sKh[base];
        qfh[ks][1] = *(const uint32_t*)&sKh[base + 8 * 72];
        qfh[ks][2] = *(const uint32_t*)&sKh[base + 8];
        qfh[ks][3] = *(const uint32_t*)&sKh[base + 8 * 72 + 8];
        qfl[ks][0] = *(const uint32_t*)&sKl[base];
        qfl[ks][1] = *(const uint32_t*)&sKl[base + 8 * 72];
        qfl[ks][2] = *(const uint32_t*)&sKl[base + 8];
        qfl[ks][3] = *(const uint32_t*)&sKl[base + 8 * 72 + 8];
    }
    __syncthreads();

    float o[8][4] = {};
    float Z0 = 0.f, Z1 = 0.f;
    const int qr0 = q0 + wq + gID, qr1 = qr0 + 8;
    const size_t mr0 = ((size_t)h * kS + qr0) * kS;
    const size_t mr1 = ((size_t)h * kS + qr1) * kS;

    // causal skip: chunks kc > qt contribute nothing (e == 0 for all kg > qr)
    for (int kc = 0; kc <= qt; ++kc) {
#pragma unroll
        for (int it = 0; it < 4; ++it) {
            int unit = tid + it * 256;
            int row = unit >> 3, u = (unit & 7) * 8;
            *(float4*)&sKh[row * 72 + u] =
                *(const float4*)&g_kh[bh + (size_t)(kc * 128 + row) * kHD + u];
            *(float4*)&sKl[row * 72 + u] =
                *(const float4*)&g_kl[bh + (size_t)(kc * 128 + row) * kHD + u];
        }
#pragma unroll
        for (int it = 0; it < 4; ++it) {
            int unit = tid + it * 256;
            int row = unit >> 4, u = (unit & 15) * 8;
            *(float4*)&sVh[row * 136 + u] =
                *(const float4*)&g_vth[(bhT + row) * kS + kc * 128 + u];
            *(float4*)&sVl[row * 136 + u] =
                *(const float4*)&g_vtl[(bhT + row) * kS + kc * 128 + u];
        }
        __syncthreads();

        for (int qq = 0; qq < 4; ++qq) {  // 32-key quarters of the chunk
            float sa[4][4] = {};
#pragma unroll
            for (int ks = 0; ks < 4; ++ks)
#pragma unroll
                for (int nt = 0; nt < 4; ++nt) {
                    int kb = (qq * 32 + nt * 8 + gID) * 72 + ks * 16 + tig2;
                    uint32_t b0 = *(const uint32_t*)&sKh[kb];
                    uint32_t b1 = *(const uint32_t*)&sKh[kb + 8];
                    mma16816(sa[nt], qfh[ks], b0, b1);
                    mma16816(sa[nt], qfl[ks], b0, b1);
                    uint32_t c0 = *(const uint32_t*)&sKl[kb];
                    uint32_t c1 = *(const uint32_t*)&sKl[kb + 8];
                    mma16816(sa[nt], qfh[ks], c0, c1);
                }

            uint32_t ehr0[4], ehr1[4], elr0[4], elr1[4];
#pragma unroll
            for (int nt = 0; nt < 4; ++nt) {
                int kg = kc * 128 + qq * 32 + nt * 8 + tig2;
                float e00 = (kg     <= qr0) ? __expf(sa[nt][0] * 0.125f) : 0.f;
                float e01 = (kg + 1 <= qr0) ? __expf(sa[nt][1] * 0.125f) : 0.f;
                float e10 = (kg     <= qr1) ? __expf(sa[nt][2] * 0.125f) : 0.f;
                float e11 = (kg + 1 <= qr1) ? __expf(sa[nt][3] * 0.125f) : 0.f;
                Z0 += e00 + e01;
                Z1 += e10 + e11;
                uint2 m0 = mask2(mask, mr0 + kg, mkind);
                uint2 m1 = mask2(mask, mr1 + kg, mkind);
                if (m0.x) e00 = 0.f;
                if (m0.y) e01 = 0.f;
                if (m1.x) e10 = 0.f;
                if (m1.y) e11 = 0.f;
                packsplit(e00, e01, ehr0[nt], elr0[nt]);
                packsplit(e10, e11, ehr1[nt], elr1[nt]);
            }
#pragma unroll
            for (int k2 = 0; k2 < 2; ++k2) {
                uint32_t ah[4] = {ehr0[2 * k2], ehr1[2 * k2],
                                  ehr0[2 * k2 + 1], ehr1[2 * k2 + 1]};
                uint32_t al[4] = {elr0[2 * k2], elr1[2 * k2],
                                  elr0[2 * k2 + 1], elr1[2 * k2 + 1]};
#pragma unroll
                for (int dn = 0; dn < 8; ++dn) {
                    int vb = (dn * 8 + gID) * 136 + qq * 32 + k2 * 16 + tig2;
                    uint32_t b0 = *(const uint32_t*)&sVh[vb];
                    uint32_t b1 = *(const uint32_t*)&sVh[vb + 8];
                    mma16816(o[dn], ah, b0, b1);
                    mma16816(o[dn], al, b0, b1);
                    uint32_t c0 = *(const uint32_t*)&sVl[vb];
                    uint32_t c1 = *(const uint32_t*)&sVl[vb + 8];
                    mma16816(o[dn], ah, c0, c1);
                }
            }
        }
        __syncthreads();
    }

    Z0 += __shfl_xor_sync(0xffffffffu, Z0, 1);
    Z0 += __shfl_xor_sync(0xffffffffu, Z0, 2);
    Z1 += __shfl_xor_sync(0xffffffffu, Z1, 1);
    Z1 += __shfl_xor_sync(0xffffffffu, Z1, 2);
    float i0 = 1.f / Z0, i1 = 1.f / Z1;

#pragma unroll
    for (int dn = 0; dn < 8; ++dn) {
        int d = h * kHD + dn * 8 + tig2;
        size_t r0 = (size_t)(b * kS + qr0) * kD + d;
        size_t r1 = (size_t)(b * kS + qr1) * kD + d;
        float2 p0 = *(float2*)&aio[r0];
        float2 p1 = *(float2*)&aio[r1];
        *(float2*)&aio[r0] =
            make_float2(p0.x + o[dn][0] * i0, p0.y + o[dn][1] * i0);
        *(float2*)&aio[r1] =
            make_float2(p1.x + o[dn][2] * i1, p1.y + o[dn][3] * i1);
    }
}

// ---------------------------------------------------------------------------
extern "C" void kernel_launch(void* const* d_in, const int* in_sizes, int n_in,
                              void* d_out, int out_size)
{
    const float* x       = (const float*)d_in[0];
    const float* w_attn  = (const float*)d_in[1];
    const float* b_attn  = (const float*)d_in[2];
    const float* w_proj  = (const float*)d_in[3];
    const float* b_proj  = (const float*)d_in[4];
    const float* ov      = (const float*)d_in[5];
    const void*  msk     = (const void*)d_in[6];

    float* out = (float*)d_out;
    float* presentK = out + (size_t)kM * kD;
    float* presentV = presentK + (size_t)kB * kH * kS * kHD;

    float* aptr = nullptr;
    __nv_bfloat16 *xh, *xl, *ah, *al, *wth, *wtl, *pth, *ptl;
    cudaGetSymbolAddress((void**)&aptr, g_a);
    cudaGetSymbolAddress((void**)&xh, g_xh);
    cudaGetSymbolAddress((void**)&xl, g_xl);
    cudaGetSymbolAddress((void**)&ah, g_ah);
    cudaGetSymbolAddress((void**)&al, g_al);
    cudaGetSymbolAddress((void**)&wth, g_wth);
    cudaGetSymbolAddress((void**)&wtl, g_wtl);
    cudaGetSymbolAddress((void**)&pth, g_pth);
    cudaGetSymbolAddress((void**)&ptl, g_ptl);

    cudaFuncSetAttribute(flash_kernel,
                         cudaFuncAttributeMaxDynamicSharedMemorySize,
                         FLASH_SMEM_BYTES);

    // 0) mask classification + operand prep
    detect_mask_kind_kernel<<<1, 256>>>((const unsigned int*)msk);
    split_kernel<<<kM * kD / 256, 256>>>(x, xh, xl, kM * kD);
    transpose_split_kernel<<<dim3(3 * kD / 32, kD / 32), dim3(32, 8)>>>(
        w_attn, wth, wtl, kD, 3 * kD);
    transpose_split_kernel<<<dim3(kD / 32, kD / 32), dim3(32, 8)>>>(
        w_proj, pth, ptl, kD, kD);

    // 1) QKV GEMM -> present fp32 + q/k bf16 hi/lo
    mma_gemm_kernel<<<dim3(3 * kD / 128, kM / 128), 256>>>(
        xh, xl, wth, wtl, b_attn, nullptr, kM, 3 * kD, kD, 1, presentK, presentV);

    // 2) V transpose+split -> g_vt
    vtrans_kernel<<<dim3(kHD / 32, kS / 32, kB * kH), dim3(32, 8)>>>(presentV);

    // 3) override term -> g_a (full overwrite)
    ov_kernel<<<dim3(kS / 128, kH, kB), 256>>>(ov, msk, aptr);

    // 4) flash attention adds softmax term -> g_a (causal-skipped chunks)
    flash_kernel<<<dim3(kS / 128, kH, kB), 256, FLASH_SMEM_BYTES>>>(msk, aptr);

    // 5) split g_a, output projection
    split_kernel<<<kM * kD / 256, 256>>>(aptr, ah, al, kM * kD);
    mma_gemm_kernel<<<dim3(kD / 128, kM / 128), 256>>>(
        ah, al, pth, ptl, b_proj, out, kM, kD, kD, 0, nullptr, nullptr);
}

// round 8
// speedup vs baseline: 2.2724x; 1.2022x over previous
#include <cuda_runtime.h>
#include <cuda_fp16.h>
#include <cstdint>

// ---------------------------------------------------------------------------
// AttentionOverride, round 8: fp16 hi/lo arithmetic.
//   2-product (A exact, B fp16-rounded) for QKV, proj, ov, E@V  (err ~2^-12)
//   3-product for flash QK^T (scores feed exp)                  (err ~2^-22)
// O = (E_unmasked @ V)/Z + (mask?ov:0) @ V, causal chunk skipping.
// Output layout: [ a (4M floats) | presentK (4M) | presentV (4M) ]
// ---------------------------------------------------------------------------

namespace {
constexpr int kB  = 4;
constexpr int kS  = 1024;
constexpr int kD  = 1024;
constexpr int kH  = 16;
constexpr int kHD = 64;
constexpr int kM  = kB * kS;  // 4096

constexpr int kSTR = 40;  // GEMM smem stride (half)

// flash smem (half elems): K[128][72] hi/lo, Vh[64][136]
constexpr int F_KH = 0;
constexpr int F_KL = 9216;
constexpr int F_VH = 18432;
constexpr int FLASH_SMEM_BYTES = (18432 + 8704) * 2;  // 54272
}  // namespace

// scratch (device globals; no allocation allowed)
__device__ float g_a[(size_t)kM * kD];
__device__ int   g_mask_kind;
__device__ __half g_qh[(size_t)kM * kD], g_ql[(size_t)kM * kD];
__device__ __half g_kh[(size_t)kM * kD], g_kl[(size_t)kM * kD];
__device__ __half g_vth[(size_t)kM * kD];                    // [BH][64][S] hi only
__device__ __half g_xh[(size_t)kM * kD], g_xl[(size_t)kM * kD];
__device__ __half g_ah[(size_t)kM * kD], g_al[(size_t)kM * kD];
__device__ __half g_wth[(size_t)3 * kD * kD];                // w_attn^T hi only
__device__ __half g_pth[(size_t)kD * kD];                    // w_proj^T hi only

// ---------------------------------------------------------------------------
__device__ __forceinline__ void mma16816(float* c, const uint32_t* a,
                                         uint32_t b0, uint32_t b1) {
    asm volatile(
        "mma.sync.aligned.m16n8k16.row.col.f32.f16.f16.f32 "
        "{%0,%1,%2,%3}, {%4,%5,%6,%7}, {%8,%9}, {%0,%1,%2,%3};"
        : "+f"(c[0]), "+f"(c[1]), "+f"(c[2]), "+f"(c[3])
        : "r"(a[0]), "r"(a[1]), "r"(a[2]), "r"(a[3]), "r"(b0), "r"(b1));
}

__device__ __forceinline__ void split2(float x, __half& h, __half& l) {
    h = __float2half_rn(x);
    l = __float2half_rn(x - __half2float(h));
}
__device__ __forceinline__ uint32_t packh(__half a, __half b) {
    __half2 t = __halves2half2(a, b);
    return *(uint32_t*)&t;
}
__device__ __forceinline__ void packsplit(float x, float y,
                                          uint32_t& hw, uint32_t& lw) {
    __half hx, lx, hy, ly;
    split2(x, hx, lx);
    split2(y, hy, ly);
    hw = packh(hx, hy);
    lw = packh(lx, ly);
}

__device__ __forceinline__ uint2 mask2(const void* m, size_t i, int kind) {
    if (kind == 0) {
        const unsigned char* p = (const unsigned char*)m;
        return make_uint2(p[i], p[i + 1]);
    }
    return *(const uint2*)((const unsigned int*)m + i);
}

// ---------------------------------------------------------------------------
__global__ void split_kernel(const float* __restrict__ X,
                             __half* __restrict__ H,
                             __half* __restrict__ L, int n) {
    int i = blockIdx.x * 256 + threadIdx.x;
    if (i < n) split2(X[i], H[i], L[i]);
}

// W[K,N] fp32 -> Th [N,K] fp16 (hi only)
__global__ void transpose_h_kernel(const float* __restrict__ W,
                                   __half* __restrict__ Th, int K, int N) {
    __shared__ float t[32][33];
    int n0 = blockIdx.x * 32, k0 = blockIdx.y * 32;
    int tx = threadIdx.x, ty = threadIdx.y;
#pragma unroll
    for (int j = 0; j < 4; ++j)
        t[ty + j * 8][tx] = W[(size_t)(k0 + ty + j * 8) * N + n0 + tx];
    __syncthreads();
#pragma unroll
    for (int j = 0; j < 4; ++j)
        Th[(size_t)(n0 + ty + j * 8) * K + k0 + tx] =
            __float2half_rn(t[tx][ty + j * 8]);
}

// presentV fp32 [BH][S][64] -> g_vth fp16 [BH][64][S]
__global__ void vtrans_kernel(const float* __restrict__ V) {
    __shared__ float t[32][33];
    int d0 = blockIdx.x * 32, s0 = blockIdx.y * 32, bh = blockIdx.z;
    int tx = threadIdx.x, ty = threadIdx.y;
#pragma unroll
    for (int j = 0; j < 4; ++j)
        t[ty + j * 8][tx] =
            V[(size_t)bh * (kS * kHD) + (size_t)(s0 + ty + j * 8) * kHD + d0 + tx];
    __syncthreads();
#pragma unroll
    for (int j = 0; j < 4; ++j)
        g_vth[((size_t)bh * kHD + d0 + ty + j * 8) * kS + s0 + tx] =
            __float2half_rn(t[tx][ty + j * 8]);
}

__global__ void detect_mask_kind_kernel(const unsigned int* __restrict__ m) {
    __shared__ int any_gt1, any_not_f32;
    if (threadIdx.x == 0) { any_gt1 = 0; any_not_f32 = 0; }
    __syncthreads();
    int gt1 = 0, nf32 = 0;
    for (int i = threadIdx.x; i < 16384; i += 256) {
        unsigned int w = m[i];
        if (w > 1u) gt1 = 1;
        if (w != 0u && w != 0x3F800000u) nf32 = 1;
    }
    if (gt1)  atomicOr(&any_gt1, 1);
    if (nf32) atomicOr(&any_not_f32, 1);
    __syncthreads();
    if (threadIdx.x == 0)
        g_mask_kind = (!any_gt1) ? 1 : ((!any_not_f32) ? 2 : 0);
}

// ---------------------------------------------------------------------------
// HMMA GEMM, fp16 2-product: C = (Ah+Al) @ Bh^T + bias.
// mode 0: row-major C. mode 1: QKV scatter.
// ---------------------------------------------------------------------------
__global__ __launch_bounds__(256, 2) void mma_gemm_kernel(
    const __half* __restrict__ Ah, const __half* __restrict__ Al,
    const __half* __restrict__ Bh,
    const float* __restrict__ bias, float* __restrict__ C,
    int M, int N, int K, int mode,
    float* __restrict__ kout, float* __restrict__ vout)
{
    __shared__ __half sAh[128 * kSTR], sAl[128 * kSTR], sBh[128 * kSTR];

    const int tid = threadIdx.x;
    const int lane = tid & 31;
    const int wid = tid >> 5;
    const int wm = (wid & 3) * 32;
    const int wn = (wid >> 2) * 64;
    const int m0 = blockIdx.y * 128;
    const int n0 = blockIdx.x * 128;
    const int gID = lane >> 2;
    const int tig2 = (lane & 3) * 2;

    float acc[2][8][4] = {};

    for (int c = 0; c < K / 32; ++c) {
#pragma unroll
        for (int j = 0; j < 2; ++j) {
            int unit = tid + j * 256;
            int rr = unit >> 2;
            int uu = unit & 3;
            size_t ga = (size_t)(m0 + rr) * K + c * 32 + uu * 8;
            size_t gb = (size_t)(n0 + rr) * K + c * 32 + uu * 8;
            int so = rr * kSTR + uu * 8;
            *(float4*)&sAh[so] = *(const float4*)&Ah[ga];
            *(float4*)&sAl[so] = *(const float4*)&Al[ga];
            *(float4*)&sBh[so] = *(const float4*)&Bh[gb];
        }
        __syncthreads();

#pragma unroll
        for (int ks = 0; ks < 2; ++ks) {
            const int k0 = ks * 16;
            uint32_t ah[2][4], al[2][4];
#pragma unroll
            for (int mi = 0; mi < 2; ++mi) {
                int base = (wm + mi * 16 + gID) * kSTR + k0 + tig2;
                ah[mi][0] = *(const uint32_t*)&sAh[base];
                ah[mi][1] = *(const uint32_t*)&sAh[base + 8 * kSTR];
                ah[mi][2] = *(const uint32_t*)&sAh[base + 8];
                ah[mi][3] = *(const uint32_t*)&sAh[base + 8 * kSTR + 8];
                al[mi][0] = *(const uint32_t*)&sAl[base];
                al[mi][1] = *(const uint32_t*)&sAl[base + 8 * kSTR];
                al[mi][2] = *(const uint32_t*)&sAl[base + 8];
                al[mi][3] = *(const uint32_t*)&sAl[base + 8 * kSTR + 8];
            }
#pragma unroll
            for (int nt = 0; nt < 8; ++nt) {
                int nb = (wn + nt * 8 + gID) * kSTR + k0 + tig2;
                uint32_t bh0 = *(const uint32_t*)&sBh[nb];
                uint32_t bh1 = *(const uint32_t*)&sBh[nb + 8];
                mma16816(acc[0][nt], ah[0], bh0, bh1);
                mma16816(acc[1][nt], ah[1], bh0, bh1);
                mma16816(acc[0][nt], al[0], bh0, bh1);
                mma16816(acc[1][nt], al[1], bh0, bh1);
            }
        }
        __syncthreads();
    }

#pragma unroll
    for (int mi = 0; mi < 2; ++mi) {
#pragma unroll
        for (int nt = 0; nt < 8; ++nt) {
            int m = m0 + wm + mi * 16 + gID;
            int n = n0 + wn + nt * 8 + tig2;
            float b0 = bias[n], b1 = bias[n + 1];
            float v0 = acc[mi][nt][0] + b0;
            float v1 = acc[mi][nt][1] + b1;
            float v2 = acc[mi][nt][2] + b0;
            float v3 = acc[mi][nt][3] + b1;
            if (mode == 0) {
                *(float2*)&C[(size_t)m * N + n] = make_float2(v0, v1);
                *(float2*)&C[(size_t)(m + 8) * N + n] = make_float2(v2, v3);
            } else {
                int sec = n >> 10;
                int e = n & 1023;
                int h = e >> 6;
                int d = e & 63;
#pragma unroll
                for (int rr = 0; rr < 2; ++rr) {
                    int mm = m + rr * 8;
                    int bb = mm >> 10;
                    int s = mm & 1023;
                    size_t idx = (((size_t)(bb * kH + h)) * kS + s) * kHD + d;
                    float p0 = rr ? v2 : v0, p1 = rr ? v3 : v1;
                    if (sec == 0) {
                        uint32_t hw, lw;
                        packsplit(p0, p1, hw, lw);
                        *(uint32_t*)&g_qh[idx] = hw;
                        *(uint32_t*)&g_ql[idx] = lw;
                    } else if (sec == 1) {
                        *(float2*)&kout[idx] = make_float2(p0, p1);
                        uint32_t hw, lw;
                        packsplit(p0, p1, hw, lw);
                        *(uint32_t*)&g_kh[idx] = hw;
                        *(uint32_t*)&g_kl[idx] = lw;
                    } else {
                        *(float2*)&vout[idx] = make_float2(p0, p1);
                    }
                }
            }
        }
    }
}

// ---------------------------------------------------------------------------
// OV kernel: g_a = (mask? ov : 0) @ V ; E exact (hi/lo), V fp16-rounded.
// ---------------------------------------------------------------------------
__global__ __launch_bounds__(256, 2) void ov_kernel(
    const float* __restrict__ ov, const void* __restrict__ mask,
    float* __restrict__ out)
{
    __shared__ __half sVh[64 * 136];
    const int tid = threadIdx.x, lane = tid & 31, wid = tid >> 5;
    const int gID = lane >> 2, tig2 = (lane & 3) * 2;
    const int b = blockIdx.z, h = blockIdx.y, q0 = blockIdx.x * 128;
    const int wq = wid * 16;
    const int mkind = g_mask_kind;
    const size_t bhT = (size_t)(b * kH + h) * kHD;
    const int qr0 = q0 + wq + gID, qr1 = qr0 + 8;
    const size_t mr0 = ((size_t)h * kS + qr0) * kS;
    const size_t mr1 = ((size_t)h * kS + qr1) * kS;

    float o[8][4] = {};

    for (int kc = 0; kc < 8; ++kc) {
#pragma unroll
        for (int it = 0; it < 2; ++it) {
            int unit = tid + it * 256;
            int row = unit >> 3, u = (unit & 7) * 16;
            *(float4*)&sVh[row * 136 + u] =
                *(const float4*)&g_vth[(bhT + row) * kS + kc * 128 + u];
            *(float4*)&sVh[row * 136 + u + 8] =
                *(const float4*)&g_vth[(bhT + row) * kS + kc * 128 + u + 8];
        }
        __syncthreads();

#pragma unroll
        for (int ks = 0; ks < 8; ++ks) {
            size_t kg = (size_t)kc * 128 + ks * 16 + tig2;
            uint2 m00 = mask2(mask, mr0 + kg, mkind);
            uint2 m02 = mask2(mask, mr0 + kg + 8, mkind);
            uint2 m10 = mask2(mask, mr1 + kg, mkind);
            uint2 m12 = mask2(mask, mr1 + kg + 8, mkind);
            float2 v00 = *(const float2*)&ov[mr0 + kg];
            float2 v02 = *(const float2*)&ov[mr0 + kg + 8];
            float2 v10 = *(const float2*)&ov[mr1 + kg];
            float2 v12 = *(const float2*)&ov[mr1 + kg + 8];
            float f00x = m00.x ? v00.x : 0.f, f00y = m00.y ? v00.y : 0.f;
            float f02x = m02.x ? v02.x : 0.f, f02y = m02.y ? v02.y : 0.f;
            float f10x = m10.x ? v10.x : 0.f, f10y = m10.y ? v10.y : 0.f;
            float f12x = m12.x ? v12.x : 0.f, f12y = m12.y ? v12.y : 0.f;
            uint32_t ah[4], al[4];
            packsplit(f00x, f00y, ah[0], al[0]);
            packsplit(f10x, f10y, ah[1], al[1]);
            packsplit(f02x, f02y, ah[2], al[2]);
            packsplit(f12x, f12y, ah[3], al[3]);
#pragma unroll
            for (int dn = 0; dn < 8; ++dn) {
                int vb = (dn * 8 + gID) * 136 + ks * 16 + tig2;
                uint32_t b0 = *(const uint32_t*)&sVh[vb];
                uint32_t b1 = *(const uint32_t*)&sVh[vb + 8];
                mma16816(o[dn], ah, b0, b1);
                mma16816(o[dn], al, b0, b1);
            }
        }
        __syncthreads();
    }

#pragma unroll
    for (int dn = 0; dn < 8; ++dn) {
        int d = h * kHD + dn * 8 + tig2;
        *(float2*)&out[(size_t)(b * kS + qr0) * kD + d] =
            make_float2(o[dn][0], o[dn][1]);
        *(float2*)&out[(size_t)(b * kS + qr1) * kD + d] =
            make_float2(o[dn][2], o[dn][3]);
    }
}

// ---------------------------------------------------------------------------
// Flash kernel: O1 = (causal-exp, masked-zeroed) E @ V; g_a += O1 / Z.
// QK^T: 3-product fp16 (Qh·Kh + Ql·Kh + Qh·Kl). E@V: 2-product.
// Chunks kc > q-tile skipped (causal).
// ---------------------------------------------------------------------------
__global__ __launch_bounds__(256, 2) void flash_kernel(
    const void* __restrict__ mask, float* __restrict__ aio)
{
    extern __shared__ __half fsm[];
    __half* sKh = fsm + F_KH;   // [128][72]
    __half* sKl = fsm + F_KL;
    __half* sVh = fsm + F_VH;   // [64][136]

    const int tid = threadIdx.x, lane = tid & 31, wid = tid >> 5;
    const int gID = lane >> 2, tig2 = (lane & 3) * 2;
    const int b = blockIdx.z, h = blockIdx.y;
    const int qt = blockIdx.x;
    const int q0 = qt * 128;
    const int wq = wid * 16;
    const int mkind = g_mask_kind;
    const size_t bh = (size_t)(b * kH + h) * kS * kHD;
    const size_t bhT = (size_t)(b * kH + h) * kHD;

    // stage Q tile, load register fragments
#pragma unroll
    for (int it = 0; it < 4; ++it) {
        int unit = tid + it * 256;
        int row = unit >> 3, u = (unit & 7) * 8;
        *(float4*)&sKh[row * 72 + u] =
            *(const float4*)&g_qh[bh + (size_t)(q0 + row) * kHD + u];
        *(float4*)&sKl[row * 72 + u] =
            *(const float4*)&g_ql[bh + (size_t)(q0 + row) * kHD + u];
    }
    __syncthreads();
    uint32_t qfh[4][4], qfl[4][4];
#pragma unroll
    for (int ks = 0; ks < 4; ++ks) {
        int base = (wq + gID) * 72 + ks * 16 + tig2;
        qfh[ks][0] = *(const uint32_t*)&sKh[base];
        qfh[ks][1] = *(const uint32_t*)&sKh[base + 8 * 72];
        qfh[ks][2] = *(const uint32_t*)&sKh[base + 8];
        qfh[ks][3] = *(const uint32_t*)&sKh[base + 8 * 72 + 8];
        qfl[ks][0] = *(const uint32_t*)&sKl[base];
        qfl[ks][1] = *(const uint32_t*)&sKl[base + 8 * 72];
        qfl[ks][2] = *(const uint32_t*)&sKl[base + 8];
        qfl[ks][3] = *(const uint32_t*)&sKl[base + 8 * 72 + 8];
    }
    __syncthreads();

    float o[8][4] = {};
    float Z0 = 0.f, Z1 = 0.f;
    const int qr0 = q0 + wq + gID, qr1 = qr0 + 8;
    const size_t mr0 = ((size_t)h * kS + qr0) * kS;
    const size_t mr1 = ((size_t)h * kS + qr1) * kS;

    for (int kc = 0; kc <= qt; ++kc) {
#pragma unroll
        for (int it = 0; it < 4; ++it) {
            int unit = tid + it * 256;
            int row = unit >> 3, u = (unit & 7) * 8;
            *(float4*)&sKh[row * 72 + u] =
                *(const float4*)&g_kh[bh + (size_t)(kc * 128 + row) * kHD + u];
            *(float4*)&sKl[row * 72 + u] =
                *(const float4*)&g_kl[bh + (size_t)(kc * 128 + row) * kHD + u];
        }
#pragma unroll
        for (int it = 0; it < 2; ++it) {
            int unit = tid + it * 256;
            int row = unit >> 3, u = (unit & 7) * 16;
            *(float4*)&sVh[row * 136 + u] =
                *(const float4*)&g_vth[(bhT + row) * kS + kc * 128 + u];
            *(float4*)&sVh[row * 136 + u + 8] =
                *(const float4*)&g_vth[(bhT + row) * kS + kc * 128 + u + 8];
        }
        __syncthreads();

        for (int qq = 0; qq < 4; ++qq) {
            float sa[4][4] = {};
#pragma unroll
            for (int ks = 0; ks < 4; ++ks)
#pragma unroll
                for (int nt = 0; nt < 4; ++nt) {
                    int kb = (qq * 32 + nt * 8 + gID) * 72 + ks * 16 + tig2;
                    uint32_t b0 = *(const uint32_t*)&sKh[kb];
                    uint32_t b1 = *(const uint32_t*)&sKh[kb + 8];
                    mma16816(sa[nt], qfh[ks], b0, b1);
                    mma16816(sa[nt], qfl[ks], b0, b1);
                    uint32_t c0 = *(const uint32_t*)&sKl[kb];
                    uint32_t c1 = *(const uint32_t*)&sKl[kb + 8];
                    mma16816(sa[nt], qfh[ks], c0, c1);
                }

            uint32_t ehr0[4], ehr1[4], elr0[4], elr1[4];
#pragma unroll
            for (int nt = 0; nt < 4; ++nt) {
                int kg = kc * 128 + qq * 32 + nt * 8 + tig2;
                float e00 = (kg     <= qr0) ? __expf(sa[nt][0] * 0.125f) : 0.f;
                float e01 = (kg + 1 <= qr0) ? __expf(sa[nt][1] * 0.125f) : 0.f;
                float e10 = (kg     <= qr1) ? __expf(sa[nt][2] * 0.125f) : 0.f;
                float e11 = (kg + 1 <= qr1) ? __expf(sa[nt][3] * 0.125f) : 0.f;
                Z0 += e00 + e01;
                Z1 += e10 + e11;
                uint2 m0 = mask2(mask, mr0 + kg, mkind);
                uint2 m1 = mask2(mask, mr1 + kg, mkind);
                if (m0.x) e00 = 0.f;
                if (m0.y) e01 = 0.f;
                if (m1.x) e10 = 0.f;
                if (m1.y) e11 = 0.f;
                packsplit(e00, e01, ehr0[nt], elr0[nt]);
                packsplit(e10, e11, ehr1[nt], elr1[nt]);
            }
#pragma unroll
            for (int k2 = 0; k2 < 2; ++k2) {
                uint32_t ah[4] = {ehr0[2 * k2], ehr1[2 * k2],
                                  ehr0[2 * k2 + 1], ehr1[2 * k2 + 1]};
                uint32_t al[4] = {elr0[2 * k2], elr1[2 * k2],
                                  elr0[2 * k2 + 1], elr1[2 * k2 + 1]};
#pragma unroll
                for (int dn = 0; dn < 8; ++dn) {
                    int vb = (dn * 8 + gID) * 136 + qq * 32 + k2 * 16 + tig2;
                    uint32_t b0 = *(const uint32_t*)&sVh[vb];
                    uint32_t b1 = *(const uint32_t*)&sVh[vb + 8];
                    mma16816(o[dn], ah, b0, b1);
                    mma16816(o[dn], al, b0, b1);
                }
            }
        }
        __syncthreads();
    }

    Z0 += __shfl_xor_sync(0xffffffffu, Z0, 1);
    Z0 += __shfl_xor_sync(0xffffffffu, Z0, 2);
    Z1 += __shfl_xor_sync(0xffffffffu, Z1, 1);
    Z1 += __shfl_xor_sync(0xffffffffu, Z1, 2);
    float i0 = 1.f / Z0, i1 = 1.f / Z1;

#pragma unroll
    for (int dn = 0; dn < 8; ++dn) {
        int d = h * kHD + dn * 8 + tig2;
        size_t r0 = (size_t)(b * kS + qr0) * kD + d;
        size_t r1 = (size_t)(b * kS + qr1) * kD + d;
        float2 p0 = *(float2*)&aio[r0];
        float2 p1 = *(float2*)&aio[r1];
        *(float2*)&aio[r0] =
            make_float2(p0.x + o[dn][0] * i0, p0.y + o[dn][1] * i0);
        *(float2*)&aio[r1] =
            make_float2(p1.x + o[dn][2] * i1, p1.y + o[dn][3] * i1);
    }
}

// ---------------------------------------------------------------------------
extern "C" void kernel_launch(void* const* d_in, const int* in_sizes, int n_in,
                              void* d_out, int out_size)
{
    const float* x       = (const float*)d_in[0];
    const float* w_attn  = (const float*)d_in[1];
    const float* b_attn  = (const float*)d_in[2];
    const float* w_proj  = (const float*)d_in[3];
    const float* b_proj  = (const float*)d_in[4];
    const float* ov      = (const float*)d_in[5];
    const void*  msk     = (const void*)d_in[6];

    float* out = (float*)d_out;
    float* presentK = out + (size_t)kM * kD;
    float* presentV = presentK + (size_t)kB * kH * kS * kHD;

    float* aptr = nullptr;
    __half *xh, *xl, *ah, *al, *wth, *pth;
    cudaGetSymbolAddress((void**)&aptr, g_a);
    cudaGetSymbolAddress((void**)&xh, g_xh);
    cudaGetSymbolAddress((void**)&xl, g_xl);
    cudaGetSymbolAddress((void**)&ah, g_ah);
    cudaGetSymbolAddress((void**)&al, g_al);
    cudaGetSymbolAddress((void**)&wth, g_wth);
    cudaGetSymbolAddress((void**)&pth, g_pth);

    cudaFuncSetAttribute(flash_kernel,
                         cudaFuncAttributeMaxDynamicSharedMemorySize,
                         FLASH_SMEM_BYTES);

    // 0) mask classification + operand prep
    detect_mask_kind_kernel<<<1, 256>>>((const unsigned int*)msk);
    split_kernel<<<kM * kD / 256, 256>>>(x, xh, xl, kM * kD);
    transpose_h_kernel<<<dim3(3 * kD / 32, kD / 32), dim3(32, 8)>>>(
        w_attn, wth, kD, 3 * kD);
    transpose_h_kernel<<<dim3(kD / 32, kD / 32), dim3(32, 8)>>>(
        w_proj, pth, kD, kD);

    // 1) QKV GEMM -> present fp32 + q/k fp16 hi/lo
    mma_gemm_kernel<<<dim3(3 * kD / 128, kM / 128), 256>>>(
        xh, xl, wth, b_attn, nullptr, kM, 3 * kD, kD, 1, presentK, presentV);

    // 2) V transpose -> g_vth (fp16 hi)
    vtrans_kernel<<<dim3(kHD / 32, kS / 32, kB * kH), dim3(32, 8)>>>(presentV);

    // 3) override term -> g_a (full overwrite)
    ov_kernel<<<dim3(kS / 128, kH, kB), 256>>>(ov, msk, aptr);

    // 4) flash attention adds softmax term -> g_a
    flash_kernel<<<dim3(kS / 128, kH, kB), 256, FLASH_SMEM_BYTES>>>(msk, aptr);

    // 5) split g_a, output projection
    split_kernel<<<kM * kD / 256, 256>>>(aptr, ah, al, kM * kD);
    mma_gemm_kernel<<<dim3(kD / 128, kM / 128), 256>>>(
        ah, al, pth, b_proj, out, kM, kD, kD, 0, nullptr, nullptr);
}

// round 9
// speedup vs baseline: 2.9225x; 1.2861x over previous
#include <cuda_runtime.h>
#include <cuda_fp16.h>
#include <cstdint>

// ---------------------------------------------------------------------------
// AttentionOverride, round 9: fp16 1-product MMA for all stages not feeding
// exp (QKV, proj, ov, E@V); 3-product for flash QK^T (scores feed exp).
// O = (E_unmasked @ V)/Z + (mask?ov:0) @ V, causal chunk skipping.
// Output layout: [ a (4M floats) | presentK (4M) | presentV (4M) ]
// ---------------------------------------------------------------------------

namespace {
constexpr int kB  = 4;
constexpr int kS  = 1024;
constexpr int kD  = 1024;
constexpr int kH  = 16;
constexpr int kHD = 64;
constexpr int kM  = kB * kS;  // 4096

constexpr int kSTR = 40;  // GEMM smem stride (half)

// flash smem (half elems): K[128][72] hi/lo, Vh[64][136]
constexpr int F_KH = 0;
constexpr int F_KL = 9216;
constexpr int F_VH = 18432;
constexpr int FLASH_SMEM_BYTES = (18432 + 8704) * 2;  // 54272
}  // namespace

// scratch (device globals; no allocation allowed)
__device__ float g_a[(size_t)kM * kD];
__device__ int   g_mask_kind;
__device__ __half g_qh[(size_t)kM * kD], g_ql[(size_t)kM * kD];
__device__ __half g_kh[(size_t)kM * kD], g_kl[(size_t)kM * kD];
__device__ __half g_vth[(size_t)kM * kD];                    // [BH][64][S]
__device__ __half g_xh[(size_t)kM * kD];                     // x rounded
__device__ __half g_ah[(size_t)kM * kD];                     // g_a rounded
__device__ __half g_wth[(size_t)3 * kD * kD];                // w_attn^T
__device__ __half g_pth[(size_t)kD * kD];                    // w_proj^T

// ---------------------------------------------------------------------------
__device__ __forceinline__ void mma16816(float* c, const uint32_t* a,
                                         uint32_t b0, uint32_t b1) {
    asm volatile(
        "mma.sync.aligned.m16n8k16.row.col.f32.f16.f16.f32 "
        "{%0,%1,%2,%3}, {%4,%5,%6,%7}, {%8,%9}, {%0,%1,%2,%3};"
        : "+f"(c[0]), "+f"(c[1]), "+f"(c[2]), "+f"(c[3])
        : "r"(a[0]), "r"(a[1]), "r"(a[2]), "r"(a[3]), "r"(b0), "r"(b1));
}

__device__ __forceinline__ void split2(float x, __half& h, __half& l) {
    h = __float2half_rn(x);
    l = __float2half_rn(x - __half2float(h));
}
__device__ __forceinline__ uint32_t packh(__half a, __half b) {
    __half2 t = __halves2half2(a, b);
    return *(uint32_t*)&t;
}
__device__ __forceinline__ uint32_t packround(float x, float y) {
    return packh(__float2half_rn(x), __float2half_rn(y));
}
__device__ __forceinline__ void packsplit(float x, float y,
                                          uint32_t& hw, uint32_t& lw) {
    __half hx, lx, hy, ly;
    split2(x, hx, lx);
    split2(y, hy, ly);
    hw = packh(hx, hy);
    lw = packh(lx, ly);
}

__device__ __forceinline__ uint2 mask2(const void* m, size_t i, int kind) {
    if (kind == 0) {
        const unsigned char* p = (const unsigned char*)m;
        return make_uint2(p[i], p[i + 1]);
    }
    return *(const uint2*)((const unsigned int*)m + i);
}

// ---------------------------------------------------------------------------
__global__ void round_kernel(const float* __restrict__ X,
                             __half* __restrict__ H, int n) {
    int i = blockIdx.x * 256 + threadIdx.x;
    if (i < n) H[i] = __float2half_rn(X[i]);
}

// W[K,N] fp32 -> Th [N,K] fp16
__global__ void transpose_h_kernel(const float* __restrict__ W,
                                   __half* __restrict__ Th, int K, int N) {
    __shared__ float t[32][33];
    int n0 = blockIdx.x * 32, k0 = blockIdx.y * 32;
    int tx = threadIdx.x, ty = threadIdx.y;
#pragma unroll
    for (int j = 0; j < 4; ++j)
        t[ty + j * 8][tx] = W[(size_t)(k0 + ty + j * 8) * N + n0 + tx];
    __syncthreads();
#pragma unroll
    for (int j = 0; j < 4; ++j)
        Th[(size_t)(n0 + ty + j * 8) * K + k0 + tx] =
            __float2half_rn(t[tx][ty + j * 8]);
}

// presentV fp32 [BH][S][64] -> g_vth fp16 [BH][64][S]
__global__ void vtrans_kernel(const float* __restrict__ V) {
    __shared__ float t[32][33];
    int d0 = blockIdx.x * 32, s0 = blockIdx.y * 32, bh = blockIdx.z;
    int tx = threadIdx.x, ty = threadIdx.y;
#pragma unroll
    for (int j = 0; j < 4; ++j)
        t[ty + j * 8][tx] =
            V[(size_t)bh * (kS * kHD) + (size_t)(s0 + ty + j * 8) * kHD + d0 + tx];
    __syncthreads();
#pragma unroll
    for (int j = 0; j < 4; ++j)
        g_vth[((size_t)bh * kHD + d0 + ty + j * 8) * kS + s0 + tx] =
            __float2half_rn(t[tx][ty + j * 8]);
}

__global__ void detect_mask_kind_kernel(const unsigned int* __restrict__ m) {
    __shared__ int any_gt1, any_not_f32;
    if (threadIdx.x == 0) { any_gt1 = 0; any_not_f32 = 0; }
    __syncthreads();
    int gt1 = 0, nf32 = 0;
    for (int i = threadIdx.x; i < 16384; i += 256) {
        unsigned int w = m[i];
        if (w > 1u) gt1 = 1;
        if (w != 0u && w != 0x3F800000u) nf32 = 1;
    }
    if (gt1)  atomicOr(&any_gt1, 1);
    if (nf32) atomicOr(&any_not_f32, 1);
    __syncthreads();
    if (threadIdx.x == 0)
        g_mask_kind = (!any_gt1) ? 1 : ((!any_not_f32) ? 2 : 0);
}

// ---------------------------------------------------------------------------
// HMMA GEMM, fp16 1-product: C = Ah @ Bh^T + bias.
// mode 0: row-major C. mode 1: QKV scatter (q/k hi-lo split for QK^T stage).
// ---------------------------------------------------------------------------
__global__ __launch_bounds__(256, 2) void mma_gemm_kernel(
    const __half* __restrict__ Ah, const __half* __restrict__ Bh,
    const float* __restrict__ bias, float* __restrict__ C,
    int M, int N, int K, int mode,
    float* __restrict__ kout, float* __restrict__ vout)
{
    __shared__ __half sAh[128 * kSTR], sBh[128 * kSTR];

    const int tid = threadIdx.x;
    const int lane = tid & 31;
    const int wid = tid >> 5;
    const int wm = (wid & 3) * 32;
    const int wn = (wid >> 2) * 64;
    const int m0 = blockIdx.y * 128;
    const int n0 = blockIdx.x * 128;
    const int gID = lane >> 2;
    const int tig2 = (lane & 3) * 2;

    float acc[2][8][4] = {};

    for (int c = 0; c < K / 32; ++c) {
#pragma unroll
        for (int j = 0; j < 2; ++j) {
            int unit = tid + j * 256;
            int rr = unit >> 2;
            int uu = unit & 3;
            size_t ga = (size_t)(m0 + rr) * K + c * 32 + uu * 8;
            size_t gb = (size_t)(n0 + rr) * K + c * 32 + uu * 8;
            int so = rr * kSTR + uu * 8;
            *(float4*)&sAh[so] = *(const float4*)&Ah[ga];
            *(float4*)&sBh[so] = *(const float4*)&Bh[gb];
        }
        __syncthreads();

#pragma unroll
        for (int ks = 0; ks < 2; ++ks) {
            const int k0 = ks * 16;
            uint32_t ah[2][4];
#pragma unroll
            for (int mi = 0; mi < 2; ++mi) {
                int base = (wm + mi * 16 + gID) * kSTR + k0 + tig2;
                ah[mi][0] = *(const uint32_t*)&sAh[base];
                ah[mi][1] = *(const uint32_t*)&sAh[base + 8 * kSTR];
                ah[mi][2] = *(const uint32_t*)&sAh[base + 8];
                ah[mi][3] = *(const uint32_t*)&sAh[base + 8 * kSTR + 8];
            }
#pragma unroll
            for (int nt = 0; nt < 8; ++nt) {
                int nb = (wn + nt * 8 + gID) * kSTR + k0 + tig2;
                uint32_t bh0 = *(const uint32_t*)&sBh[nb];
                uint32_t bh1 = *(const uint32_t*)&sBh[nb + 8];
                mma16816(acc[0][nt], ah[0], bh0, bh1);
                mma16816(acc[1][nt], ah[1], bh0, bh1);
            }
        }
        __syncthreads();
    }

#pragma unroll
    for (int mi = 0; mi < 2; ++mi) {
#pragma unroll
        for (int nt = 0; nt < 8; ++nt) {
            int m = m0 + wm + mi * 16 + gID;
            int n = n0 + wn + nt * 8 + tig2;
            float b0 = bias[n], b1 = bias[n + 1];
            float v0 = acc[mi][nt][0] + b0;
            float v1 = acc[mi][nt][1] + b1;
            float v2 = acc[mi][nt][2] + b0;
            float v3 = acc[mi][nt][3] + b1;
            if (mode == 0) {
                *(float2*)&C[(size_t)m * N + n] = make_float2(v0, v1);
                *(float2*)&C[(size_t)(m + 8) * N + n] = make_float2(v2, v3);
            } else {
                int sec = n >> 10;
                int e = n & 1023;
                int h = e >> 6;
                int d = e & 63;
#pragma unroll
                for (int rr = 0; rr < 2; ++rr) {
                    int mm = m + rr * 8;
                    int bb = mm >> 10;
                    int s = mm & 1023;
                    size_t idx = (((size_t)(bb * kH + h)) * kS + s) * kHD + d;
                    float p0 = rr ? v2 : v0, p1 = rr ? v3 : v1;
                    if (sec == 0) {
                        uint32_t hw, lw;
                        packsplit(p0, p1, hw, lw);
                        *(uint32_t*)&g_qh[idx] = hw;
                        *(uint32_t*)&g_ql[idx] = lw;
                    } else if (sec == 1) {
                        *(float2*)&kout[idx] = make_float2(p0, p1);
                        uint32_t hw, lw;
                        packsplit(p0, p1, hw, lw);
                        *(uint32_t*)&g_kh[idx] = hw;
                        *(uint32_t*)&g_kl[idx] = lw;
                    } else {
                        *(float2*)&vout[idx] = make_float2(p0, p1);
                    }
                }
            }
        }
    }
}

// ---------------------------------------------------------------------------
// OV kernel: g_a = (mask? ov : 0) @ V ; 1-product fp16.
// ---------------------------------------------------------------------------
__global__ __launch_bounds__(256, 2) void ov_kernel(
    const float* __restrict__ ov, const void* __restrict__ mask,
    float* __restrict__ out)
{
    __shared__ __half sVh[64 * 136];
    const int tid = threadIdx.x, lane = tid & 31, wid = tid >> 5;
    const int gID = lane >> 2, tig2 = (lane & 3) * 2;
    const int b = blockIdx.z, h = blockIdx.y, q0 = blockIdx.x * 128;
    const int wq = wid * 16;
    const int mkind = g_mask_kind;
    const size_t bhT = (size_t)(b * kH + h) * kHD;
    const int qr0 = q0 + wq + gID, qr1 = qr0 + 8;
    const size_t mr0 = ((size_t)h * kS + qr0) * kS;
    const size_t mr1 = ((size_t)h * kS + qr1) * kS;

    float o[8][4] = {};

    for (int kc = 0; kc < 8; ++kc) {
#pragma unroll
        for (int it = 0; it < 2; ++it) {
            int unit = tid + it * 256;
            int row = unit >> 3, u = (unit & 7) * 16;
            *(float4*)&sVh[row * 136 + u] =
                *(const float4*)&g_vth[(bhT + row) * kS + kc * 128 + u];
            *(float4*)&sVh[row * 136 + u + 8] =
                *(const float4*)&g_vth[(bhT + row) * kS + kc * 128 + u + 8];
        }
        __syncthreads();

#pragma unroll
        for (int ks = 0; ks < 8; ++ks) {
            size_t kg = (size_t)kc * 128 + ks * 16 + tig2;
            uint2 m00 = mask2(mask, mr0 + kg, mkind);
            uint2 m02 = mask2(mask, mr0 + kg + 8, mkind);
            uint2 m10 = mask2(mask, mr1 + kg, mkind);
            uint2 m12 = mask2(mask, mr1 + kg + 8, mkind);
            float2 v00 = *(const float2*)&ov[mr0 + kg];
            float2 v02 = *(const float2*)&ov[mr0 + kg + 8];
            float2 v10 = *(const float2*)&ov[mr1 + kg];
            float2 v12 = *(const float2*)&ov[mr1 + kg + 8];
            uint32_t ah[4];
            ah[0] = packround(m00.x ? v00.x : 0.f, m00.y ? v00.y : 0.f);
            ah[1] = packround(m10.x ? v10.x : 0.f, m10.y ? v10.y : 0.f);
            ah[2] = packround(m02.x ? v02.x : 0.f, m02.y ? v02.y : 0.f);
            ah[3] = packround(m12.x ? v12.x : 0.f, m12.y ? v12.y : 0.f);
#pragma unroll
            for (int dn = 0; dn < 8; ++dn) {
                int vb = (dn * 8 + gID) * 136 + ks * 16 + tig2;
                uint32_t b0 = *(const uint32_t*)&sVh[vb];
                uint32_t b1 = *(const uint32_t*)&sVh[vb + 8];
                mma16816(o[dn], ah, b0, b1);
            }
        }
        __syncthreads();
    }

#pragma unroll
    for (int dn = 0; dn < 8; ++dn) {
        int d = h * kHD + dn * 8 + tig2;
        *(float2*)&out[(size_t)(b * kS + qr0) * kD + d] =
            make_float2(o[dn][0], o[dn][1]);
        *(float2*)&out[(size_t)(b * kS + qr1) * kD + d] =
            make_float2(o[dn][2], o[dn][3]);
    }
}

// ---------------------------------------------------------------------------
// Flash kernel: O1 = (causal-exp, masked-zeroed) E @ V; g_a += O1 / Z.
// QK^T: 3-product fp16. E@V: 1-product. Causal chunk skipping.
// ---------------------------------------------------------------------------
__global__ __launch_bounds__(256, 2) void flash_kernel(
    const void* __restrict__ mask, float* __restrict__ aio)
{
    extern __shared__ __half fsm[];
    __half* sKh = fsm + F_KH;   // [128][72]
    __half* sKl = fsm + F_KL;
    __half* sVh = fsm + F_VH;   // [64][136]

    const int tid = threadIdx.x, lane = tid & 31, wid = tid >> 5;
    const int gID = lane >> 2, tig2 = (lane & 3) * 2;
    const int b = blockIdx.z, h = blockIdx.y;
    const int qt = blockIdx.x;
    const int q0 = qt * 128;
    const int wq = wid * 16;
    const int mkind = g_mask_kind;
    const size_t bh = (size_t)(b * kH + h) * kS * kHD;
    const size_t bhT = (size_t)(b * kH + h) * kHD;

    // stage Q tile, load register fragments
#pragma unroll
    for (int it = 0; it < 4; ++it) {
        int unit = tid + it * 256;
        int row = unit >> 3, u = (unit & 7) * 8;
        *(float4*)&sKh[row * 72 + u] =
            *(const float4*)&g_qh[bh + (size_t)(q0 + row) * kHD + u];
        *(float4*)&sKl[row * 72 + u] =
            *(const float4*)&g_ql[bh + (size_t)(q0 + row) * kHD + u];
    }
    __syncthreads();
    uint32_t qfh[4][4], qfl[4][4];
#pragma unroll
    for (int ks = 0; ks < 4; ++ks) {
        int base = (wq + gID) * 72 + ks * 16 + tig2;
        qfh[ks][0] = *(const uint32_t*)&sKh[base];
        qfh[ks][1] = *(const uint32_t*)&sKh[base + 8 * 72];
        qfh[ks][2] = *(const uint32_t*)&sKh[base + 8];
        qfh[ks][3] = *(const uint32_t*)&sKh[base + 8 * 72 + 8];
        qfl[ks][0] = *(const uint32_t*)&sKl[base];
        qfl[ks][1] = *(const uint32_t*)&sKl[base + 8 * 72];
        qfl[ks][2] = *(const uint32_t*)&sKl[base + 8];
        qfl[ks][3] = *(const uint32_t*)&sKl[base + 8 * 72 + 8];
    }
    __syncthreads();

    float o[8][4] = {};
    float Z0 = 0.f, Z1 = 0.f;
    const int qr0 = q0 + wq + gID, qr1 = qr0 + 8;
    const size_t mr0 = ((size_t)h * kS + qr0) * kS;
    const size_t mr1 = ((size_t)h * kS + qr1) * kS;

    for (int kc = 0; kc <= qt; ++kc) {
#pragma unroll
        for (int it = 0; it < 4; ++it) {
            int unit = tid + it * 256;
            int row = unit >> 3, u = (unit & 7) * 8;
            *(float4*)&sKh[row * 72 + u] =
                *(const float4*)&g_kh[bh + (size_t)(kc * 128 + row) * kHD + u];
            *(float4*)&sKl[row * 72 + u] =
                *(const float4*)&g_kl[bh + (size_t)(kc * 128 + row) * kHD + u];
        }
#pragma unroll
        for (int it = 0; it < 2; ++it) {
            int unit = tid + it * 256;
            int row = unit >> 3, u = (unit & 7) * 16;
            *(float4*)&sVh[row * 136 + u] =
                *(const float4*)&g_vth[(bhT + row) * kS + kc * 128 + u];
            *(float4*)&sVh[row * 136 + u + 8] =
                *(const float4*)&g_vth[(bhT + row) * kS + kc * 128 + u + 8];
        }
        __syncthreads();

        for (int qq = 0; qq < 4; ++qq) {
            float sa[4][4] = {};
#pragma unroll
            for (int ks = 0; ks < 4; ++ks)
#pragma unroll
                for (int nt = 0; nt < 4; ++nt) {
                    int kb = (qq * 32 + nt * 8 + gID) * 72 + ks * 16 + tig2;
                    uint32_t b0 = *(const uint32_t*)&sKh[kb];
                    uint32_t b1 = *(const uint32_t*)&sKh[kb + 8];
                    mma16816(sa[nt], qfh[ks], b0, b1);
                    mma16816(sa[nt], qfl[ks], b0, b1);
                    uint32_t c0 = *(const uint32_t*)&sKl[kb];
                    uint32_t c1 = *(const uint32_t*)&sKl[kb + 8];
                    mma16816(sa[nt], qfh[ks], c0, c1);
                }

            uint32_t ehr0[4], ehr1[4];
#pragma unroll
            for (int nt = 0; nt < 4; ++nt) {
                int kg = kc * 128 + qq * 32 + nt * 8 + tig2;
                float e00 = (kg     <= qr0) ? __expf(sa[nt][0] * 0.125f) : 0.f;
                float e01 = (kg + 1 <= qr0) ? __expf(sa[nt][1] * 0.125f) : 0.f;
                float e10 = (kg     <= qr1) ? __expf(sa[nt][2] * 0.125f) : 0.f;
                float e11 = (kg + 1 <= qr1) ? __expf(sa[nt][3] * 0.125f) : 0.f;
                Z0 += e00 + e01;
                Z1 += e10 + e11;
                uint2 m0 = mask2(mask, mr0 + kg, mkind);
                uint2 m1 = mask2(mask, mr1 + kg, mkind);
                if (m0.x) e00 = 0.f;
                if (m0.y) e01 = 0.f;
                if (m1.x) e10 = 0.f;
                if (m1.y) e11 = 0.f;
                ehr0[nt] = packround(e00, e01);
                ehr1[nt] = packround(e10, e11);
            }
#pragma unroll
            for (int k2 = 0; k2 < 2; ++k2) {
                uint32_t ah[4] = {ehr0[2 * k2], ehr1[2 * k2],
                                  ehr0[2 * k2 + 1], ehr1[2 * k2 + 1]};
#pragma unroll
                for (int dn = 0; dn < 8; ++dn) {
                    int vb = (dn * 8 + gID) * 136 + qq * 32 + k2 * 16 + tig2;
                    uint32_t b0 = *(const uint32_t*)&sVh[vb];
                    uint32_t b1 = *(const uint32_t*)&sVh[vb + 8];
                    mma16816(o[dn], ah, b0, b1);
                }
            }
        }
        __syncthreads();
    }

    Z0 += __shfl_xor_sync(0xffffffffu, Z0, 1);
    Z0 += __shfl_xor_sync(0xffffffffu, Z0, 2);
    Z1 += __shfl_xor_sync(0xffffffffu, Z1, 1);
    Z1 += __shfl_xor_sync(0xffffffffu, Z1, 2);
    float i0 = 1.f / Z0, i1 = 1.f / Z1;

#pragma unroll
    for (int dn = 0; dn < 8; ++dn) {
        int d = h * kHD + dn * 8 + tig2;
        size_t r0 = (size_t)(b * kS + qr0) * kD + d;
        size_t r1 = (size_t)(b * kS + qr1) * kD + d;
        float2 p0 = *(float2*)&aio[r0];
        float2 p1 = *(float2*)&aio[r1];
        *(float2*)&aio[r0] =
            make_float2(p0.x + o[dn][0] * i0, p0.y + o[dn][1] * i0);
        *(float2*)&aio[r1] =
            make_float2(p1.x + o[dn][2] * i1, p1.y + o[dn][3] * i1);
    }
}

// ---------------------------------------------------------------------------
extern "C" void kernel_launch(void* const* d_in, const int* in_sizes, int n_in,
                              void* d_out, int out_size)
{
    const float* x       = (const float*)d_in[0];
    const float* w_attn  = (const float*)d_in[1];
    const float* b_attn  = (const float*)d_in[2];
    const float* w_proj  = (const float*)d_in[3];
    const float* b_proj  = (const float*)d_in[4];
    const float* ov      = (const float*)d_in[5];
    const void*  msk     = (const void*)d_in[6];

    float* out = (float*)d_out;
    float* presentK = out + (size_t)kM * kD;
    float* presentV = presentK + (size_t)kB * kH * kS * kHD;

    float* aptr = nullptr;
    __half *xh, *ah, *wth, *pth;
    cudaGetSymbolAddress((void**)&aptr, g_a);
    cudaGetSymbolAddress((void**)&xh, g_xh);
    cudaGetSymbolAddress((void**)&ah, g_ah);
    cudaGetSymbolAddress((void**)&wth, g_wth);
    cudaGetSymbolAddress((void**)&pth, g_pth);

    cudaFuncSetAttribute(flash_kernel,
                         cudaFuncAttributeMaxDynamicSharedMemorySize,
                         FLASH_SMEM_BYTES);

    // 0) mask classification + operand prep
    detect_mask_kind_kernel<<<1, 256>>>((const unsigned int*)msk);
    round_kernel<<<kM * kD / 256, 256>>>(x, xh, kM * kD);
    transpose_h_kernel<<<dim3(3 * kD / 32, kD / 32), dim3(32, 8)>>>(
        w_attn, wth, kD, 3 * kD);
    transpose_h_kernel<<<dim3(kD / 32, kD / 32), dim3(32, 8)>>>(
        w_proj, pth, kD, kD);

    // 1) QKV GEMM -> present fp32 + q/k fp16 hi/lo
    mma_gemm_kernel<<<dim3(3 * kD / 128, kM / 128), 256>>>(
        xh, wth, b_attn, nullptr, kM, 3 * kD, kD, 1, presentK, presentV);

    // 2) V transpose -> g_vth
    vtrans_kernel<<<dim3(kHD / 32, kS / 32, kB * kH), dim3(32, 8)>>>(presentV);

    // 3) override term -> g_a (full overwrite)
    ov_kernel<<<dim3(kS / 128, kH, kB), 256>>>(ov, msk, aptr);

    // 4) flash attention adds softmax term -> g_a
    flash_kernel<<<dim3(kS / 128, kH, kB), 256, FLASH_SMEM_BYTES>>>(msk, aptr);

    // 5) round g_a, output projection
    round_kernel<<<kM * kD / 256, 256>>>(aptr, ah, kM * kD);
    mma_gemm_kernel<<<dim3(kD / 128, kM / 128), 256>>>(
        ah, pth, b_proj, out, kM, kD, kD, 0, nullptr, nullptr);
}

// round 10
// speedup vs baseline: 3.1612x; 1.0817x over previous
#include <cuda_runtime.h>
#include <cuda_fp16.h>
#include <cstdint>

// ---------------------------------------------------------------------------
// AttentionOverride, round 10: R9 + batch-shared ov_kernel.
// ov term = (mask?ov:0)[h] @ Vcat[h]  (one GEMM per head; mask/ov read once,
// not once per batch). fp16 1-product everywhere except flash QK^T (3-prod).
// Output layout: [ a (4M floats) | presentK (4M) | presentV (4M) ]
// ---------------------------------------------------------------------------

namespace {
constexpr int kB  = 4;
constexpr int kS  = 1024;
constexpr int kD  = 1024;
constexpr int kH  = 16;
constexpr int kHD = 64;
constexpr int kM  = kB * kS;  // 4096

constexpr int kSTR = 40;  // GEMM smem stride (half)

// flash smem (half elems): K[128][72] hi/lo, Vh[64][136]
constexpr int F_KH = 0;
constexpr int F_KL = 9216;
constexpr int F_VH = 18432;
constexpr int FLASH_SMEM_BYTES = (18432 + 8704) * 2;  // 54272

constexpr int OV_VT = 8704;                 // one V tile: 64*136 halves
constexpr int OV_SMEM_BYTES = 4 * OV_VT * 2;  // 69632
}  // namespace

// scratch (device globals; no allocation allowed)
__device__ float g_a[(size_t)kM * kD];
__device__ int   g_mask_kind;
__device__ __half g_qh[(size_t)kM * kD], g_ql[(size_t)kM * kD];
__device__ __half g_kh[(size_t)kM * kD], g_kl[(size_t)kM * kD];
__device__ __half g_vth[(size_t)kM * kD];                    // [BH][64][S]
__device__ __half g_xh[(size_t)kM * kD];                     // x rounded
__device__ __half g_ah[(size_t)kM * kD];                     // g_a rounded
__device__ __half g_wth[(size_t)3 * kD * kD];                // w_attn^T
__device__ __half g_pth[(size_t)kD * kD];                    // w_proj^T

// ---------------------------------------------------------------------------
__device__ __forceinline__ void mma16816(float* c, const uint32_t* a,
                                         uint32_t b0, uint32_t b1) {
    asm volatile(
        "mma.sync.aligned.m16n8k16.row.col.f32.f16.f16.f32 "
        "{%0,%1,%2,%3}, {%4,%5,%6,%7}, {%8,%9}, {%0,%1,%2,%3};"
        : "+f"(c[0]), "+f"(c[1]), "+f"(c[2]), "+f"(c[3])
        : "r"(a[0]), "r"(a[1]), "r"(a[2]), "r"(a[3]), "r"(b0), "r"(b1));
}

__device__ __forceinline__ void split2(float x, __half& h, __half& l) {
    h = __float2half_rn(x);
    l = __float2half_rn(x - __half2float(h));
}
__device__ __forceinline__ uint32_t packh(__half a, __half b) {
    __half2 t = __halves2half2(a, b);
    return *(uint32_t*)&t;
}
__device__ __forceinline__ uint32_t packround(float x, float y) {
    return packh(__float2half_rn(x), __float2half_rn(y));
}
__device__ __forceinline__ void packsplit(float x, float y,
                                          uint32_t& hw, uint32_t& lw) {
    __half hx, lx, hy, ly;
    split2(x, hx, lx);
    split2(y, hy, ly);
    hw = packh(hx, hy);
    lw = packh(lx, ly);
}

__device__ __forceinline__ uint2 mask2(const void* m, size_t i, int kind) {
    if (kind == 0) {
        const unsigned char* p = (const unsigned char*)m;
        return make_uint2(p[i], p[i + 1]);
    }
    return *(const uint2*)((const unsigned int*)m + i);
}

// ---------------------------------------------------------------------------
__global__ void round_kernel(const float* __restrict__ X,
                             __half* __restrict__ H, int n) {
    int i = blockIdx.x * 256 + threadIdx.x;
    if (i < n) H[i] = __float2half_rn(X[i]);
}

// W[K,N] fp32 -> Th [N,K] fp16
__global__ void transpose_h_kernel(const float* __restrict__ W,
                                   __half* __restrict__ Th, int K, int N) {
    __shared__ float t[32][33];
    int n0 = blockIdx.x * 32, k0 = blockIdx.y * 32;
    int tx = threadIdx.x, ty = threadIdx.y;
#pragma unroll
    for (int j = 0; j < 4; ++j)
        t[ty + j * 8][tx] = W[(size_t)(k0 + ty + j * 8) * N + n0 + tx];
    __syncthreads();
#pragma unroll
    for (int j = 0; j < 4; ++j)
        Th[(size_t)(n0 + ty + j * 8) * K + k0 + tx] =
            __float2half_rn(t[tx][ty + j * 8]);
}

// presentV fp32 [BH][S][64] -> g_vth fp16 [BH][64][S]
__global__ void vtrans_kernel(const float* __restrict__ V) {
    __shared__ float t[32][33];
    int d0 = blockIdx.x * 32, s0 = blockIdx.y * 32, bh = blockIdx.z;
    int tx = threadIdx.x, ty = threadIdx.y;
#pragma unroll
    for (int j = 0; j < 4; ++j)
        t[ty + j * 8][tx] =
            V[(size_t)bh * (kS * kHD) + (size_t)(s0 + ty + j * 8) * kHD + d0 + tx];
    __syncthreads();
#pragma unroll
    for (int j = 0; j < 4; ++j)
        g_vth[((size_t)bh * kHD + d0 + ty + j * 8) * kS + s0 + tx] =
            __float2half_rn(t[tx][ty + j * 8]);
}

__global__ void detect_mask_kind_kernel(const unsigned int* __restrict__ m) {
    __shared__ int any_gt1, any_not_f32;
    if (threadIdx.x == 0) { any_gt1 = 0; any_not_f32 = 0; }
    __syncthreads();
    int gt1 = 0, nf32 = 0;
    for (int i = threadIdx.x; i < 16384; i += 256) {
        unsigned int w = m[i];
        if (w > 1u) gt1 = 1;
        if (w != 0u && w != 0x3F800000u) nf32 = 1;
    }
    if (gt1)  atomicOr(&any_gt1, 1);
    if (nf32) atomicOr(&any_not_f32, 1);
    __syncthreads();
    if (threadIdx.x == 0)
        g_mask_kind = (!any_gt1) ? 1 : ((!any_not_f32) ? 2 : 0);
}

// ---------------------------------------------------------------------------
// HMMA GEMM, fp16 1-product: C = Ah @ Bh^T + bias.
// mode 0: row-major C. mode 1: QKV scatter (q/k hi-lo split for QK^T stage).
// ---------------------------------------------------------------------------
__global__ __launch_bounds__(256, 2) void mma_gemm_kernel(
    const __half* __restrict__ Ah, const __half* __restrict__ Bh,
    const float* __restrict__ bias, float* __restrict__ C,
    int M, int N, int K, int mode,
    float* __restrict__ kout, float* __restrict__ vout)
{
    __shared__ __half sAh[128 * kSTR], sBh[128 * kSTR];

    const int tid = threadIdx.x;
    const int lane = tid & 31;
    const int wid = tid >> 5;
    const int wm = (wid & 3) * 32;
    const int wn = (wid >> 2) * 64;
    const int m0 = blockIdx.y * 128;
    const int n0 = blockIdx.x * 128;
    const int gID = lane >> 2;
    const int tig2 = (lane & 3) * 2;

    float acc[2][8][4] = {};

    for (int c = 0; c < K / 32; ++c) {
#pragma unroll
        for (int j = 0; j < 2; ++j) {
            int unit = tid + j * 256;
            int rr = unit >> 2;
            int uu = unit & 3;
            size_t ga = (size_t)(m0 + rr) * K + c * 32 + uu * 8;
            size_t gb = (size_t)(n0 + rr) * K + c * 32 + uu * 8;
            int so = rr * kSTR + uu * 8;
            *(float4*)&sAh[so] = *(const float4*)&Ah[ga];
            *(float4*)&sBh[so] = *(const float4*)&Bh[gb];
        }
        __syncthreads();

#pragma unroll
        for (int ks = 0; ks < 2; ++ks) {
            const int k0 = ks * 16;
            uint32_t ah[2][4];
#pragma unroll
            for (int mi = 0; mi < 2; ++mi) {
                int base = (wm + mi * 16 + gID) * kSTR + k0 + tig2;
                ah[mi][0] = *(const uint32_t*)&sAh[base];
                ah[mi][1] = *(const uint32_t*)&sAh[base + 8 * kSTR];
                ah[mi][2] = *(const uint32_t*)&sAh[base + 8];
                ah[mi][3] = *(const uint32_t*)&sAh[base + 8 * kSTR + 8];
            }
#pragma unroll
            for (int nt = 0; nt < 8; ++nt) {
                int nb = (wn + nt * 8 + gID) * kSTR + k0 + tig2;
                uint32_t bh0 = *(const uint32_t*)&sBh[nb];
                uint32_t bh1 = *(const uint32_t*)&sBh[nb + 8];
                mma16816(acc[0][nt], ah[0], bh0, bh1);
                mma16816(acc[1][nt], ah[1], bh0, bh1);
            }
        }
        __syncthreads();
    }

#pragma unroll
    for (int mi = 0; mi < 2; ++mi) {
#pragma unroll
        for (int nt = 0; nt < 8; ++nt) {
            int m = m0 + wm + mi * 16 + gID;
            int n = n0 + wn + nt * 8 + tig2;
            float b0 = bias[n], b1 = bias[n + 1];
            float v0 = acc[mi][nt][0] + b0;
            float v1 = acc[mi][nt][1] + b1;
            float v2 = acc[mi][nt][2] + b0;
            float v3 = acc[mi][nt][3] + b1;
            if (mode == 0) {
                *(float2*)&C[(size_t)m * N + n] = make_float2(v0, v1);
                *(float2*)&C[(size_t)(m + 8) * N + n] = make_float2(v2, v3);
            } else {
                int sec = n >> 10;
                int e = n & 1023;
                int h = e >> 6;
                int d = e & 63;
#pragma unroll
                for (int rr = 0; rr < 2; ++rr) {
                    int mm = m + rr * 8;
                    int bb = mm >> 10;
                    int s = mm & 1023;
                    size_t idx = (((size_t)(bb * kH + h)) * kS + s) * kHD + d;
                    float p0 = rr ? v2 : v0, p1 = rr ? v3 : v1;
                    if (sec == 0) {
                        uint32_t hw, lw;
                        packsplit(p0, p1, hw, lw);
                        *(uint32_t*)&g_qh[idx] = hw;
                        *(uint32_t*)&g_ql[idx] = lw;
                    } else if (sec == 1) {
                        *(float2*)&kout[idx] = make_float2(p0, p1);
                        uint32_t hw, lw;
                        packsplit(p0, p1, hw, lw);
                        *(uint32_t*)&g_kh[idx] = hw;
                        *(uint32_t*)&g_kl[idx] = lw;
                    } else {
                        *(float2*)&vout[idx] = make_float2(p0, p1);
                    }
                }
            }
        }
    }
}

// ---------------------------------------------------------------------------
// OV kernel v2 (batch-shared): per (h, 64 q-rows) CTA computes, for ALL 4
// batches, o[b] = (mask?ov:0)[h,q,:] @ V[b,h,:,:]. mask/ov read ONCE.
// 8 warps = 4 q-subtiles x 2 d-halves; accum o[4][4][4] per thread.
// ---------------------------------------------------------------------------
__global__ __launch_bounds__(256, 2) void ov_kernel(
    const float* __restrict__ ov, const void* __restrict__ mask,
    float* __restrict__ out)
{
    extern __shared__ __half sV[];  // 4 batch tiles, each [64][136]
    const int tid = threadIdx.x, lane = tid & 31, wid = tid >> 5;
    const int gID = lane >> 2, tig2 = (lane & 3) * 2;
    const int h = blockIdx.y, q0 = blockIdx.x * 64;
    const int qsub = wid & 3;        // 16-q-row subtile
    const int dhalf = wid >> 2;      // 0: d 0..31, 1: d 32..63
    const int mkind = g_mask_kind;
    const int qr0 = q0 + qsub * 16 + gID, qr1 = qr0 + 8;
    const size_t mr0 = ((size_t)h * kS + qr0) * kS;
    const size_t mr1 = ((size_t)h * kS + qr1) * kS;

    float o[4][4][4] = {};

    for (int kc = 0; kc < 8; ++kc) {
        // stage 4 batch V tiles: [64 d][128 k] each
#pragma unroll
        for (int bb = 0; bb < 4; ++bb) {
            const size_t bhT = (size_t)(bb * kH + h) * kHD;
#pragma unroll
            for (int it = 0; it < 2; ++it) {
                int unit = tid + it * 256;
                int row = unit >> 3, u = (unit & 7) * 16;
                *(float4*)&sV[bb * OV_VT + row * 136 + u] =
                    *(const float4*)&g_vth[(bhT + row) * kS + kc * 128 + u];
                *(float4*)&sV[bb * OV_VT + row * 136 + u + 8] =
                    *(const float4*)&g_vth[(bhT + row) * kS + kc * 128 + u + 8];
            }
        }
        __syncthreads();

#pragma unroll
        for (int ks = 0; ks < 8; ++ks) {
            size_t kg = (size_t)kc * 128 + ks * 16 + tig2;
            uint2 m00 = mask2(mask, mr0 + kg, mkind);
            uint2 m02 = mask2(mask, mr0 + kg + 8, mkind);
            uint2 m10 = mask2(mask, mr1 + kg, mkind);
            uint2 m12 = mask2(mask, mr1 + kg + 8, mkind);
            float2 v00 = *(const float2*)&ov[mr0 + kg];
            float2 v02 = *(const float2*)&ov[mr0 + kg + 8];
            float2 v10 = *(const float2*)&ov[mr1 + kg];
            float2 v12 = *(const float2*)&ov[mr1 + kg + 8];
            uint32_t ah[4];
            ah[0] = packround(m00.x ? v00.x : 0.f, m00.y ? v00.y : 0.f);
            ah[1] = packround(m10.x ? v10.x : 0.f, m10.y ? v10.y : 0.f);
            ah[2] = packround(m02.x ? v02.x : 0.f, m02.y ? v02.y : 0.f);
            ah[3] = packround(m12.x ? v12.x : 0.f, m12.y ? v12.y : 0.f);
#pragma unroll
            for (int bb = 0; bb < 4; ++bb)
#pragma unroll
                for (int dn = 0; dn < 4; ++dn) {
                    int vb = bb * OV_VT +
                             (dhalf * 32 + dn * 8 + gID) * 136 + ks * 16 + tig2;
                    uint32_t b0 = *(const uint32_t*)&sV[vb];
                    uint32_t b1 = *(const uint32_t*)&sV[vb + 8];
                    mma16816(o[bb][dn], ah, b0, b1);
                }
        }
        __syncthreads();
    }

#pragma unroll
    for (int bb = 0; bb < 4; ++bb)
#pragma unroll
        for (int dn = 0; dn < 4; ++dn) {
            int d = h * kHD + dhalf * 32 + dn * 8 + tig2;
            *(float2*)&out[(size_t)(bb * kS + qr0) * kD + d] =
                make_float2(o[bb][dn][0], o[bb][dn][1]);
            *(float2*)&out[(size_t)(bb * kS + qr1) * kD + d] =
                make_float2(o[bb][dn][2], o[bb][dn][3]);
        }
}

// ---------------------------------------------------------------------------
// Flash kernel: O1 = (causal-exp, masked-zeroed) E @ V; g_a += O1 / Z.
// QK^T: 3-product fp16. E@V: 1-product. Causal chunk skipping.
// ---------------------------------------------------------------------------
__global__ __launch_bounds__(256, 2) void flash_kernel(
    const void* __restrict__ mask, float* __restrict__ aio)
{
    extern __shared__ __half fsm[];
    __half* sKh = fsm + F_KH;   // [128][72]
    __half* sKl = fsm + F_KL;
    __half* sVh = fsm + F_VH;   // [64][136]

    const int tid = threadIdx.x, lane = tid & 31, wid = tid >> 5;
    const int gID = lane >> 2, tig2 = (lane & 3) * 2;
    const int b = blockIdx.z, h = blockIdx.y;
    const int qt = blockIdx.x;
    const int q0 = qt * 128;
    const int wq = wid * 16;
    const int mkind = g_mask_kind;
    const size_t bh = (size_t)(b * kH + h) * kS * kHD;
    const size_t bhT = (size_t)(b * kH + h) * kHD;

    // stage Q tile, load register fragments
#pragma unroll
    for (int it = 0; it < 4; ++it) {
        int unit = tid + it * 256;
        int row = unit >> 3, u = (unit & 7) * 8;
        *(float4*)&sKh[row * 72 + u] =
            *(const float4*)&g_qh[bh + (size_t)(q0 + row) * kHD + u];
        *(float4*)&sKl[row * 72 + u] =
            *(const float4*)&g_ql[bh + (size_t)(q0 + row) * kHD + u];
    }
    __syncthreads();
    uint32_t qfh[4][4], qfl[4][4];
#pragma unroll
    for (int ks = 0; ks < 4; ++ks) {
        int base = (wq + gID) * 72 + ks * 16 + tig2;
        qfh[ks][0] = *(const uint32_t*)&sKh[base];
        qfh[ks][1] = *(const uint32_t*)&sKh[base + 8 * 72];
        qfh[ks][2] = *(const uint32_t*)&sKh[base + 8];
        qfh[ks][3] = *(const uint32_t*)&sKh[base + 8 * 72 + 8];
        qfl[ks][0] = *(const uint32_t*)&sKl[base];
        qfl[ks][1] = *(const uint32_t*)&sKl[base + 8 * 72];
        qfl[ks][2] = *(const uint32_t*)&sKl[base + 8];
        qfl[ks][3] = *(const uint32_t*)&sKl[base + 8 * 72 + 8];
    }
    __syncthreads();

    float o[8][4] = {};
    float Z0 = 0.f, Z1 = 0.f;
    const int qr0 = q0 + wq + gID, qr1 = qr0 + 8;
    const size_t mr0 = ((size_t)h * kS + qr0) * kS;
    const size_t mr1 = ((size_t)h * kS + qr1) * kS;

    for (int kc = 0; kc <= qt; ++kc) {
#pragma unroll
        for (int it = 0; it < 4; ++it) {
            int unit = tid + it * 256;
            int row = unit >> 3, u = (unit & 7) * 8;
            *(float4*)&sKh[row * 72 + u] =
                *(const float4*)&g_kh[bh + (size_t)(kc * 128 + row) * kHD + u];
            *(float4*)&sKl[row * 72 + u] =
                *(const float4*)&g_kl[bh + (size_t)(kc * 128 + row) * kHD + u];
        }
#pragma unroll
        for (int it = 0; it < 2; ++it) {
            int unit = tid + it * 256;
            int row = unit >> 3, u = (unit & 7) * 16;
            *(float4*)&sVh[row * 136 + u] =
                *(const float4*)&g_vth[(bhT + row) * kS + kc * 128 + u];
            *(float4*)&sVh[row * 136 + u + 8] =
                *(const float4*)&g_vth[(bhT + row) * kS + kc * 128 + u + 8];
        }
        __syncthreads();

        for (int qq = 0; qq < 4; ++qq) {
            float sa[4][4] = {};
#pragma unroll
            for (int ks = 0; ks < 4; ++ks)
#pragma unroll
                for (int nt = 0; nt < 4; ++nt) {
                    int kb = (qq * 32 + nt * 8 + gID) * 72 + ks * 16 + tig2;
                    uint32_t b0 = *(const uint32_t*)&sKh[kb];
                    uint32_t b1 = *(const uint32_t*)&sKh[kb + 8];
                    mma16816(sa[nt], qfh[ks], b0, b1);
                    mma16816(sa[nt], qfl[ks], b0, b1);
                    uint32_t c0 = *(const uint32_t*)&sKl[kb];
                    uint32_t c1 = *(const uint32_t*)&sKl[kb + 8];
                    mma16816(sa[nt], qfh[ks], c0, c1);
                }

            uint32_t ehr0[4], ehr1[4];
#pragma unroll
            for (int nt = 0; nt < 4; ++nt) {
                int kg = kc * 128 + qq * 32 + nt * 8 + tig2;
                float e00 = (kg     <= qr0) ? __expf(sa[nt][0] * 0.125f) : 0.f;
                float e01 = (kg + 1 <= qr0) ? __expf(sa[nt][1] * 0.125f) : 0.f;
                float e10 = (kg     <= qr1) ? __expf(sa[nt][2] * 0.125f) : 0.f;
                float e11 = (kg + 1 <= qr1) ? __expf(sa[nt][3] * 0.125f) : 0.f;
                Z0 += e00 + e01;
                Z1 += e10 + e11;
                uint2 m0 = mask2(mask, mr0 + kg, mkind);
                uint2 m1 = mask2(mask, mr1 + kg, mkind);
                if (m0.x) e00 = 0.f;
                if (m0.y) e01 = 0.f;
                if (m1.x) e10 = 0.f;
                if (m1.y) e11 = 0.f;
                ehr0[nt] = packround(e00, e01);
                ehr1[nt] = packround(e10, e11);
            }
#pragma unroll
            for (int k2 = 0; k2 < 2; ++k2) {
                uint32_t ah[4] = {ehr0[2 * k2], ehr1[2 * k2],
                                  ehr0[2 * k2 + 1], ehr1[2 * k2 + 1]};
#pragma unroll
                for (int dn = 0; dn < 8; ++dn) {
                    int vb = (dn * 8 + gID) * 136 + qq * 32 + k2 * 16 + tig2;
                    uint32_t b0 = *(const uint32_t*)&sVh[vb];
                    uint32_t b1 = *(const uint32_t*)&sVh[vb + 8];
                    mma16816(o[dn], ah, b0, b1);
                }
            }
        }
        __syncthreads();
    }

    Z0 += __shfl_xor_sync(0xffffffffu, Z0, 1);
    Z0 += __shfl_xor_sync(0xffffffffu, Z0, 2);
    Z1 += __shfl_xor_sync(0xffffffffu, Z1, 1);
    Z1 += __shfl_xor_sync(0xffffffffu, Z1, 2);
    float i0 = 1.f / Z0, i1 = 1.f / Z1;

#pragma unroll
    for (int dn = 0; dn < 8; ++dn) {
        int d = h * kHD + dn * 8 + tig2;
        size_t r0 = (size_t)(b * kS + qr0) * kD + d;
        size_t r1 = (size_t)(b * kS + qr1) * kD + d;
        float2 p0 = *(float2*)&aio[r0];
        float2 p1 = *(float2*)&aio[r1];
        *(float2*)&aio[r0] =
            make_float2(p0.x + o[dn][0] * i0, p0.y + o[dn][1] * i0);
        *(float2*)&aio[r1] =
            make_float2(p1.x + o[dn][2] * i1, p1.y + o[dn][3] * i1);
    }
}

// ---------------------------------------------------------------------------
extern "C" void kernel_launch(void* const* d_in, const int* in_sizes, int n_in,
                              void* d_out, int out_size)
{
    const float* x       = (const float*)d_in[0];
    const float* w_attn  = (const float*)d_in[1];
    const float* b_attn  = (const float*)d_in[2];
    const float* w_proj  = (const float*)d_in[3];
    const float* b_proj  = (const float*)d_in[4];
    const float* ov      = (const float*)d_in[5];
    const void*  msk     = (const void*)d_in[6];

    float* out = (float*)d_out;
    float* presentK = out + (size_t)kM * kD;
    float* presentV = presentK + (size_t)kB * kH * kS * kHD;

    float* aptr = nullptr;
    __half *xh, *ah, *wth, *pth;
    cudaGetSymbolAddress((void**)&aptr, g_a);
    cudaGetSymbolAddress((void**)&xh, g_xh);
    cudaGetSymbolAddress((void**)&ah, g_ah);
    cudaGetSymbolAddress((void**)&wth, g_wth);
    cudaGetSymbolAddress((void**)&pth, g_pth);

    cudaFuncSetAttribute(flash_kernel,
                         cudaFuncAttributeMaxDynamicSharedMemorySize,
                         FLASH_SMEM_BYTES);
    cudaFuncSetAttribute(ov_kernel,
                         cudaFuncAttributeMaxDynamicSharedMemorySize,
                         OV_SMEM_BYTES);

    // 0) mask classification + operand prep
    detect_mask_kind_kernel<<<1, 256>>>((const unsigned int*)msk);
    round_kernel<<<kM * kD / 256, 256>>>(x, xh, kM * kD);
    transpose_h_kernel<<<dim3(3 * kD / 32, kD / 32), dim3(32, 8)>>>(
        w_attn, wth, kD, 3 * kD);
    transpose_h_kernel<<<dim3(kD / 32, kD / 32), dim3(32, 8)>>>(
        w_proj, pth, kD, kD);

    // 1) QKV GEMM -> present fp32 + q/k fp16 hi/lo
    mma_gemm_kernel<<<dim3(3 * kD / 128, kM / 128), 256>>>(
        xh, wth, b_attn, nullptr, kM, 3 * kD, kD, 1, presentK, presentV);

    // 2) V transpose -> g_vth
    vtrans_kernel<<<dim3(kHD / 32, kS / 32, kB * kH), dim3(32, 8)>>>(presentV);

    // 3) override term -> g_a (batch-shared; full overwrite)
    ov_kernel<<<dim3(kS / 64, kH), 256, OV_SMEM_BYTES>>>(ov, msk, aptr);

    // 4) flash attention adds softmax term -> g_a
    flash_kernel<<<dim3(kS / 128, kH, kB), 256, FLASH_SMEM_BYTES>>>(msk, aptr);

    // 5) round g_a, output projection
    round_kernel<<<kM * kD / 256, 256>>>(aptr, ah, kM * kD);
    mma_gemm_kernel<<<dim3(kD / 128, kM / 128), 256>>>(
        ah, pth, b_proj, out, kM, kD, kD, 0, nullptr, nullptr);
}

// round 11
// speedup vs baseline: 3.3300x; 1.0534x over previous
#include <cuda_runtime.h>
#include <cuda_fp16.h>
#include <cstdint>

// ---------------------------------------------------------------------------
// AttentionOverride, round 11: R10 + cp.async pipelining.
//   mma_gemm: 2-deep double-buffered A/B tiles (cp.async.cg, wait_group 1)
//   flash:    V tile double-buffered (prefetch hidden behind S+EV MMAs)
// Math unchanged -> rel_err must remain 4.540033e-4.
// Output layout: [ a (4M floats) | presentK (4M) | presentV (4M) ]
// ---------------------------------------------------------------------------

namespace {
constexpr int kB  = 4;
constexpr int kS  = 1024;
constexpr int kD  = 1024;
constexpr int kH  = 16;
constexpr int kHD = 64;
constexpr int kM  = kB * kS;  // 4096

constexpr int kSTR = 40;       // GEMM smem stride (half)
constexpr int GT   = 128 * kSTR;  // one GEMM tile in halves (5120)

// flash smem (half elems): K[128][72] hi/lo, V double buffer [2][64][136]
constexpr int F_KH = 0;
constexpr int F_KL = 9216;
constexpr int F_VH = 18432;              // two buffers of 8704
constexpr int FLASH_SMEM_BYTES = (18432 + 2 * 8704) * 2;  // 71680

constexpr int OV_VT = 8704;
constexpr int OV_SMEM_BYTES = 4 * OV_VT * 2;  // 69632
}  // namespace

// scratch (device globals; no allocation allowed)
__device__ float g_a[(size_t)kM * kD];
__device__ int   g_mask_kind;
__device__ __half g_qh[(size_t)kM * kD], g_ql[(size_t)kM * kD];
__device__ __half g_kh[(size_t)kM * kD], g_kl[(size_t)kM * kD];
__device__ __half g_vth[(size_t)kM * kD];                    // [BH][64][S]
__device__ __half g_xh[(size_t)kM * kD];
__device__ __half g_ah[(size_t)kM * kD];
__device__ __half g_wth[(size_t)3 * kD * kD];
__device__ __half g_pth[(size_t)kD * kD];

// ---------------------------------------------------------------------------
__device__ __forceinline__ void mma16816(float* c, const uint32_t* a,
                                         uint32_t b0, uint32_t b1) {
    asm volatile(
        "mma.sync.aligned.m16n8k16.row.col.f32.f16.f16.f32 "
        "{%0,%1,%2,%3}, {%4,%5,%6,%7}, {%8,%9}, {%0,%1,%2,%3};"
        : "+f"(c[0]), "+f"(c[1]), "+f"(c[2]), "+f"(c[3])
        : "r"(a[0]), "r"(a[1]), "r"(a[2]), "r"(a[3]), "r"(b0), "r"(b1));
}

#define CP_ASYNC16(saddr, gptr)                                          \
    asm volatile("cp.async.cg.shared.global [%0], [%1], 16;"             \
                 :: "r"(saddr), "l"(gptr) : "memory")
#define CP_COMMIT() asm volatile("cp.async.commit_group;" ::: "memory")
#define CP_WAIT0()  asm volatile("cp.async.wait_group 0;" ::: "memory")
#define CP_WAIT1()  asm volatile("cp.async.wait_group 1;" ::: "memory")

__device__ __forceinline__ uint32_t smem_u32(const void* p) {
    return (uint32_t)__cvta_generic_to_shared(p);
}

__device__ __forceinline__ void split2(float x, __half& h, __half& l) {
    h = __float2half_rn(x);
    l = __float2half_rn(x - __half2float(h));
}
__device__ __forceinline__ uint32_t packh(__half a, __half b) {
    __half2 t = __halves2half2(a, b);
    return *(uint32_t*)&t;
}
__device__ __forceinline__ uint32_t packround(float x, float y) {
    return packh(__float2half_rn(x), __float2half_rn(y));
}
__device__ __forceinline__ void packsplit(float x, float y,
                                          uint32_t& hw, uint32_t& lw) {
    __half hx, lx, hy, ly;
    split2(x, hx, lx);
    split2(y, hy, ly);
    hw = packh(hx, hy);
    lw = packh(lx, ly);
}

__device__ __forceinline__ uint2 mask2(const void* m, size_t i, int kind) {
    if (kind == 0) {
        const unsigned char* p = (const unsigned char*)m;
        return make_uint2(p[i], p[i + 1]);
    }
    return *(const uint2*)((const unsigned int*)m + i);
}

// ---------------------------------------------------------------------------
__global__ void round_kernel(const float* __restrict__ X,
                             __half* __restrict__ H, int n) {
    int i = blockIdx.x * 256 + threadIdx.x;
    if (i < n) H[i] = __float2half_rn(X[i]);
}

__global__ void transpose_h_kernel(const float* __restrict__ W,
                                   __half* __restrict__ Th, int K, int N) {
    __shared__ float t[32][33];
    int n0 = blockIdx.x * 32, k0 = blockIdx.y * 32;
    int tx = threadIdx.x, ty = threadIdx.y;
#pragma unroll
    for (int j = 0; j < 4; ++j)
        t[ty + j * 8][tx] = W[(size_t)(k0 + ty + j * 8) * N + n0 + tx];
    __syncthreads();
#pragma unroll
    for (int j = 0; j < 4; ++j)
        Th[(size_t)(n0 + ty + j * 8) * K + k0 + tx] =
            __float2half_rn(t[tx][ty + j * 8]);
}

__global__ void vtrans_kernel(const float* __restrict__ V) {
    __shared__ float t[32][33];
    int d0 = blockIdx.x * 32, s0 = blockIdx.y * 32, bh = blockIdx.z;
    int tx = threadIdx.x, ty = threadIdx.y;
#pragma unroll
    for (int j = 0; j < 4; ++j)
        t[ty + j * 8][tx] =
            V[(size_t)bh * (kS * kHD) + (size_t)(s0 + ty + j * 8) * kHD + d0 + tx];
    __syncthreads();
#pragma unroll
    for (int j = 0; j < 4; ++j)
        g_vth[((size_t)bh * kHD + d0 + ty + j * 8) * kS + s0 + tx] =
            __float2half_rn(t[tx][ty + j * 8]);
}

__global__ void detect_mask_kind_kernel(const unsigned int* __restrict__ m) {
    __shared__ int any_gt1, any_not_f32;
    if (threadIdx.x == 0) { any_gt1 = 0; any_not_f32 = 0; }
    __syncthreads();
    int gt1 = 0, nf32 = 0;
    for (int i = threadIdx.x; i < 16384; i += 256) {
        unsigned int w = m[i];
        if (w > 1u) gt1 = 1;
        if (w != 0u && w != 0x3F800000u) nf32 = 1;
    }
    if (gt1)  atomicOr(&any_gt1, 1);
    if (nf32) atomicOr(&any_not_f32, 1);
    __syncthreads();
    if (threadIdx.x == 0)
        g_mask_kind = (!any_gt1) ? 1 : ((!any_not_f32) ? 2 : 0);
}

// ---------------------------------------------------------------------------
// HMMA GEMM, fp16 1-product, cp.async double-buffered.
// ---------------------------------------------------------------------------
__global__ __launch_bounds__(256, 2) void mma_gemm_kernel(
    const __half* __restrict__ Ah, const __half* __restrict__ Bh,
    const float* __restrict__ bias, float* __restrict__ C,
    int M, int N, int K, int mode,
    float* __restrict__ kout, float* __restrict__ vout)
{
    __shared__ __half sA[2 * GT], sB[2 * GT];

    const int tid = threadIdx.x;
    const int lane = tid & 31;
    const int wid = tid >> 5;
    const int wm = (wid & 3) * 32;
    const int wn = (wid >> 2) * 64;
    const int m0 = blockIdx.y * 128;
    const int n0 = blockIdx.x * 128;
    const int gID = lane >> 2;
    const int tig2 = (lane & 3) * 2;

    const uint32_t sbA = smem_u32(sA);
    const uint32_t sbB = smem_u32(sB);

    // per-thread staging coordinates (2 units of 16B for A, 2 for B)
    const int rr0 = tid >> 2;                 // rows for unit j=0
    const int uu0 = tid & 3;
    const int rr1 = (tid + 256) >> 2;
    const int uu1 = (tid + 256) & 3;

    auto stage = [&](int c, int buf) {
        size_t ka = (size_t)c * 32;
        uint32_t so0 = (uint32_t)(rr0 * 80 + uu0 * 16) + buf * (GT * 2);
        uint32_t so1 = (uint32_t)(rr1 * 80 + uu1 * 16) + buf * (GT * 2);
        CP_ASYNC16(sbA + so0, Ah + (size_t)(m0 + rr0) * K + ka + uu0 * 8);
        CP_ASYNC16(sbA + so1, Ah + (size_t)(m0 + rr1) * K + ka + uu1 * 8);
        CP_ASYNC16(sbB + so0, Bh + (size_t)(n0 + rr0) * K + ka + uu0 * 8);
        CP_ASYNC16(sbB + so1, Bh + (size_t)(n0 + rr1) * K + ka + uu1 * 8);
        CP_COMMIT();
    };

    float acc[2][8][4] = {};
    const int nchunks = K / 32;

    stage(0, 0);
    for (int c = 0; c < nchunks; ++c) {
        if (c + 1 < nchunks) {
            stage(c + 1, (c + 1) & 1);
            CP_WAIT1();
        } else {
            CP_WAIT0();
        }
        __syncthreads();

        const __half* tA = sA + (c & 1) * GT;
        const __half* tB = sB + (c & 1) * GT;
#pragma unroll
        for (int ks = 0; ks < 2; ++ks) {
            const int k0 = ks * 16;
            uint32_t ah[2][4];
#pragma unroll
            for (int mi = 0; mi < 2; ++mi) {
                int base = (wm + mi * 16 + gID) * kSTR + k0 + tig2;
                ah[mi][0] = *(const uint32_t*)&tA[base];
                ah[mi][1] = *(const uint32_t*)&tA[base + 8 * kSTR];
                ah[mi][2] = *(const uint32_t*)&tA[base + 8];
                ah[mi][3] = *(const uint32_t*)&tA[base + 8 * kSTR + 8];
            }
#pragma unroll
            for (int nt = 0; nt < 8; ++nt) {
                int nb = (wn + nt * 8 + gID) * kSTR + k0 + tig2;
                uint32_t bh0 = *(const uint32_t*)&tB[nb];
                uint32_t bh1 = *(const uint32_t*)&tB[nb + 8];
                mma16816(acc[0][nt], ah[0], bh0, bh1);
                mma16816(acc[1][nt], ah[1], bh0, bh1);
            }
        }
        __syncthreads();
    }

#pragma unroll
    for (int mi = 0; mi < 2; ++mi) {
#pragma unroll
        for (int nt = 0; nt < 8; ++nt) {
            int m = m0 + wm + mi * 16 + gID;
            int n = n0 + wn + nt * 8 + tig2;
            float b0 = bias[n], b1 = bias[n + 1];
            float v0 = acc[mi][nt][0] + b0;
            float v1 = acc[mi][nt][1] + b1;
            float v2 = acc[mi][nt][2] + b0;
            float v3 = acc[mi][nt][3] + b1;
            if (mode == 0) {
                *(float2*)&C[(size_t)m * N + n] = make_float2(v0, v1);
                *(float2*)&C[(size_t)(m + 8) * N + n] = make_float2(v2, v3);
            } else {
                int sec = n >> 10;
                int e = n & 1023;
                int h = e >> 6;
                int d = e & 63;
#pragma unroll
                for (int rr = 0; rr < 2; ++rr) {
                    int mm = m + rr * 8;
                    int bb = mm >> 10;
                    int s = mm & 1023;
                    size_t idx = (((size_t)(bb * kH + h)) * kS + s) * kHD + d;
                    float p0 = rr ? v2 : v0, p1 = rr ? v3 : v1;
                    if (sec == 0) {
                        uint32_t hw, lw;
                        packsplit(p0, p1, hw, lw);
                        *(uint32_t*)&g_qh[idx] = hw;
                        *(uint32_t*)&g_ql[idx] = lw;
                    } else if (sec == 1) {
                        *(float2*)&kout[idx] = make_float2(p0, p1);
                        uint32_t hw, lw;
                        packsplit(p0, p1, hw, lw);
                        *(uint32_t*)&g_kh[idx] = hw;
                        *(uint32_t*)&g_kl[idx] = lw;
                    } else {
                        *(float2*)&vout[idx] = make_float2(p0, p1);
                    }
                }
            }
        }
    }
}

// ---------------------------------------------------------------------------
// OV kernel (batch-shared, unchanged from R10)
// ---------------------------------------------------------------------------
__global__ __launch_bounds__(256, 2) void ov_kernel(
    const float* __restrict__ ov, const void* __restrict__ mask,
    float* __restrict__ out)
{
    extern __shared__ __half sV[];
    const int tid = threadIdx.x, lane = tid & 31, wid = tid >> 5;
    const int gID = lane >> 2, tig2 = (lane & 3) * 2;
    const int h = blockIdx.y, q0 = blockIdx.x * 64;
    const int qsub = wid & 3;
    const int dhalf = wid >> 2;
    const int mkind = g_mask_kind;
    const int qr0 = q0 + qsub * 16 + gID, qr1 = qr0 + 8;
    const size_t mr0 = ((size_t)h * kS + qr0) * kS;
    const size_t mr1 = ((size_t)h * kS + qr1) * kS;

    float o[4][4][4] = {};

    for (int kc = 0; kc < 8; ++kc) {
#pragma unroll
        for (int bb = 0; bb < 4; ++bb) {
            const size_t bhT = (size_t)(bb * kH + h) * kHD;
#pragma unroll
            for (int it = 0; it < 2; ++it) {
                int unit = tid + it * 256;
                int row = unit >> 3, u = (unit & 7) * 16;
                *(float4*)&sV[bb * OV_VT + row * 136 + u] =
                    *(const float4*)&g_vth[(bhT + row) * kS + kc * 128 + u];
                *(float4*)&sV[bb * OV_VT + row * 136 + u + 8] =
                    *(const float4*)&g_vth[(bhT + row) * kS + kc * 128 + u + 8];
            }
        }
        __syncthreads();

#pragma unroll
        for (int ks = 0; ks < 8; ++ks) {
            size_t kg = (size_t)kc * 128 + ks * 16 + tig2;
            uint2 m00 = mask2(mask, mr0 + kg, mkind);
            uint2 m02 = mask2(mask, mr0 + kg + 8, mkind);
            uint2 m10 = mask2(mask, mr1 + kg, mkind);
            uint2 m12 = mask2(mask, mr1 + kg + 8, mkind);
            float2 v00 = *(const float2*)&ov[mr0 + kg];
            float2 v02 = *(const float2*)&ov[mr0 + kg + 8];
            float2 v10 = *(const float2*)&ov[mr1 + kg];
            float2 v12 = *(const float2*)&ov[mr1 + kg + 8];
            uint32_t ah[4];
            ah[0] = packround(m00.x ? v00.x : 0.f, m00.y ? v00.y : 0.f);
            ah[1] = packround(m10.x ? v10.x : 0.f, m10.y ? v10.y : 0.f);
            ah[2] = packround(m02.x ? v02.x : 0.f, m02.y ? v02.y : 0.f);
            ah[3] = packround(m12.x ? v12.x : 0.f, m12.y ? v12.y : 0.f);
#pragma unroll
            for (int bb = 0; bb < 4; ++bb)
#pragma unroll
                for (int dn = 0; dn < 4; ++dn) {
                    int vb = bb * OV_VT +
                             (dhalf * 32 + dn * 8 + gID) * 136 + ks * 16 + tig2;
                    uint32_t b0 = *(const uint32_t*)&sV[vb];
                    uint32_t b1 = *(const uint32_t*)&sV[vb + 8];
                    mma16816(o[bb][dn], ah, b0, b1);
                }
        }
        __syncthreads();
    }

#pragma unroll
    for (int bb = 0; bb < 4; ++bb)
#pragma unroll
        for (int dn = 0; dn < 4; ++dn) {
            int d = h * kHD + dhalf * 32 + dn * 8 + tig2;
            *(float2*)&out[(size_t)(bb * kS + qr0) * kD + d] =
                make_float2(o[bb][dn][0], o[bb][dn][1]);
            *(float2*)&out[(size_t)(bb * kS + qr1) * kD + d] =
                make_float2(o[bb][dn][2], o[bb][dn][3]);
        }
}

// ---------------------------------------------------------------------------
// Flash kernel: V tile double-buffered via cp.async; K synchronous.
// ---------------------------------------------------------------------------
__global__ __launch_bounds__(256, 2) void flash_kernel(
    const void* __restrict__ mask, float* __restrict__ aio)
{
    extern __shared__ __half fsm[];
    __half* sKh = fsm + F_KH;   // [128][72]
    __half* sKl = fsm + F_KL;
    __half* sVh = fsm + F_VH;   // [2][64][136]

    const int tid = threadIdx.x, lane = tid & 31, wid = tid >> 5;
    const int gID = lane >> 2, tig2 = (lane & 3) * 2;
    const int b = blockIdx.z, h = blockIdx.y;
    const int qt = blockIdx.x;
    const int q0 = qt * 128;
    const int wq = wid * 16;
    const int mkind = g_mask_kind;
    const size_t bh = (size_t)(b * kH + h) * kS * kHD;
    const size_t bhT = (size_t)(b * kH + h) * kHD;
    const uint32_t sbV = smem_u32(sVh);

    // V staging coordinates: 4 x 16B per thread per tile
    auto stageV = [&](int c, int buf) {
#pragma unroll
        for (int it = 0; it < 4; ++it) {
            int unit = tid + it * 256;          // 0..1023
            int row = unit >> 4, u16 = unit & 15;
            uint32_t so = (uint32_t)(row * 272 + u16 * 16) + buf * (8704 * 2);
            CP_ASYNC16(sbV + so,
                       g_vth + (bhT + row) * kS + (size_t)c * 128 + u16 * 8);
        }
        CP_COMMIT();
    };

    // prefetch V(0) immediately
    stageV(0, 0);

    // stage Q tile (borrow sK space), load register fragments
#pragma unroll
    for (int it = 0; it < 4; ++it) {
        int unit = tid + it * 256;
        int row = unit >> 3, u = (unit & 7) * 8;
        *(float4*)&sKh[row * 72 + u] =
            *(const float4*)&g_qh[bh + (size_t)(q0 + row) * kHD + u];
        *(float4*)&sKl[row * 72 + u] =
            *(const float4*)&g_ql[bh + (size_t)(q0 + row) * kHD + u];
    }
    __syncthreads();
    uint32_t qfh[4][4], qfl[4][4];
#pragma unroll
    for (int ks = 0; ks < 4; ++ks) {
        int base = (wq + gID) * 72 + ks * 16 + tig2;
        qfh[ks][0] = *(const uint32_t*)&sKh[base];
        qfh[ks][1] = *(const uint32_t*)&sKh[base + 8 * 72];
        qfh[ks][2] = *(const uint32_t*)&sKh[base + 8];
        qfh[ks][3] = *(const uint32_t*)&sKh[base + 8 * 72 + 8];
        qfl[ks][0] = *(const uint32_t*)&sKl[base];
        qfl[ks][1] = *(const uint32_t*)&sKl[base + 8 * 72];
        qfl[ks][2] = *(const uint32_t*)&sKl[base + 8];
        qfl[ks][3] = *(const uint32_t*)&sKl[base + 8 * 72 + 8];
    }
    __syncthreads();

    float o[8][4] = {};
    float Z0 = 0.f, Z1 = 0.f;
    const int qr0 = q0 + wq + gID, qr1 = qr0 + 8;
    const size_t mr0 = ((size_t)h * kS + qr0) * kS;
    const size_t mr1 = ((size_t)h * kS + qr1) * kS;

    for (int kc = 0; kc <= qt; ++kc) {
        // prefetch V(kc+1) while loading K(kc) and computing chunk kc
        if (kc + 1 <= qt) stageV(kc + 1, (kc + 1) & 1);

        // K(kc) synchronous staging
#pragma unroll
        for (int it = 0; it < 4; ++it) {
            int unit = tid + it * 256;
            int row = unit >> 3, u = (unit & 7) * 8;
            *(float4*)&sKh[row * 72 + u] =
                *(const float4*)&g_kh[bh + (size_t)(kc * 128 + row) * kHD + u];
            *(float4*)&sKl[row * 72 + u] =
                *(const float4*)&g_kl[bh + (size_t)(kc * 128 + row) * kHD + u];
        }
        if (kc + 1 <= qt) CP_WAIT1(); else CP_WAIT0();
        __syncthreads();

        const __half* tV = sVh + (kc & 1) * 8704;

        for (int qq = 0; qq < 4; ++qq) {
            float sa[4][4] = {};
#pragma unroll
            for (int ks = 0; ks < 4; ++ks)
#pragma unroll
                for (int nt = 0; nt < 4; ++nt) {
                    int kb = (qq * 32 + nt * 8 + gID) * 72 + ks * 16 + tig2;
                    uint32_t b0 = *(const uint32_t*)&sKh[kb];
                    uint32_t b1 = *(const uint32_t*)&sKh[kb + 8];
                    mma16816(sa[nt], qfh[ks], b0, b1);
                    mma16816(sa[nt], qfl[ks], b0, b1);
                    uint32_t c0 = *(const uint32_t*)&sKl[kb];
                    uint32_t c1 = *(const uint32_t*)&sKl[kb + 8];
                    mma16816(sa[nt], qfh[ks], c0, c1);
                }

            uint32_t ehr0[4], ehr1[4];
#pragma unroll
            for (int nt = 0; nt < 4; ++nt) {
                int kg = kc * 128 + qq * 32 + nt * 8 + tig2;
                float e00 = (kg     <= qr0) ? __expf(sa[nt][0] * 0.125f) : 0.f;
                float e01 = (kg + 1 <= qr0) ? __expf(sa[nt][1] * 0.125f) : 0.f;
                float e10 = (kg     <= qr1) ? __expf(sa[nt][2] * 0.125f) : 0.f;
                float e11 = (kg + 1 <= qr1) ? __expf(sa[nt][3] * 0.125f) : 0.f;
                Z0 += e00 + e01;
                Z1 += e10 + e11;
                uint2 m0 = mask2(mask, mr0 + kg, mkind);
                uint2 m1 = mask2(mask, mr1 + kg, mkind);
                if (m0.x) e00 = 0.f;
                if (m0.y) e01 = 0.f;
                if (m1.x) e10 = 0.f;
                if (m1.y) e11 = 0.f;
                ehr0[nt] = packround(e00, e01);
                ehr1[nt] = packround(e10, e11);
            }
#pragma unroll
            for (int k2 = 0; k2 < 2; ++k2) {
                uint32_t ah[4] = {ehr0[2 * k2], ehr1[2 * k2],
                                  ehr0[2 * k2 + 1], ehr1[2 * k2 + 1]};
#pragma unroll
                for (int dn = 0; dn < 8; ++dn) {
                    int vb = (dn * 8 + gID) * 136 + qq * 32 + k2 * 16 + tig2;
                    uint32_t b0 = *(const uint32_t*)&tV[vb];
                    uint32_t b1 = *(const uint32_t*)&tV[vb + 8];
                    mma16816(o[dn], ah, b0, b1);
                }
            }
        }
        __syncthreads();
    }

    Z0 += __shfl_xor_sync(0xffffffffu, Z0, 1);
    Z0 += __shfl_xor_sync(0xffffffffu, Z0, 2);
    Z1 += __shfl_xor_sync(0xffffffffu, Z1, 1);
    Z1 += __shfl_xor_sync(0xffffffffu, Z1, 2);
    float i0 = 1.f / Z0, i1 = 1.f / Z1;

#pragma unroll
    for (int dn = 0; dn < 8; ++dn) {
        int d = h * kHD + dn * 8 + tig2;
        size_t r0 = (size_t)(b * kS + qr0) * kD + d;
        size_t r1 = (size_t)(b * kS + qr1) * kD + d;
        float2 p0 = *(float2*)&aio[r0];
        float2 p1 = *(float2*)&aio[r1];
        *(float2*)&aio[r0] =
            make_float2(p0.x + o[dn][0] * i0, p0.y + o[dn][1] * i0);
        *(float2*)&aio[r1] =
            make_float2(p1.x + o[dn][2] * i1, p1.y + o[dn][3] * i1);
    }
}

// ---------------------------------------------------------------------------
extern "C" void kernel_launch(void* const* d_in, const int* in_sizes, int n_in,
                              void* d_out, int out_size)
{
    const float* x       = (const float*)d_in[0];
    const float* w_attn  = (const float*)d_in[1];
    const float* b_attn  = (const float*)d_in[2];
    const float* w_proj  = (const float*)d_in[3];
    const float* b_proj  = (const float*)d_in[4];
    const float* ov      = (const float*)d_in[5];
    const void*  msk     = (const void*)d_in[6];

    float* out = (float*)d_out;
    float* presentK = out + (size_t)kM * kD;
    float* presentV = presentK + (size_t)kB * kH * kS * kHD;

    float* aptr = nullptr;
    __half *xh, *ah, *wth, *pth;
    cudaGetSymbolAddress((void**)&aptr, g_a);
    cudaGetSymbolAddress((void**)&xh, g_xh);
    cudaGetSymbolAddress((void**)&ah, g_ah);
    cudaGetSymbolAddress((void**)&wth, g_wth);
    cudaGetSymbolAddress((void**)&pth, g_pth);

    cudaFuncSetAttribute(flash_kernel,
                         cudaFuncAttributeMaxDynamicSharedMemorySize,
                         FLASH_SMEM_BYTES);
    cudaFuncSetAttribute(ov_kernel,
                         cudaFuncAttributeMaxDynamicSharedMemorySize,
                         OV_SMEM_BYTES);

    // 0) mask classification + operand prep
    detect_mask_kind_kernel<<<1, 256>>>((const unsigned int*)msk);
    round_kernel<<<kM * kD / 256, 256>>>(x, xh, kM * kD);
    transpose_h_kernel<<<dim3(3 * kD / 32, kD / 32), dim3(32, 8)>>>(
        w_attn, wth, kD, 3 * kD);
    transpose_h_kernel<<<dim3(kD / 32, kD / 32), dim3(32, 8)>>>(
        w_proj, pth, kD, kD);

    // 1) QKV GEMM -> present fp32 + q/k fp16 hi/lo
    mma_gemm_kernel<<<dim3(3 * kD / 128, kM / 128), 256>>>(
        xh, wth, b_attn, nullptr, kM, 3 * kD, kD, 1, presentK, presentV);

    // 2) V transpose -> g_vth
    vtrans_kernel<<<dim3(kHD / 32, kS / 32, kB * kH), dim3(32, 8)>>>(presentV);

    // 3) override term -> g_a (batch-shared; full overwrite)
    ov_kernel<<<dim3(kS / 64, kH), 256, OV_SMEM_BYTES>>>(ov, msk, aptr);

    // 4) flash attention adds softmax term -> g_a
    flash_kernel<<<dim3(kS / 128, kH, kB), 256, FLASH_SMEM_BYTES>>>(msk, aptr);

    // 5) round g_a, output projection
    round_kernel<<<kM * kD / 256, 256>>>(aptr, ah, kM * kD);
    mma_gemm_kernel<<<dim3(kD / 128, kM / 128), 256>>>(
        ah, pth, b_proj, out, kM, kD, kD, 0, nullptr, nullptr);
}

// round 12
// speedup vs baseline: 3.4027x; 1.0218x over previous
#include <cuda_runtime.h>
#include <cuda_fp16.h>
#include <cstdint>

// ---------------------------------------------------------------------------
// AttentionOverride, round 12: R11 + bit-packed mask (ballot prepass) used by
// flash+ov, and flash epilogue writes fp16 g_ah directly (round pass removed).
// Math value-identical to R11 -> rel_err must remain 4.540033e-4.
// Output layout: [ a (4M floats) | presentK (4M) | presentV (4M) ]
// ---------------------------------------------------------------------------

namespace {
constexpr int kB  = 4;
constexpr int kS  = 1024;
constexpr int kD  = 1024;
constexpr int kH  = 16;
constexpr int kHD = 64;
constexpr int kM  = kB * kS;  // 4096

constexpr int kSTR = 40;          // GEMM smem stride (half)
constexpr int GT   = 128 * kSTR;  // one GEMM tile in halves (5120)

// flash smem (half elems): K[128][72] hi/lo, V double buffer [2][64][136]
constexpr int F_KH = 0;
constexpr int F_KL = 9216;
constexpr int F_VH = 18432;
constexpr int FLASH_SMEM_BYTES = (18432 + 2 * 8704) * 2;  // 71680

constexpr int OV_VT = 8704;
constexpr int OV_SMEM_BYTES = 4 * OV_VT * 2;  // 69632
}  // namespace

// scratch (device globals; no allocation allowed)
__device__ float g_a[(size_t)kM * kD];          // ov term (fp32)
__device__ int   g_mask_kind;
__device__ uint32_t g_mpack[(size_t)kH * kS * (kS / 32)];  // 2MB bit mask
__device__ __half g_qh[(size_t)kM * kD], g_ql[(size_t)kM * kD];
__device__ __half g_kh[(size_t)kM * kD], g_kl[(size_t)kM * kD];
__device__ __half g_vth[(size_t)kM * kD];       // [BH][64][S]
__device__ __half g_xh[(size_t)kM * kD];
__device__ __half g_ah[(size_t)kM * kD];        // a (fp16) for proj
__device__ __half g_wth[(size_t)3 * kD * kD];
__device__ __half g_pth[(size_t)kD * kD];

// ---------------------------------------------------------------------------
__device__ __forceinline__ void mma16816(float* c, const uint32_t* a,
                                         uint32_t b0, uint32_t b1) {
    asm volatile(
        "mma.sync.aligned.m16n8k16.row.col.f32.f16.f16.f32 "
        "{%0,%1,%2,%3}, {%4,%5,%6,%7}, {%8,%9}, {%0,%1,%2,%3};"
        : "+f"(c[0]), "+f"(c[1]), "+f"(c[2]), "+f"(c[3])
        : "r"(a[0]), "r"(a[1]), "r"(a[2]), "r"(a[3]), "r"(b0), "r"(b1));
}

#define CP_ASYNC16(saddr, gptr)                                          \
    asm volatile("cp.async.cg.shared.global [%0], [%1], 16;"             \
                 :: "r"(saddr), "l"(gptr) : "memory")
#define CP_COMMIT() asm volatile("cp.async.commit_group;" ::: "memory")
#define CP_WAIT0()  asm volatile("cp.async.wait_group 0;" ::: "memory")
#define CP_WAIT1()  asm volatile("cp.async.wait_group 1;" ::: "memory")

__device__ __forceinline__ uint32_t smem_u32(const void* p) {
    return (uint32_t)__cvta_generic_to_shared(p);
}

__device__ __forceinline__ void split2(float x, __half& h, __half& l) {
    h = __float2half_rn(x);
    l = __float2half_rn(x - __half2float(h));
}
__device__ __forceinline__ uint32_t packh(__half a, __half b) {
    __half2 t = __halves2half2(a, b);
    return *(uint32_t*)&t;
}
__device__ __forceinline__ uint32_t packround(float x, float y) {
    return packh(__float2half_rn(x), __float2half_rn(y));
}
__device__ __forceinline__ void packsplit(float x, float y,
                                          uint32_t& hw, uint32_t& lw) {
    __half hx, lx, hy, ly;
    split2(x, hx, lx);
    split2(y, hy, ly);
    hw = packh(hx, hy);
    lw = packh(lx, ly);
}

// ---------------------------------------------------------------------------
__global__ void round_kernel(const float* __restrict__ X,
                             __half* __restrict__ H, int n) {
    int i = blockIdx.x * 256 + threadIdx.x;
    if (i < n) H[i] = __float2half_rn(X[i]);
}

__global__ void transpose_h_kernel(const float* __restrict__ W,
                                   __half* __restrict__ Th, int K, int N) {
    __shared__ float t[32][33];
    int n0 = blockIdx.x * 32, k0 = blockIdx.y * 32;
    int tx = threadIdx.x, ty = threadIdx.y;
#pragma unroll
    for (int j = 0; j < 4; ++j)
        t[ty + j * 8][tx] = W[(size_t)(k0 + ty + j * 8) * N + n0 + tx];
    __syncthreads();
#pragma unroll
    for (int j = 0; j < 4; ++j)
        Th[(size_t)(n0 + ty + j * 8) * K + k0 + tx] =
            __float2half_rn(t[tx][ty + j * 8]);
}

__global__ void vtrans_kernel(const float* __restrict__ V) {
    __shared__ float t[32][33];
    int d0 = blockIdx.x * 32, s0 = blockIdx.y * 32, bh = blockIdx.z;
    int tx = threadIdx.x, ty = threadIdx.y;
#pragma unroll
    for (int j = 0; j < 4; ++j)
        t[ty + j * 8][tx] =
            V[(size_t)bh * (kS * kHD) + (size_t)(s0 + ty + j * 8) * kHD + d0 + tx];
    __syncthreads();
#pragma unroll
    for (int j = 0; j < 4; ++j)
        g_vth[((size_t)bh * kHD + d0 + ty + j * 8) * kS + s0 + tx] =
            __float2half_rn(t[tx][ty + j * 8]);
}

__global__ void detect_mask_kind_kernel(const unsigned int* __restrict__ m) {
    __shared__ int any_gt1, any_not_f32;
    if (threadIdx.x == 0) { any_gt1 = 0; any_not_f32 = 0; }
    __syncthreads();
    int gt1 = 0, nf32 = 0;
    for (int i = threadIdx.x; i < 16384; i += 256) {
        unsigned int w = m[i];
        if (w > 1u) gt1 = 1;
        if (w != 0u && w != 0x3F800000u) nf32 = 1;
    }
    if (gt1)  atomicOr(&any_gt1, 1);
    if (nf32) atomicOr(&any_not_f32, 1);
    __syncthreads();
    if (threadIdx.x == 0)
        g_mask_kind = (!any_gt1) ? 1 : ((!any_not_f32) ? 2 : 0);
}

// Bit-pack the mask: one thread per element, warp ballot -> one uint32/32.
__global__ void pack_mask_kernel(const void* __restrict__ m) {
    size_t i = (size_t)blockIdx.x * 256 + threadIdx.x;
    const int kind = g_mask_kind;
    bool v;
    if (kind == 0) v = ((const unsigned char*)m)[i] != 0;
    else           v = ((const unsigned int*)m)[i] != 0;  // int32 0/1 or f32 0/1.0
    unsigned int w = __ballot_sync(0xffffffffu, v);
    if ((threadIdx.x & 31) == 0) g_mpack[i >> 5] = w;
}

// ---------------------------------------------------------------------------
// HMMA GEMM, fp16 1-product, cp.async double-buffered (unchanged from R11).
// ---------------------------------------------------------------------------
__global__ __launch_bounds__(256, 2) void mma_gemm_kernel(
    const __half* __restrict__ Ah, const __half* __restrict__ Bh,
    const float* __restrict__ bias, float* __restrict__ C,
    int M, int N, int K, int mode,
    float* __restrict__ kout, float* __restrict__ vout)
{
    __shared__ __half sA[2 * GT], sB[2 * GT];

    const int tid = threadIdx.x;
    const int lane = tid & 31;
    const int wid = tid >> 5;
    const int wm = (wid & 3) * 32;
    const int wn = (wid >> 2) * 64;
    const int m0 = blockIdx.y * 128;
    const int n0 = blockIdx.x * 128;
    const int gID = lane >> 2;
    const int tig2 = (lane & 3) * 2;

    const uint32_t sbA = smem_u32(sA);
    const uint32_t sbB = smem_u32(sB);

    const int rr0 = tid >> 2;
    const int uu0 = tid & 3;
    const int rr1 = (tid + 256) >> 2;
    const int uu1 = (tid + 256) & 3;

    auto stage = [&](int c, int buf) {
        size_t ka = (size_t)c * 32;
        uint32_t so0 = (uint32_t)(rr0 * 80 + uu0 * 16) + buf * (GT * 2);
        uint32_t so1 = (uint32_t)(rr1 * 80 + uu1 * 16) + buf * (GT * 2);
        CP_ASYNC16(sbA + so0, Ah + (size_t)(m0 + rr0) * K + ka + uu0 * 8);
        CP_ASYNC16(sbA + so1, Ah + (size_t)(m0 + rr1) * K + ka + uu1 * 8);
        CP_ASYNC16(sbB + so0, Bh + (size_t)(n0 + rr0) * K + ka + uu0 * 8);
        CP_ASYNC16(sbB + so1, Bh + (size_t)(n0 + rr1) * K + ka + uu1 * 8);
        CP_COMMIT();
    };

    float acc[2][8][4] = {};
    const int nchunks = K / 32;

    stage(0, 0);
    for (int c = 0; c < nchunks; ++c) {
        if (c + 1 < nchunks) {
            stage(c + 1, (c + 1) & 1);
            CP_WAIT1();
        } else {
            CP_WAIT0();
        }
        __syncthreads();

        const __half* tA = sA + (c & 1) * GT;
        const __half* tB = sB + (c & 1) * GT;
#pragma unroll
        for (int ks = 0; ks < 2; ++ks) {
            const int k0 = ks * 16;
            uint32_t ah[2][4];
#pragma unroll
            for (int mi = 0; mi < 2; ++mi) {
                int base = (wm + mi * 16 + gID) * kSTR + k0 + tig2;
                ah[mi][0] = *(const uint32_t*)&tA[base];
                ah[mi][1] = *(const uint32_t*)&tA[base + 8 * kSTR];
                ah[mi][2] = *(const uint32_t*)&tA[base + 8];
                ah[mi][3] = *(const uint32_t*)&tA[base + 8 * kSTR + 8];
            }
#pragma unroll
            for (int nt = 0; nt < 8; ++nt) {
                int nb = (wn + nt * 8 + gID) * kSTR + k0 + tig2;
                uint32_t bh0 = *(const uint32_t*)&tB[nb];
                uint32_t bh1 = *(const uint32_t*)&tB[nb + 8];
                mma16816(acc[0][nt], ah[0], bh0, bh1);
                mma16816(acc[1][nt], ah[1], bh0, bh1);
            }
        }
        __syncthreads();
    }

#pragma unroll
    for (int mi = 0; mi < 2; ++mi) {
#pragma unroll
        for (int nt = 0; nt < 8; ++nt) {
            int m = m0 + wm + mi * 16 + gID;
            int n = n0 + wn + nt * 8 + tig2;
            float b0 = bias[n], b1 = bias[n + 1];
            float v0 = acc[mi][nt][0] + b0;
            float v1 = acc[mi][nt][1] + b1;
            float v2 = acc[mi][nt][2] + b0;
            float v3 = acc[mi][nt][3] + b1;
            if (mode == 0) {
                *(float2*)&C[(size_t)m * N + n] = make_float2(v0, v1);
                *(float2*)&C[(size_t)(m + 8) * N + n] = make_float2(v2, v3);
            } else {
                int sec = n >> 10;
                int e = n & 1023;
                int h = e >> 6;
                int d = e & 63;
#pragma unroll
                for (int rr = 0; rr < 2; ++rr) {
                    int mm = m + rr * 8;
                    int bb = mm >> 10;
                    int s = mm & 1023;
                    size_t idx = (((size_t)(bb * kH + h)) * kS + s) * kHD + d;
                    float p0 = rr ? v2 : v0, p1 = rr ? v3 : v1;
                    if (sec == 0) {
                        uint32_t hw, lw;
                        packsplit(p0, p1, hw, lw);
                        *(uint32_t*)&g_qh[idx] = hw;
                        *(uint32_t*)&g_ql[idx] = lw;
                    } else if (sec == 1) {
                        *(float2*)&kout[idx] = make_float2(p0, p1);
                        uint32_t hw, lw;
                        packsplit(p0, p1, hw, lw);
                        *(uint32_t*)&g_kh[idx] = hw;
                        *(uint32_t*)&g_kl[idx] = lw;
                    } else {
                        *(float2*)&vout[idx] = make_float2(p0, p1);
                    }
                }
            }
        }
    }
}

// ---------------------------------------------------------------------------
// OV kernel (batch-shared) with bit-packed mask.
// ---------------------------------------------------------------------------
__global__ __launch_bounds__(256, 2) void ov_kernel(
    const float* __restrict__ ov, float* __restrict__ out)
{
    extern __shared__ __half sV[];
    const int tid = threadIdx.x, lane = tid & 31, wid = tid >> 5;
    const int gID = lane >> 2, tig2 = (lane & 3) * 2;
    const int h = blockIdx.y, q0 = blockIdx.x * 64;
    const int qsub = wid & 3;
    const int dhalf = wid >> 2;
    const int qr0 = q0 + qsub * 16 + gID, qr1 = qr0 + 8;
    const size_t mr0 = ((size_t)h * kS + qr0) * kS;
    const size_t mr1 = ((size_t)h * kS + qr1) * kS;
    const size_t wb0 = ((size_t)h * kS + qr0) * 32;
    const size_t wb1 = ((size_t)h * kS + qr1) * 32;

    float o[4][4][4] = {};

    for (int kc = 0; kc < 8; ++kc) {
#pragma unroll
        for (int bb = 0; bb < 4; ++bb) {
            const size_t bhT = (size_t)(bb * kH + h) * kHD;
#pragma unroll
            for (int it = 0; it < 2; ++it) {
                int unit = tid + it * 256;
                int row = unit >> 3, u = (unit & 7) * 16;
                *(float4*)&sV[bb * OV_VT + row * 136 + u] =
                    *(const float4*)&g_vth[(bhT + row) * kS + kc * 128 + u];
                *(float4*)&sV[bb * OV_VT + row * 136 + u + 8] =
                    *(const float4*)&g_vth[(bhT + row) * kS + kc * 128 + u + 8];
            }
        }
        __syncthreads();

        uint32_t w0[4], w1[4];
#pragma unroll
        for (int j = 0; j < 4; ++j) {
            w0[j] = g_mpack[wb0 + kc * 4 + j];
            w1[j] = g_mpack[wb1 + kc * 4 + j];
        }

#pragma unroll
        for (int ks = 0; ks < 8; ++ks) {
            size_t kg = (size_t)kc * 128 + ks * 16 + tig2;
            int wd = ks >> 1;
            int bp = (ks & 1) * 16 + tig2;
            float2 v00 = *(const float2*)&ov[mr0 + kg];
            float2 v02 = *(const float2*)&ov[mr0 + kg + 8];
            float2 v10 = *(const float2*)&ov[mr1 + kg];
            float2 v12 = *(const float2*)&ov[mr1 + kg + 8];
            uint32_t ah[4];
            ah[0] = packround(((w0[wd] >> bp) & 1) ? v00.x : 0.f,
                              ((w0[wd] >> (bp + 1)) & 1) ? v00.y : 0.f);
            ah[1] = packround(((w1[wd] >> bp) & 1) ? v10.x : 0.f,
                              ((w1[wd] >> (bp + 1)) & 1) ? v10.y : 0.f);
            ah[2] = packround(((w0[wd] >> (bp + 8)) & 1) ? v02.x : 0.f,
                              ((w0[wd] >> (bp + 9)) & 1) ? v02.y : 0.f);
            ah[3] = packround(((w1[wd] >> (bp + 8)) & 1) ? v12.x : 0.f,
                              ((w1[wd] >> (bp + 9)) & 1) ? v12.y : 0.f);
#pragma unroll
            for (int bb = 0; bb < 4; ++bb)
#pragma unroll
                for (int dn = 0; dn < 4; ++dn) {
                    int vb = bb * OV_VT +
                             (dhalf * 32 + dn * 8 + gID) * 136 + ks * 16 + tig2;
                    uint32_t b0 = *(const uint32_t*)&sV[vb];
                    uint32_t b1 = *(const uint32_t*)&sV[vb + 8];
                    mma16816(o[bb][dn], ah, b0, b1);
                }
        }
        __syncthreads();
    }

#pragma unroll
    for (int bb = 0; bb < 4; ++bb)
#pragma unroll
        for (int dn = 0; dn < 4; ++dn) {
            int d = h * kHD + dhalf * 32 + dn * 8 + tig2;
            *(float2*)&out[(size_t)(bb * kS + qr0) * kD + d] =
                make_float2(o[bb][dn][0], o[bb][dn][1]);
            *(float2*)&out[(size_t)(bb * kS + qr1) * kD + d] =
                make_float2(o[bb][dn][2], o[bb][dn][3]);
        }
}

// ---------------------------------------------------------------------------
// Flash kernel: bit-packed mask; epilogue writes g_ah (fp16) directly.
// ---------------------------------------------------------------------------
__global__ __launch_bounds__(256, 2) void flash_kernel(
    const float* __restrict__ aio)
{
    extern __shared__ __half fsm[];
    __half* sKh = fsm + F_KH;
    __half* sKl = fsm + F_KL;
    __half* sVh = fsm + F_VH;   // [2][64][136]

    const int tid = threadIdx.x, lane = tid & 31, wid = tid >> 5;
    const int gID = lane >> 2, tig2 = (lane & 3) * 2;
    const int b = blockIdx.z, h = blockIdx.y;
    const int qt = blockIdx.x;
    const int q0 = qt * 128;
    const int wq = wid * 16;
    const size_t bh = (size_t)(b * kH + h) * kS * kHD;
    const size_t bhT = (size_t)(b * kH + h) * kHD;
    const uint32_t sbV = smem_u32(sVh);

    auto stageV = [&](int c, int buf) {
#pragma unroll
        for (int it = 0; it < 4; ++it) {
            int unit = tid + it * 256;
            int row = unit >> 4, u16 = unit & 15;
            uint32_t so = (uint32_t)(row * 272 + u16 * 16) + buf * (8704 * 2);
            CP_ASYNC16(sbV + so,
                       g_vth + (bhT + row) * kS + (size_t)c * 128 + u16 * 8);
        }
        CP_COMMIT();
    };

    stageV(0, 0);

#pragma unroll
    for (int it = 0; it < 4; ++it) {
        int unit = tid + it * 256;
        int row = unit >> 3, u = (unit & 7) * 8;
        *(float4*)&sKh[row * 72 + u] =
            *(const float4*)&g_qh[bh + (size_t)(q0 + row) * kHD + u];
        *(float4*)&sKl[row * 72 + u] =
            *(const float4*)&g_ql[bh + (size_t)(q0 + row) * kHD + u];
    }
    __syncthreads();
    uint32_t qfh[4][4], qfl[4][4];
#pragma unroll
    for (int ks = 0; ks < 4; ++ks) {
        int base = (wq + gID) * 72 + ks * 16 + tig2;
        qfh[ks][0] = *(const uint32_t*)&sKh[base];
        qfh[ks][1] = *(const uint32_t*)&sKh[base + 8 * 72];
        qfh[ks][2] = *(const uint32_t*)&sKh[base + 8];
        qfh[ks][3] = *(const uint32_t*)&sKh[base + 8 * 72 + 8];
        qfl[ks][0] = *(const uint32_t*)&sKl[base];
        qfl[ks][1] = *(const uint32_t*)&sKl[base + 8 * 72];
        qfl[ks][2] = *(const uint32_t*)&sKl[base + 8];
        qfl[ks][3] = *(const uint32_t*)&sKl[base + 8 * 72 + 8];
    }
    __syncthreads();

    float o[8][4] = {};
    float Z0 = 0.f, Z1 = 0.f;
    const int qr0 = q0 + wq + gID, qr1 = qr0 + 8;
    const size_t wb0 = ((size_t)h * kS + qr0) * 32;
    const size_t wb1 = ((size_t)h * kS + qr1) * 32;

    for (int kc = 0; kc <= qt; ++kc) {
        if (kc + 1 <= qt) stageV(kc + 1, (kc + 1) & 1);

#pragma unroll
        for (int it = 0; it < 4; ++it) {
            int unit = tid + it * 256;
            int row = unit >> 3, u = (unit & 7) * 8;
            *(float4*)&sKh[row * 72 + u] =
                *(const float4*)&g_kh[bh + (size_t)(kc * 128 + row) * kHD + u];
            *(float4*)&sKl[row * 72 + u] =
                *(const float4*)&g_kl[bh + (size_t)(kc * 128 + row) * kHD + u];
        }
        if (kc + 1 <= qt) CP_WAIT1(); else CP_WAIT0();
        __syncthreads();

        const __half* tV = sVh + (kc & 1) * 8704;

        for (int qq = 0; qq < 4; ++qq) {
            float sa[4][4] = {};
#pragma unroll
            for (int ks = 0; ks < 4; ++ks)
#pragma unroll
                for (int nt = 0; nt < 4; ++nt) {
                    int kb = (qq * 32 + nt * 8 + gID) * 72 + ks * 16 + tig2;
                    uint32_t b0 = *(const uint32_t*)&sKh[kb];
                    uint32_t b1 = *(const uint32_t*)&sKh[kb + 8];
                    mma16816(sa[nt], qfh[ks], b0, b1);
                    mma16816(sa[nt], qfl[ks], b0, b1);
                    uint32_t c0 = *(const uint32_t*)&sKl[kb];
                    uint32_t c1 = *(const uint32_t*)&sKl[kb + 8];
                    mma16816(sa[nt], qfh[ks], c0, c1);
                }

            uint32_t mw0 = g_mpack[wb0 + kc * 4 + qq];
            uint32_t mw1 = g_mpack[wb1 + kc * 4 + qq];
            uint32_t ehr0[4], ehr1[4];
#pragma unroll
            for (int nt = 0; nt < 4; ++nt) {
                int kg = kc * 128 + qq * 32 + nt * 8 + tig2;
                int bp = nt * 8 + tig2;
                float e00 = (kg     <= qr0) ? __expf(sa[nt][0] * 0.125f) : 0.f;
                float e01 = (kg + 1 <= qr0) ? __expf(sa[nt][1] * 0.125f) : 0.f;
                float e10 = (kg     <= qr1) ? __expf(sa[nt][2] * 0.125f) : 0.f;
                float e11 = (kg + 1 <= qr1) ? __expf(sa[nt][3] * 0.125f) : 0.f;
                Z0 += e00 + e01;
                Z1 += e10 + e11;
                if ((mw0 >> bp) & 1) e00 = 0.f;
                if ((mw0 >> (bp + 1)) & 1) e01 = 0.f;
                if ((mw1 >> bp) & 1) e10 = 0.f;
                if ((mw1 >> (bp + 1)) & 1) e11 = 0.f;
                ehr0[nt] = packround(e00, e01);
                ehr1[nt] = packround(e10, e11);
            }
#pragma unroll
            for (int k2 = 0; k2 < 2; ++k2) {
                uint32_t ah[4] = {ehr0[2 * k2], ehr1[2 * k2],
                                  ehr0[2 * k2 + 1], ehr1[2 * k2 + 1]};
#pragma unroll
                for (int dn = 0; dn < 8; ++dn) {
                    int vb = (dn * 8 + gID) * 136 + qq * 32 + k2 * 16 + tig2;
                    uint32_t b0 = *(const uint32_t*)&tV[vb];
                    uint32_t b1 = *(const uint32_t*)&tV[vb + 8];
                    mma16816(o[dn], ah, b0, b1);
                }
            }
        }
        __syncthreads();
    }

    Z0 += __shfl_xor_sync(0xffffffffu, Z0, 1);
    Z0 += __shfl_xor_sync(0xffffffffu, Z0, 2);
    Z1 += __shfl_xor_sync(0xffffffffu, Z1, 1);
    Z1 += __shfl_xor_sync(0xffffffffu, Z1, 2);
    float i0 = 1.f / Z0, i1 = 1.f / Z1;

    // epilogue: a = ov_term + o/Z, rounded straight to fp16 for the proj GEMM
#pragma unroll
    for (int dn = 0; dn < 8; ++dn) {
        int d = h * kHD + dn * 8 + tig2;
        size_t r0 = (size_t)(b * kS + qr0) * kD + d;
        size_t r1 = (size_t)(b * kS + qr1) * kD + d;
        float2 p0 = *(const float2*)&aio[r0];
        float2 p1 = *(const float2*)&aio[r1];
        *(uint32_t*)&g_ah[r0] =
            packround(p0.x + o[dn][0] * i0, p0.y + o[dn][1] * i0);
        *(uint32_t*)&g_ah[r1] =
            packround(p1.x + o[dn][2] * i1, p1.y + o[dn][3] * i1);
    }
}

// ---------------------------------------------------------------------------
extern "C" void kernel_launch(void* const* d_in, const int* in_sizes, int n_in,
                              void* d_out, int out_size)
{
    const float* x       = (const float*)d_in[0];
    const float* w_attn  = (const float*)d_in[1];
    const float* b_attn  = (const float*)d_in[2];
    const float* w_proj  = (const float*)d_in[3];
    const float* b_proj  = (const float*)d_in[4];
    const float* ov      = (const float*)d_in[5];
    const void*  msk     = (const void*)d_in[6];

    float* out = (float*)d_out;
    float* presentK = out + (size_t)kM * kD;
    float* presentV = presentK + (size_t)kB * kH * kS * kHD;

    float* aptr = nullptr;
    __half *xh, *ah, *wth, *pth;
    cudaGetSymbolAddress((void**)&aptr, g_a);
    cudaGetSymbolAddress((void**)&xh, g_xh);
    cudaGetSymbolAddress((void**)&ah, g_ah);
    cudaGetSymbolAddress((void**)&wth, g_wth);
    cudaGetSymbolAddress((void**)&pth, g_pth);

    cudaFuncSetAttribute(flash_kernel,
                         cudaFuncAttributeMaxDynamicSharedMemorySize,
                         FLASH_SMEM_BYTES);
    cudaFuncSetAttribute(ov_kernel,
                         cudaFuncAttributeMaxDynamicSharedMemorySize,
                         OV_SMEM_BYTES);

    // 0) mask classification + bit-pack + operand prep
    detect_mask_kind_kernel<<<1, 256>>>((const unsigned int*)msk);
    pack_mask_kernel<<<(kH * kS * kS) / 256, 256>>>(msk);
    round_kernel<<<kM * kD / 256, 256>>>(x, xh, kM * kD);
    transpose_h_kernel<<<dim3(3 * kD / 32, kD / 32), dim3(32, 8)>>>(
        w_attn, wth, kD, 3 * kD);
    transpose_h_kernel<<<dim3(kD / 32, kD / 32), dim3(32, 8)>>>(
        w_proj, pth, kD, kD);

    // 1) QKV GEMM -> present fp32 + q/k fp16 hi/lo
    mma_gemm_kernel<<<dim3(3 * kD / 128, kM / 128), 256>>>(
        xh, wth, b_attn, nullptr, kM, 3 * kD, kD, 1, presentK, presentV);

    // 2) V transpose -> g_vth
    vtrans_kernel<<<dim3(kHD / 32, kS / 32, kB * kH), dim3(32, 8)>>>(presentV);

    // 3) override term -> g_a (batch-shared)
    ov_kernel<<<dim3(kS / 64, kH), 256, OV_SMEM_BYTES>>>(ov, aptr);

    // 4) flash: adds softmax term, writes fp16 a directly
    flash_kernel<<<dim3(kS / 128, kH, kB), 256, FLASH_SMEM_BYTES>>>(aptr);

    // 5) output projection
    mma_gemm_kernel<<<dim3(kD / 128, kM / 128), 256>>>(
        ah, pth, b_proj, out, kM, kD, kD, 0, nullptr, nullptr);
}

// round 13
// speedup vs baseline: 3.7304x; 1.0963x over previous
#include <cuda_runtime.h>
#include <cuda_fp16.h>
#include <cstdint>

// ---------------------------------------------------------------------------
// AttentionOverride, round 13: R12 + 1-product fp16 QK^T (q/k lo-halves
// removed), K+V both cp.async double-buffered in flash, heavy-first q-tile
// scheduling. All stages now 1-product fp16.
// Output layout: [ a (4M floats) | presentK (4M) | presentV (4M) ]
// ---------------------------------------------------------------------------

namespace {
constexpr int kB  = 4;
constexpr int kS  = 1024;
constexpr int kD  = 1024;
constexpr int kH  = 16;
constexpr int kHD = 64;
constexpr int kM  = kB * kS;  // 4096

constexpr int kSTR = 40;          // GEMM smem stride (half)
constexpr int GT   = 128 * kSTR;  // one GEMM tile in halves (5120)

// flash smem (half elems): K double buffer [2][128][72], V double [2][64][136]
constexpr int F_KT = 9216;                     // one K tile (128*72)
constexpr int F_VT = 8704;                     // one V tile (64*136)
constexpr int F_V0 = 2 * F_KT;                 // 18432
constexpr int FLASH_SMEM_BYTES = (2 * F_KT + 2 * F_VT) * 2;  // 71680

constexpr int OV_VT = 8704;
constexpr int OV_SMEM_BYTES = 4 * OV_VT * 2;   // 69632
}  // namespace

// scratch (device globals; no allocation allowed)
__device__ float g_a[(size_t)kM * kD];          // ov term (fp32)
__device__ int   g_mask_kind;
__device__ uint32_t g_mpack[(size_t)kH * kS * (kS / 32)];
__device__ __half g_qh[(size_t)kM * kD];
__device__ __half g_kh[(size_t)kM * kD];
__device__ __half g_vth[(size_t)kM * kD];       // [BH][64][S]
__device__ __half g_xh[(size_t)kM * kD];
__device__ __half g_ah[(size_t)kM * kD];        // a (fp16) for proj
__device__ __half g_wth[(size_t)3 * kD * kD];
__device__ __half g_pth[(size_t)kD * kD];

// ---------------------------------------------------------------------------
__device__ __forceinline__ void mma16816(float* c, const uint32_t* a,
                                         uint32_t b0, uint32_t b1) {
    asm volatile(
        "mma.sync.aligned.m16n8k16.row.col.f32.f16.f16.f32 "
        "{%0,%1,%2,%3}, {%4,%5,%6,%7}, {%8,%9}, {%0,%1,%2,%3};"
        : "+f"(c[0]), "+f"(c[1]), "+f"(c[2]), "+f"(c[3])
        : "r"(a[0]), "r"(a[1]), "r"(a[2]), "r"(a[3]), "r"(b0), "r"(b1));
}

#define CP_ASYNC16(saddr, gptr)                                          \
    asm volatile("cp.async.cg.shared.global [%0], [%1], 16;"             \
                 :: "r"(saddr), "l"(gptr) : "memory")
#define CP_COMMIT() asm volatile("cp.async.commit_group;" ::: "memory")
#define CP_WAIT0()  asm volatile("cp.async.wait_group 0;" ::: "memory")
#define CP_WAIT1()  asm volatile("cp.async.wait_group 1;" ::: "memory")

__device__ __forceinline__ uint32_t smem_u32(const void* p) {
    return (uint32_t)__cvta_generic_to_shared(p);
}

__device__ __forceinline__ uint32_t packh(__half a, __half b) {
    __half2 t = __halves2half2(a, b);
    return *(uint32_t*)&t;
}
__device__ __forceinline__ uint32_t packround(float x, float y) {
    return packh(__float2half_rn(x), __float2half_rn(y));
}

// ---------------------------------------------------------------------------
__global__ void round_kernel(const float* __restrict__ X,
                             __half* __restrict__ H, int n) {
    int i = blockIdx.x * 256 + threadIdx.x;
    if (i < n) H[i] = __float2half_rn(X[i]);
}

__global__ void transpose_h_kernel(const float* __restrict__ W,
                                   __half* __restrict__ Th, int K, int N) {
    __shared__ float t[32][33];
    int n0 = blockIdx.x * 32, k0 = blockIdx.y * 32;
    int tx = threadIdx.x, ty = threadIdx.y;
#pragma unroll
    for (int j = 0; j < 4; ++j)
        t[ty + j * 8][tx] = W[(size_t)(k0 + ty + j * 8) * N + n0 + tx];
    __syncthreads();
#pragma unroll
    for (int j = 0; j < 4; ++j)
        Th[(size_t)(n0 + ty + j * 8) * K + k0 + tx] =
            __float2half_rn(t[tx][ty + j * 8]);
}

__global__ void vtrans_kernel(const float* __restrict__ V) {
    __shared__ float t[32][33];
    int d0 = blockIdx.x * 32, s0 = blockIdx.y * 32, bh = blockIdx.z;
    int tx = threadIdx.x, ty = threadIdx.y;
#pragma unroll
    for (int j = 0; j < 4; ++j)
        t[ty + j * 8][tx] =
            V[(size_t)bh * (kS * kHD) + (size_t)(s0 + ty + j * 8) * kHD + d0 + tx];
    __syncthreads();
#pragma unroll
    for (int j = 0; j < 4; ++j)
        g_vth[((size_t)bh * kHD + d0 + ty + j * 8) * kS + s0 + tx] =
            __float2half_rn(t[tx][ty + j * 8]);
}

__global__ void detect_mask_kind_kernel(const unsigned int* __restrict__ m) {
    __shared__ int any_gt1, any_not_f32;
    if (threadIdx.x == 0) { any_gt1 = 0; any_not_f32 = 0; }
    __syncthreads();
    int gt1 = 0, nf32 = 0;
    for (int i = threadIdx.x; i < 16384; i += 256) {
        unsigned int w = m[i];
        if (w > 1u) gt1 = 1;
        if (w != 0u && w != 0x3F800000u) nf32 = 1;
    }
    if (gt1)  atomicOr(&any_gt1, 1);
    if (nf32) atomicOr(&any_not_f32, 1);
    __syncthreads();
    if (threadIdx.x == 0)
        g_mask_kind = (!any_gt1) ? 1 : ((!any_not_f32) ? 2 : 0);
}

__global__ void pack_mask_kernel(const void* __restrict__ m) {
    size_t i = (size_t)blockIdx.x * 256 + threadIdx.x;
    const int kind = g_mask_kind;
    bool v;
    if (kind == 0) v = ((const unsigned char*)m)[i] != 0;
    else           v = ((const unsigned int*)m)[i] != 0;
    unsigned int w = __ballot_sync(0xffffffffu, v);
    if ((threadIdx.x & 31) == 0) g_mpack[i >> 5] = w;
}

// ---------------------------------------------------------------------------
// HMMA GEMM, fp16 1-product, cp.async double-buffered.
// ---------------------------------------------------------------------------
__global__ __launch_bounds__(256, 2) void mma_gemm_kernel(
    const __half* __restrict__ Ah, const __half* __restrict__ Bh,
    const float* __restrict__ bias, float* __restrict__ C,
    int M, int N, int K, int mode,
    float* __restrict__ kout, float* __restrict__ vout)
{
    __shared__ __half sA[2 * GT], sB[2 * GT];

    const int tid = threadIdx.x;
    const int lane = tid & 31;
    const int wid = tid >> 5;
    const int wm = (wid & 3) * 32;
    const int wn = (wid >> 2) * 64;
    const int m0 = blockIdx.y * 128;
    const int n0 = blockIdx.x * 128;
    const int gID = lane >> 2;
    const int tig2 = (lane & 3) * 2;

    const uint32_t sbA = smem_u32(sA);
    const uint32_t sbB = smem_u32(sB);

    const int rr0 = tid >> 2;
    const int uu0 = tid & 3;
    const int rr1 = (tid + 256) >> 2;
    const int uu1 = (tid + 256) & 3;

    auto stage = [&](int c, int buf) {
        size_t ka = (size_t)c * 32;
        uint32_t so0 = (uint32_t)(rr0 * 80 + uu0 * 16) + buf * (GT * 2);
        uint32_t so1 = (uint32_t)(rr1 * 80 + uu1 * 16) + buf * (GT * 2);
        CP_ASYNC16(sbA + so0, Ah + (size_t)(m0 + rr0) * K + ka + uu0 * 8);
        CP_ASYNC16(sbA + so1, Ah + (size_t)(m0 + rr1) * K + ka + uu1 * 8);
        CP_ASYNC16(sbB + so0, Bh + (size_t)(n0 + rr0) * K + ka + uu0 * 8);
        CP_ASYNC16(sbB + so1, Bh + (size_t)(n0 + rr1) * K + ka + uu1 * 8);
        CP_COMMIT();
    };

    float acc[2][8][4] = {};
    const int nchunks = K / 32;

    stage(0, 0);
    for (int c = 0; c < nchunks; ++c) {
        if (c + 1 < nchunks) {
            stage(c + 1, (c + 1) & 1);
            CP_WAIT1();
        } else {
            CP_WAIT0();
        }
        __syncthreads();

        const __half* tA = sA + (c & 1) * GT;
        const __half* tB = sB + (c & 1) * GT;
#pragma unroll
        for (int ks = 0; ks < 2; ++ks) {
            const int k0 = ks * 16;
            uint32_t ah[2][4];
#pragma unroll
            for (int mi = 0; mi < 2; ++mi) {
                int base = (wm + mi * 16 + gID) * kSTR + k0 + tig2;
                ah[mi][0] = *(const uint32_t*)&tA[base];
                ah[mi][1] = *(const uint32_t*)&tA[base + 8 * kSTR];
                ah[mi][2] = *(const uint32_t*)&tA[base + 8];
                ah[mi][3] = *(const uint32_t*)&tA[base + 8 * kSTR + 8];
            }
#pragma unroll
            for (int nt = 0; nt < 8; ++nt) {
                int nb = (wn + nt * 8 + gID) * kSTR + k0 + tig2;
                uint32_t bh0 = *(const uint32_t*)&tB[nb];
                uint32_t bh1 = *(const uint32_t*)&tB[nb + 8];
                mma16816(acc[0][nt], ah[0], bh0, bh1);
                mma16816(acc[1][nt], ah[1], bh0, bh1);
            }
        }
        __syncthreads();
    }

#pragma unroll
    for (int mi = 0; mi < 2; ++mi) {
#pragma unroll
        for (int nt = 0; nt < 8; ++nt) {
            int m = m0 + wm + mi * 16 + gID;
            int n = n0 + wn + nt * 8 + tig2;
            float b0 = bias[n], b1 = bias[n + 1];
            float v0 = acc[mi][nt][0] + b0;
            float v1 = acc[mi][nt][1] + b1;
            float v2 = acc[mi][nt][2] + b0;
            float v3 = acc[mi][nt][3] + b1;
            if (mode == 0) {
                *(float2*)&C[(size_t)m * N + n] = make_float2(v0, v1);
                *(float2*)&C[(size_t)(m + 8) * N + n] = make_float2(v2, v3);
            } else {
                int sec = n >> 10;
                int e = n & 1023;
                int h = e >> 6;
                int d = e & 63;
#pragma unroll
                for (int rr = 0; rr < 2; ++rr) {
                    int mm = m + rr * 8;
                    int bb = mm >> 10;
                    int s = mm & 1023;
                    size_t idx = (((size_t)(bb * kH + h)) * kS + s) * kHD + d;
                    float p0 = rr ? v2 : v0, p1 = rr ? v3 : v1;
                    if (sec == 0) {
                        *(uint32_t*)&g_qh[idx] = packround(p0, p1);
                    } else if (sec == 1) {
                        *(float2*)&kout[idx] = make_float2(p0, p1);
                        *(uint32_t*)&g_kh[idx] = packround(p0, p1);
                    } else {
                        *(float2*)&vout[idx] = make_float2(p0, p1);
                    }
                }
            }
        }
    }
}

// ---------------------------------------------------------------------------
// OV kernel (batch-shared, bit-packed mask; unchanged from R12)
// ---------------------------------------------------------------------------
__global__ __launch_bounds__(256, 2) void ov_kernel(
    const float* __restrict__ ov, float* __restrict__ out)
{
    extern __shared__ __half sV[];
    const int tid = threadIdx.x, lane = tid & 31, wid = tid >> 5;
    const int gID = lane >> 2, tig2 = (lane & 3) * 2;
    const int h = blockIdx.y, q0 = blockIdx.x * 64;
    const int qsub = wid & 3;
    const int dhalf = wid >> 2;
    const int qr0 = q0 + qsub * 16 + gID, qr1 = qr0 + 8;
    const size_t mr0 = ((size_t)h * kS + qr0) * kS;
    const size_t mr1 = ((size_t)h * kS + qr1) * kS;
    const size_t wb0 = ((size_t)h * kS + qr0) * 32;
    const size_t wb1 = ((size_t)h * kS + qr1) * 32;

    float o[4][4][4] = {};

    for (int kc = 0; kc < 8; ++kc) {
#pragma unroll
        for (int bb = 0; bb < 4; ++bb) {
            const size_t bhT = (size_t)(bb * kH + h) * kHD;
#pragma unroll
            for (int it = 0; it < 2; ++it) {
                int unit = tid + it * 256;
                int row = unit >> 3, u = (unit & 7) * 16;
                *(float4*)&sV[bb * OV_VT + row * 136 + u] =
                    *(const float4*)&g_vth[(bhT + row) * kS + kc * 128 + u];
                *(float4*)&sV[bb * OV_VT + row * 136 + u + 8] =
                    *(const float4*)&g_vth[(bhT + row) * kS + kc * 128 + u + 8];
            }
        }
        __syncthreads();

        uint32_t w0[4], w1[4];
#pragma unroll
        for (int j = 0; j < 4; ++j) {
            w0[j] = g_mpack[wb0 + kc * 4 + j];
            w1[j] = g_mpack[wb1 + kc * 4 + j];
        }

#pragma unroll
        for (int ks = 0; ks < 8; ++ks) {
            size_t kg = (size_t)kc * 128 + ks * 16 + tig2;
            int wd = ks >> 1;
            int bp = (ks & 1) * 16 + tig2;
            float2 v00 = *(const float2*)&ov[mr0 + kg];
            float2 v02 = *(const float2*)&ov[mr0 + kg + 8];
            float2 v10 = *(const float2*)&ov[mr1 + kg];
            float2 v12 = *(const float2*)&ov[mr1 + kg + 8];
            uint32_t ah[4];
            ah[0] = packround(((w0[wd] >> bp) & 1) ? v00.x : 0.f,
                              ((w0[wd] >> (bp + 1)) & 1) ? v00.y : 0.f);
            ah[1] = packround(((w1[wd] >> bp) & 1) ? v10.x : 0.f,
                              ((w1[wd] >> (bp + 1)) & 1) ? v10.y : 0.f);
            ah[2] = packround(((w0[wd] >> (bp + 8)) & 1) ? v02.x : 0.f,
                              ((w0[wd] >> (bp + 9)) & 1) ? v02.y : 0.f);
            ah[3] = packround(((w1[wd] >> (bp + 8)) & 1) ? v12.x : 0.f,
                              ((w1[wd] >> (bp + 9)) & 1) ? v12.y : 0.f);
#pragma unroll
            for (int bb = 0; bb < 4; ++bb)
#pragma unroll
                for (int dn = 0; dn < 4; ++dn) {
                    int vb = bb * OV_VT +
                             (dhalf * 32 + dn * 8 + gID) * 136 + ks * 16 + tig2;
                    uint32_t b0 = *(const uint32_t*)&sV[vb];
                    uint32_t b1 = *(const uint32_t*)&sV[vb + 8];
                    mma16816(o[bb][dn], ah, b0, b1);
                }
        }
        __syncthreads();
    }

#pragma unroll
    for (int bb = 0; bb < 4; ++bb)
#pragma unroll
        for (int dn = 0; dn < 4; ++dn) {
            int d = h * kHD + dhalf * 32 + dn * 8 + tig2;
            *(float2*)&out[(size_t)(bb * kS + qr0) * kD + d] =
                make_float2(o[bb][dn][0], o[bb][dn][1]);
            *(float2*)&out[(size_t)(bb * kS + qr1) * kD + d] =
                make_float2(o[bb][dn][2], o[bb][dn][3]);
        }
}

// ---------------------------------------------------------------------------
// Flash kernel: 1-product QK^T; K+V double-buffered via cp.async; heavy-first
// q-tile order; writes fp16 a directly.
// ---------------------------------------------------------------------------
__global__ __launch_bounds__(256, 2) void flash_kernel(
    const float* __restrict__ aio)
{
    extern __shared__ __half fsm[];
    __half* sK = fsm;              // [2][128][72]
    __half* sV = fsm + F_V0;       // [2][64][136]

    const int tid = threadIdx.x, lane = tid & 31, wid = tid >> 5;
    const int gID = lane >> 2, tig2 = (lane & 3) * 2;
    const int b = blockIdx.z, h = blockIdx.y;
    const int qt = (int)gridDim.x - 1 - (int)blockIdx.x;  // heavy-first
    const int q0 = qt * 128;
    const int wq = wid * 16;
    const size_t bh = (size_t)(b * kH + h) * kS * kHD;
    const size_t bhT = (size_t)(b * kH + h) * kHD;
    const uint32_t sbK = smem_u32(sK);
    const uint32_t sbV = smem_u32(sV);

    auto stageKV = [&](int c, int buf) {
#pragma unroll
        for (int it = 0; it < 4; ++it) {          // K: 128 rows x 8 x 16B
            int unit = tid + it * 256;
            int row = unit >> 3, u = unit & 7;
            uint32_t so = (uint32_t)(row * 144 + u * 16) + buf * (F_KT * 2);
            CP_ASYNC16(sbK + so,
                       g_kh + bh + (size_t)(c * 128 + row) * kHD + u * 8);
        }
#pragma unroll
        for (int it = 0; it < 4; ++it) {          // V: 64 rows x 16 x 16B
            int unit = tid + it * 256;
            int row = unit >> 4, u16 = unit & 15;
            uint32_t so = (uint32_t)(row * 272 + u16 * 16) + buf * (F_VT * 2);
            CP_ASYNC16(sbV + so,
                       g_vth + (bhT + row) * kS + (size_t)c * 128 + u16 * 8);
        }
        CP_COMMIT();
    };

    // stage Q synchronously (borrow K buffer 0), grab fragments
#pragma unroll
    for (int it = 0; it < 4; ++it) {
        int unit = tid + it * 256;
        int row = unit >> 3, u = (unit & 7) * 8;
        *(float4*)&sK[row * 72 + u] =
            *(const float4*)&g_qh[bh + (size_t)(q0 + row) * kHD + u];
    }
    __syncthreads();
    uint32_t qf[4][4];
#pragma unroll
    for (int ks = 0; ks < 4; ++ks) {
        int base = (wq + gID) * 72 + ks * 16 + tig2;
        qf[ks][0] = *(const uint32_t*)&sK[base];
        qf[ks][1] = *(const uint32_t*)&sK[base + 8 * 72];
        qf[ks][2] = *(const uint32_t*)&sK[base + 8];
        qf[ks][3] = *(const uint32_t*)&sK[base + 8 * 72 + 8];
    }
    __syncthreads();

    stageKV(0, 0);

    float o[8][4] = {};
    float Z0 = 0.f, Z1 = 0.f;
    const int qr0 = q0 + wq + gID, qr1 = qr0 + 8;
    const size_t wb0 = ((size_t)h * kS + qr0) * 32;
    const size_t wb1 = ((size_t)h * kS + qr1) * 32;

    for (int kc = 0; kc <= qt; ++kc) {
        if (kc + 1 <= qt) {
            stageKV(kc + 1, (kc + 1) & 1);
            CP_WAIT1();
        } else {
            CP_WAIT0();
        }
        __syncthreads();

        const __half* tK = sK + (kc & 1) * F_KT;
        const __half* tV = sV + (kc & 1) * F_VT;

        for (int qq = 0; qq < 4; ++qq) {
            float sa[4][4] = {};
#pragma unroll
            for (int ks = 0; ks < 4; ++ks)
#pragma unroll
                for (int nt = 0; nt < 4; ++nt) {
                    int kb = (qq * 32 + nt * 8 + gID) * 72 + ks * 16 + tig2;
                    uint32_t b0 = *(const uint32_t*)&tK[kb];
                    uint32_t b1 = *(const uint32_t*)&tK[kb + 8];
                    mma16816(sa[nt], qf[ks], b0, b1);
                }

            uint32_t mw0 = g_mpack[wb0 + kc * 4 + qq];
            uint32_t mw1 = g_mpack[wb1 + kc * 4 + qq];
            uint32_t ehr0[4], ehr1[4];
#pragma unroll
            for (int nt = 0; nt < 4; ++nt) {
                int kg = kc * 128 + qq * 32 + nt * 8 + tig2;
                int bp = nt * 8 + tig2;
                float e00 = (kg     <= qr0) ? __expf(sa[nt][0] * 0.125f) : 0.f;
                float e01 = (kg + 1 <= qr0) ? __expf(sa[nt][1] * 0.125f) : 0.f;
                float e10 = (kg     <= qr1) ? __expf(sa[nt][2] * 0.125f) : 0.f;
                float e11 = (kg + 1 <= qr1) ? __expf(sa[nt][3] * 0.125f) : 0.f;
                Z0 += e00 + e01;
                Z1 += e10 + e11;
                if ((mw0 >> bp) & 1) e00 = 0.f;
                if ((mw0 >> (bp + 1)) & 1) e01 = 0.f;
                if ((mw1 >> bp) & 1) e10 = 0.f;
                if ((mw1 >> (bp + 1)) & 1) e11 = 0.f;
                ehr0[nt] = packround(e00, e01);
                ehr1[nt] = packround(e10, e11);
            }
#pragma unroll
            for (int k2 = 0; k2 < 2; ++k2) {
                uint32_t ah[4] = {ehr0[2 * k2], ehr1[2 * k2],
                                  ehr0[2 * k2 + 1], ehr1[2 * k2 + 1]};
#pragma unroll
                for (int dn = 0; dn < 8; ++dn) {
                    int vb = (dn * 8 + gID) * 136 + qq * 32 + k2 * 16 + tig2;
                    uint32_t b0 = *(const uint32_t*)&tV[vb];
                    uint32_t b1 = *(const uint32_t*)&tV[vb + 8];
                    mma16816(o[dn], ah, b0, b1);
                }
            }
        }
        __syncthreads();
    }

    Z0 += __shfl_xor_sync(0xffffffffu, Z0, 1);
    Z0 += __shfl_xor_sync(0xffffffffu, Z0, 2);
    Z1 += __shfl_xor_sync(0xffffffffu, Z1, 1);
    Z1 += __shfl_xor_sync(0xffffffffu, Z1, 2);
    float i0 = 1.f / Z0, i1 = 1.f / Z1;

#pragma unroll
    for (int dn = 0; dn < 8; ++dn) {
        int d = h * kHD + dn * 8 + tig2;
        size_t r0 = (size_t)(b * kS + qr0) * kD + d;
        size_t r1 = (size_t)(b * kS + qr1) * kD + d;
        float2 p0 = *(const float2*)&aio[r0];
        float2 p1 = *(const float2*)&aio[r1];
        *(uint32_t*)&g_ah[r0] =
            packround(p0.x + o[dn][0] * i0, p0.y + o[dn][1] * i0);
        *(uint32_t*)&g_ah[r1] =
            packround(p1.x + o[dn][2] * i1, p1.y + o[dn][3] * i1);
    }
}

// ---------------------------------------------------------------------------
extern "C" void kernel_launch(void* const* d_in, const int* in_sizes, int n_in,
                              void* d_out, int out_size)
{
    const float* x       = (const float*)d_in[0];
    const float* w_attn  = (const float*)d_in[1];
    const float* b_attn  = (const float*)d_in[2];
    const float* w_proj  = (const float*)d_in[3];
    const float* b_proj  = (const float*)d_in[4];
    const float* ov      = (const float*)d_in[5];
    const void*  msk     = (const void*)d_in[6];

    float* out = (float*)d_out;
    float* presentK = out + (size_t)kM * kD;
    float* presentV = presentK + (size_t)kB * kH * kS * kHD;

    float* aptr = nullptr;
    __half *xh, *ah, *wth, *pth;
    cudaGetSymbolAddress((void**)&aptr, g_a);
    cudaGetSymbolAddress((void**)&xh, g_xh);
    cudaGetSymbolAddress((void**)&ah, g_ah);
    cudaGetSymbolAddress((void**)&wth, g_wth);
    cudaGetSymbolAddress((void**)&pth, g_pth);

    cudaFuncSetAttribute(flash_kernel,
                         cudaFuncAttributeMaxDynamicSharedMemorySize,
                         FLASH_SMEM_BYTES);
    cudaFuncSetAttribute(ov_kernel,
                         cudaFuncAttributeMaxDynamicSharedMemorySize,
                         OV_SMEM_BYTES);

    // 0) mask classification + bit-pack + operand prep
    detect_mask_kind_kernel<<<1, 256>>>((const unsigned int*)msk);
    pack_mask_kernel<<<(kH * kS * kS) / 256, 256>>>(msk);
    round_kernel<<<kM * kD / 256, 256>>>(x, xh, kM * kD);
    transpose_h_kernel<<<dim3(3 * kD / 32, kD / 32), dim3(32, 8)>>>(
        w_attn, wth, kD, 3 * kD);
    transpose_h_kernel<<<dim3(kD / 32, kD / 32), dim3(32, 8)>>>(
        w_proj, pth, kD, kD);

    // 1) QKV GEMM -> present fp32 + q/k fp16
    mma_gemm_kernel<<<dim3(3 * kD / 128, kM / 128), 256>>>(
        xh, wth, b_attn, nullptr, kM, 3 * kD, kD, 1, presentK, presentV);

    // 2) V transpose -> g_vth
    vtrans_kernel<<<dim3(kHD / 32, kS / 32, kB * kH), dim3(32, 8)>>>(presentV);

    // 3) override term -> g_a (batch-shared)
    ov_kernel<<<dim3(kS / 64, kH), 256, OV_SMEM_BYTES>>>(ov, aptr);

    // 4) flash: adds softmax term, writes fp16 a directly
    flash_kernel<<<dim3(kS / 128, kH, kB), 256, FLASH_SMEM_BYTES>>>(aptr);

    // 5) output projection
    mma_gemm_kernel<<<dim3(kD / 128, kM / 128), 256>>>(
        ah, pth, b_proj, out, kM, kD, kD, 0, nullptr, nullptr);
}

// round 14
// speedup vs baseline: 4.0545x; 1.0869x over previous
#include <cuda_runtime.h>
#include <cuda_fp16.h>
#include <cstdint>

// ---------------------------------------------------------------------------
// AttentionOverride, round 14: R13 + ldmatrix.x4 fragment loads everywhere
// (GEMM A/B, flash K/V, ov V) + vtrans fused into the QKV epilogue.
// Math bit-identical to R13 -> rel_err must remain 4.539915e-4.
// Output layout: [ a (4M floats) | presentK (4M) | presentV (4M) ]
// ---------------------------------------------------------------------------

namespace {
constexpr int kB  = 4;
constexpr int kS  = 1024;
constexpr int kD  = 1024;
constexpr int kH  = 16;
constexpr int kHD = 64;
constexpr int kM  = kB * kS;  // 4096

constexpr int kSTR = 40;          // GEMM smem stride (half)
constexpr int GT   = 128 * kSTR;  // one GEMM tile in halves (5120)

// flash smem (half elems): K double buffer [2][128][72], V double [2][64][136]
constexpr int F_KT = 9216;
constexpr int F_VT = 8704;
constexpr int F_V0 = 2 * F_KT;    // 18432
constexpr int FLASH_SMEM_BYTES = (2 * F_KT + 2 * F_VT) * 2;  // 71680

constexpr int OV_VT = 8704;
constexpr int OV_SMEM_BYTES = 4 * OV_VT * 2;   // 69632
}  // namespace

// scratch (device globals; no allocation allowed)
__device__ float g_a[(size_t)kM * kD];          // ov term (fp32)
__device__ int   g_mask_kind;
__device__ uint32_t g_mpack[(size_t)kH * kS * (kS / 32)];
__device__ __half g_qh[(size_t)kM * kD];
__device__ __half g_kh[(size_t)kM * kD];
__device__ __half g_vth[(size_t)kM * kD];       // [BH][64][S]
__device__ __half g_xh[(size_t)kM * kD];
__device__ __half g_ah[(size_t)kM * kD];        // a (fp16) for proj
__device__ __half g_wth[(size_t)3 * kD * kD];
__device__ __half g_pth[(size_t)kD * kD];

// ---------------------------------------------------------------------------
__device__ __forceinline__ void mma16816(float* c, const uint32_t* a,
                                         uint32_t b0, uint32_t b1) {
    asm volatile(
        "mma.sync.aligned.m16n8k16.row.col.f32.f16.f16.f32 "
        "{%0,%1,%2,%3}, {%4,%5,%6,%7}, {%8,%9}, {%0,%1,%2,%3};"
        : "+f"(c[0]), "+f"(c[1]), "+f"(c[2]), "+f"(c[3])
        : "r"(a[0]), "r"(a[1]), "r"(a[2]), "r"(a[3]), "r"(b0), "r"(b1));
}

__device__ __forceinline__ void ldsm_x4(uint32_t& r0, uint32_t& r1,
                                        uint32_t& r2, uint32_t& r3,
                                        uint32_t saddr) {
    asm volatile(
        "ldmatrix.sync.aligned.m8n8.x4.shared.b16 {%0,%1,%2,%3}, [%4];"
        : "=r"(r0), "=r"(r1), "=r"(r2), "=r"(r3) : "r"(saddr));
}

#define CP_ASYNC16(saddr, gptr)                                          \
    asm volatile("cp.async.cg.shared.global [%0], [%1], 16;"             \
                 :: "r"(saddr), "l"(gptr) : "memory")
#define CP_COMMIT() asm volatile("cp.async.commit_group;" ::: "memory")
#define CP_WAIT0()  asm volatile("cp.async.wait_group 0;" ::: "memory")
#define CP_WAIT1()  asm volatile("cp.async.wait_group 1;" ::: "memory")

__device__ __forceinline__ uint32_t smem_u32(const void* p) {
    return (uint32_t)__cvta_generic_to_shared(p);
}

__device__ __forceinline__ uint32_t packh(__half a, __half b) {
    __half2 t = __halves2half2(a, b);
    return *(uint32_t*)&t;
}
__device__ __forceinline__ uint32_t packround(float x, float y) {
    return packh(__float2half_rn(x), __float2half_rn(y));
}

// ---------------------------------------------------------------------------
__global__ void round_kernel(const float* __restrict__ X,
                             __half* __restrict__ H, int n) {
    int i = blockIdx.x * 256 + threadIdx.x;
    if (i < n) H[i] = __float2half_rn(X[i]);
}

__global__ void transpose_h_kernel(const float* __restrict__ W,
                                   __half* __restrict__ Th, int K, int N) {
    __shared__ float t[32][33];
    int n0 = blockIdx.x * 32, k0 = blockIdx.y * 32;
    int tx = threadIdx.x, ty = threadIdx.y;
#pragma unroll
    for (int j = 0; j < 4; ++j)
        t[ty + j * 8][tx] = W[(size_t)(k0 + ty + j * 8) * N + n0 + tx];
    __syncthreads();
#pragma unroll
    for (int j = 0; j < 4; ++j)
        Th[(size_t)(n0 + ty + j * 8) * K + k0 + tx] =
            __float2half_rn(t[tx][ty + j * 8]);
}

__global__ void detect_mask_kind_kernel(const unsigned int* __restrict__ m) {
    __shared__ int any_gt1, any_not_f32;
    if (threadIdx.x == 0) { any_gt1 = 0; any_not_f32 = 0; }
    __syncthreads();
    int gt1 = 0, nf32 = 0;
    for (int i = threadIdx.x; i < 16384; i += 256) {
        unsigned int w = m[i];
        if (w > 1u) gt1 = 1;
        if (w != 0u && w != 0x3F800000u) nf32 = 1;
    }
    if (gt1)  atomicOr(&any_gt1, 1);
    if (nf32) atomicOr(&any_not_f32, 1);
    __syncthreads();
    if (threadIdx.x == 0)
        g_mask_kind = (!any_gt1) ? 1 : ((!any_not_f32) ? 2 : 0);
}

__global__ void pack_mask_kernel(const void* __restrict__ m) {
    size_t i = (size_t)blockIdx.x * 256 + threadIdx.x;
    const int kind = g_mask_kind;
    bool v;
    if (kind == 0) v = ((const unsigned char*)m)[i] != 0;
    else           v = ((const unsigned int*)m)[i] != 0;
    unsigned int w = __ballot_sync(0xffffffffu, v);
    if ((threadIdx.x & 31) == 0) g_mpack[i >> 5] = w;
}

// ---------------------------------------------------------------------------
// HMMA GEMM, fp16 1-product, cp.async double-buffered, ldmatrix fragments.
// mode 1 epilogue also writes V transposed (vtrans fused).
// ---------------------------------------------------------------------------
__global__ __launch_bounds__(256, 2) void mma_gemm_kernel(
    const __half* __restrict__ Ah, const __half* __restrict__ Bh,
    const float* __restrict__ bias, float* __restrict__ C,
    int M, int N, int K, int mode,
    float* __restrict__ kout, float* __restrict__ vout)
{
    __shared__ __half sA[2 * GT], sB[2 * GT];

    const int tid = threadIdx.x;
    const int lane = tid & 31;
    const int wid = tid >> 5;
    const int wm = (wid & 3) * 32;
    const int wn = (wid >> 2) * 64;
    const int m0 = blockIdx.y * 128;
    const int n0 = blockIdx.x * 128;
    const int gID = lane >> 2;
    const int tig2 = (lane & 3) * 2;
    const int lt = lane >> 3;   // ldmatrix tile index 0..3
    const int lr = lane & 7;    // ldmatrix row within tile

    const uint32_t sbA = smem_u32(sA);
    const uint32_t sbB = smem_u32(sB);

    const int rr0 = tid >> 2;
    const int uu0 = tid & 3;
    const int rr1 = (tid + 256) >> 2;
    const int uu1 = (tid + 256) & 3;

    auto stage = [&](int c, int buf) {
        size_t ka = (size_t)c * 32;
        uint32_t so0 = (uint32_t)(rr0 * 80 + uu0 * 16) + buf * (GT * 2);
        uint32_t so1 = (uint32_t)(rr1 * 80 + uu1 * 16) + buf * (GT * 2);
        CP_ASYNC16(sbA + so0, Ah + (size_t)(m0 + rr0) * K + ka + uu0 * 8);
        CP_ASYNC16(sbA + so1, Ah + (size_t)(m0 + rr1) * K + ka + uu1 * 8);
        CP_ASYNC16(sbB + so0, Bh + (size_t)(n0 + rr0) * K + ka + uu0 * 8);
        CP_ASYNC16(sbB + so1, Bh + (size_t)(n0 + rr1) * K + ka + uu1 * 8);
        CP_COMMIT();
    };

    float acc[2][8][4] = {};
    const int nchunks = K / 32;

    stage(0, 0);
    for (int c = 0; c < nchunks; ++c) {
        if (c + 1 < nchunks) {
            stage(c + 1, (c + 1) & 1);
            CP_WAIT1();
        } else {
            CP_WAIT0();
        }
        __syncthreads();

        const uint32_t tAb = sbA + (c & 1) * (GT * 2);
        const uint32_t tBb = sbB + (c & 1) * (GT * 2);
#pragma unroll
        for (int ks = 0; ks < 2; ++ks) {
            const int k0 = ks * 16;
            uint32_t ah[2][4];
#pragma unroll
            for (int mi = 0; mi < 2; ++mi) {
                uint32_t addr = tAb + (uint32_t)(
                    ((wm + mi * 16 + (lt & 1) * 8 + lr) * kSTR +
                     k0 + (lt >> 1) * 8) * 2);
                ldsm_x4(ah[mi][0], ah[mi][1], ah[mi][2], ah[mi][3], addr);
            }
#pragma unroll
            for (int ntp = 0; ntp < 4; ++ntp) {
                uint32_t addr = tBb + (uint32_t)(
                    ((wn + ntp * 16 + (lt >> 1) * 8 + lr) * kSTR +
                     k0 + (lt & 1) * 8) * 2);
                uint32_t b00, b01, b10, b11;
                ldsm_x4(b00, b01, b10, b11, addr);
                mma16816(acc[0][2 * ntp],     ah[0], b00, b01);
                mma16816(acc[1][2 * ntp],     ah[1], b00, b01);
                mma16816(acc[0][2 * ntp + 1], ah[0], b10, b11);
                mma16816(acc[1][2 * ntp + 1], ah[1], b10, b11);
            }
        }
        __syncthreads();
    }

#pragma unroll
    for (int mi = 0; mi < 2; ++mi) {
#pragma unroll
        for (int nt = 0; nt < 8; ++nt) {
            int m = m0 + wm + mi * 16 + gID;
            int n = n0 + wn + nt * 8 + tig2;
            float b0 = bias[n], b1 = bias[n + 1];
            float v0 = acc[mi][nt][0] + b0;
            float v1 = acc[mi][nt][1] + b1;
            float v2 = acc[mi][nt][2] + b0;
            float v3 = acc[mi][nt][3] + b1;
            if (mode == 0) {
                *(float2*)&C[(size_t)m * N + n] = make_float2(v0, v1);
                *(float2*)&C[(size_t)(m + 8) * N + n] = make_float2(v2, v3);
            } else {
                int sec = n >> 10;
                int e = n & 1023;
                int h = e >> 6;
                int d = e & 63;
#pragma unroll
                for (int rr = 0; rr < 2; ++rr) {
                    int mm = m + rr * 8;
                    int bb = mm >> 10;
                    int s = mm & 1023;
                    size_t idx = (((size_t)(bb * kH + h)) * kS + s) * kHD + d;
                    float p0 = rr ? v2 : v0, p1 = rr ? v3 : v1;
                    if (sec == 0) {
                        *(uint32_t*)&g_qh[idx] = packround(p0, p1);
                    } else if (sec == 1) {
                        *(float2*)&kout[idx] = make_float2(p0, p1);
                        *(uint32_t*)&g_kh[idx] = packround(p0, p1);
                    } else {
                        *(float2*)&vout[idx] = make_float2(p0, p1);
                        // fused vtrans: g_vth[(bh*64 + d)*S + s]
                        size_t tb = ((size_t)(bb * kH + h) * kHD + d) * kS + s;
                        g_vth[tb] = __float2half_rn(p0);
                        g_vth[tb + kS] = __float2half_rn(p1);
                    }
                }
            }
        }
    }
}

// ---------------------------------------------------------------------------
// OV kernel (batch-shared, bit-packed mask, ldmatrix V fragments)
// ---------------------------------------------------------------------------
__global__ __launch_bounds__(256, 2) void ov_kernel(
    const float* __restrict__ ov, float* __restrict__ out)
{
    extern __shared__ __half sV[];
    const int tid = threadIdx.x, lane = tid & 31, wid = tid >> 5;
    const int gID = lane >> 2, tig2 = (lane & 3) * 2;
    const int lt = lane >> 3, lr = lane & 7;
    const int h = blockIdx.y, q0 = blockIdx.x * 64;
    const int qsub = wid & 3;
    const int dhalf = wid >> 2;
    const int qr0 = q0 + qsub * 16 + gID, qr1 = qr0 + 8;
    const size_t mr0 = ((size_t)h * kS + qr0) * kS;
    const size_t mr1 = ((size_t)h * kS + qr1) * kS;
    const size_t wb0 = ((size_t)h * kS + qr0) * 32;
    const size_t wb1 = ((size_t)h * kS + qr1) * 32;
    const uint32_t sbV = smem_u32(sV);

    float o[4][4][4] = {};

    for (int kc = 0; kc < 8; ++kc) {
#pragma unroll
        for (int bb = 0; bb < 4; ++bb) {
            const size_t bhT = (size_t)(bb * kH + h) * kHD;
#pragma unroll
            for (int it = 0; it < 2; ++it) {
                int unit = tid + it * 256;
                int row = unit >> 3, u = (unit & 7) * 16;
                *(float4*)&sV[bb * OV_VT + row * 136 + u] =
                    *(const float4*)&g_vth[(bhT + row) * kS + kc * 128 + u];
                *(float4*)&sV[bb * OV_VT + row * 136 + u + 8] =
                    *(const float4*)&g_vth[(bhT + row) * kS + kc * 128 + u + 8];
            }
        }
        __syncthreads();

        uint32_t w0[4], w1[4];
#pragma unroll
        for (int j = 0; j < 4; ++j) {
            w0[j] = g_mpack[wb0 + kc * 4 + j];
            w1[j] = g_mpack[wb1 + kc * 4 + j];
        }

#pragma unroll
        for (int ks = 0; ks < 8; ++ks) {
            size_t kg = (size_t)kc * 128 + ks * 16 + tig2;
            int wd = ks >> 1;
            int bp = (ks & 1) * 16 + tig2;
            float2 v00 = *(const float2*)&ov[mr0 + kg];
            float2 v02 = *(const float2*)&ov[mr0 + kg + 8];
            float2 v10 = *(const float2*)&ov[mr1 + kg];
            float2 v12 = *(const float2*)&ov[mr1 + kg + 8];
            uint32_t ah[4];
            ah[0] = packround(((w0[wd] >> bp) & 1) ? v00.x : 0.f,
                              ((w0[wd] >> (bp + 1)) & 1) ? v00.y : 0.f);
            ah[1] = packround(((w1[wd] >> bp) & 1) ? v10.x : 0.f,
                              ((w1[wd] >> (bp + 1)) & 1) ? v10.y : 0.f);
            ah[2] = packround(((w0[wd] >> (bp + 8)) & 1) ? v02.x : 0.f,
                              ((w0[wd] >> (bp + 9)) & 1) ? v02.y : 0.f);
            ah[3] = packround(((w1[wd] >> (bp + 8)) & 1) ? v12.x : 0.f,
                              ((w1[wd] >> (bp + 9)) & 1) ? v12.y : 0.f);
#pragma unroll
            for (int bb = 0; bb < 4; ++bb)
#pragma unroll
                for (int dnp = 0; dnp < 2; ++dnp) {
                    uint32_t addr = sbV + (uint32_t)((bb * OV_VT +
                        (dhalf * 32 + dnp * 16 + (lt >> 1) * 8 + lr) * 136 +
                        ks * 16 + (lt & 1) * 8) * 2);
                    uint32_t b00, b01, b10, b11;
                    ldsm_x4(b00, b01, b10, b11, addr);
                    mma16816(o[bb][2 * dnp],     ah, b00, b01);
                    mma16816(o[bb][2 * dnp + 1], ah, b10, b11);
                }
        }
        __syncthreads();
    }

#pragma unroll
    for (int bb = 0; bb < 4; ++bb)
#pragma unroll
        for (int dn = 0; dn < 4; ++dn) {
            int d = h * kHD + dhalf * 32 + dn * 8 + tig2;
            *(float2*)&out[(size_t)(bb * kS + qr0) * kD + d] =
                make_float2(o[bb][dn][0], o[bb][dn][1]);
            *(float2*)&out[(size_t)(bb * kS + qr1) * kD + d] =
                make_float2(o[bb][dn][2], o[bb][dn][3]);
        }
}

// ---------------------------------------------------------------------------
// Flash kernel: 1-product QK^T; K+V double-buffered; ldmatrix fragments;
// heavy-first q-tile order; writes fp16 a directly.
// ---------------------------------------------------------------------------
__global__ __launch_bounds__(256, 2) void flash_kernel(
    const float* __restrict__ aio)
{
    extern __shared__ __half fsm[];
    __half* sK = fsm;              // [2][128][72]
    __half* sV = fsm + F_V0;       // [2][64][136]

    const int tid = threadIdx.x, lane = tid & 31, wid = tid >> 5;
    const int gID = lane >> 2, tig2 = (lane & 3) * 2;
    const int lt = lane >> 3, lr = lane & 7;
    const int b = blockIdx.z, h = blockIdx.y;
    const int qt = (int)gridDim.x - 1 - (int)blockIdx.x;
    const int q0 = qt * 128;
    const int wq = wid * 16;
    const size_t bh = (size_t)(b * kH + h) * kS * kHD;
    const size_t bhT = (size_t)(b * kH + h) * kHD;
    const uint32_t sbK = smem_u32(sK);
    const uint32_t sbV = smem_u32(sV);

    auto stageKV = [&](int c, int buf) {
#pragma unroll
        for (int it = 0; it < 4; ++it) {
            int unit = tid + it * 256;
            int row = unit >> 3, u = unit & 7;
            uint32_t so = (uint32_t)(row * 144 + u * 16) + buf * (F_KT * 2);
            CP_ASYNC16(sbK + so,
                       g_kh + bh + (size_t)(c * 128 + row) * kHD + u * 8);
        }
#pragma unroll
        for (int it = 0; it < 4; ++it) {
            int unit = tid + it * 256;
            int row = unit >> 4, u16 = unit & 15;
            uint32_t so = (uint32_t)(row * 272 + u16 * 16) + buf * (F_VT * 2);
            CP_ASYNC16(sbV + so,
                       g_vth + (bhT + row) * kS + (size_t)c * 128 + u16 * 8);
        }
        CP_COMMIT();
    };

    // stage Q synchronously (borrow K buffer 0), grab fragments (ldmatrix)
#pragma unroll
    for (int it = 0; it < 4; ++it) {
        int unit = tid + it * 256;
        int row = unit >> 3, u = (unit & 7) * 8;
        *(float4*)&sK[row * 72 + u] =
            *(const float4*)&g_qh[bh + (size_t)(q0 + row) * kHD + u];
    }
    __syncthreads();
    uint32_t qf[4][4];
#pragma unroll
    for (int ks = 0; ks < 4; ++ks) {
        uint32_t addr = sbK + (uint32_t)(
            ((wq + (lt & 1) * 8 + lr) * 72 + ks * 16 + (lt >> 1) * 8) * 2);
        ldsm_x4(qf[ks][0], qf[ks][1], qf[ks][2], qf[ks][3], addr);
    }
    __syncthreads();

    stageKV(0, 0);

    float o[8][4] = {};
    float Z0 = 0.f, Z1 = 0.f;
    const int qr0 = q0 + wq + gID, qr1 = qr0 + 8;
    const size_t wb0 = ((size_t)h * kS + qr0) * 32;
    const size_t wb1 = ((size_t)h * kS + qr1) * 32;

    for (int kc = 0; kc <= qt; ++kc) {
        if (kc + 1 <= qt) {
            stageKV(kc + 1, (kc + 1) & 1);
            CP_WAIT1();
        } else {
            CP_WAIT0();
        }
        __syncthreads();

        const uint32_t tKb = sbK + (kc & 1) * (F_KT * 2);
        const uint32_t tVb = sbV + (kc & 1) * (F_VT * 2);

        for (int qq = 0; qq < 4; ++qq) {
            float sa[4][4] = {};
#pragma unroll
            for (int ks = 0; ks < 4; ++ks)
#pragma unroll
                for (int ntp = 0; ntp < 2; ++ntp) {
                    uint32_t addr = tKb + (uint32_t)(
                        ((qq * 32 + ntp * 16 + (lt >> 1) * 8 + lr) * 72 +
                         ks * 16 + (lt & 1) * 8) * 2);
                    uint32_t b00, b01, b10, b11;
                    ldsm_x4(b00, b01, b10, b11, addr);
                    mma16816(sa[2 * ntp],     qf[ks], b00, b01);
                    mma16816(sa[2 * ntp + 1], qf[ks], b10, b11);
                }

            uint32_t mw0 = g_mpack[wb0 + kc * 4 + qq];
            uint32_t mw1 = g_mpack[wb1 + kc * 4 + qq];
            uint32_t ehr0[4], ehr1[4];
#pragma unroll
            for (int nt = 0; nt < 4; ++nt) {
                int kg = kc * 128 + qq * 32 + nt * 8 + tig2;
                int bp = nt * 8 + tig2;
                float e00 = (kg     <= qr0) ? __expf(sa[nt][0] * 0.125f) : 0.f;
                float e01 = (kg + 1 <= qr0) ? __expf(sa[nt][1] * 0.125f) : 0.f;
                float e10 = (kg     <= qr1) ? __expf(sa[nt][2] * 0.125f) : 0.f;
                float e11 = (kg + 1 <= qr1) ? __expf(sa[nt][3] * 0.125f) : 0.f;
                Z0 += e00 + e01;
                Z1 += e10 + e11;
                if ((mw0 >> bp) & 1) e00 = 0.f;
                if ((mw0 >> (bp + 1)) & 1) e01 = 0.f;
                if ((mw1 >> bp) & 1) e10 = 0.f;
                if ((mw1 >> (bp + 1)) & 1) e11 = 0.f;
                ehr0[nt] = packround(e00, e01);
                ehr1[nt] = packround(e10, e11);
            }
#pragma unroll
            for (int k2 = 0; k2 < 2; ++k2) {
                uint32_t ah[4] = {ehr0[2 * k2], ehr1[2 * k2],
                                  ehr0[2 * k2 + 1], ehr1[2 * k2 + 1]};
#pragma unroll
                for (int dnp = 0; dnp < 4; ++dnp) {
                    uint32_t addr = tVb + (uint32_t)(
                        ((dnp * 16 + (lt >> 1) * 8 + lr) * 136 +
                         qq * 32 + k2 * 16 + (lt & 1) * 8) * 2);
                    uint32_t b00, b01, b10, b11;
                    ldsm_x4(b00, b01, b10, b11, addr);
                    mma16816(o[2 * dnp],     ah, b00, b01);
                    mma16816(o[2 * dnp + 1], ah, b10, b11);
                }
            }
        }
        __syncthreads();
    }

    Z0 += __shfl_xor_sync(0xffffffffu, Z0, 1);
    Z0 += __shfl_xor_sync(0xffffffffu, Z0, 2);
    Z1 += __shfl_xor_sync(0xffffffffu, Z1, 1);
    Z1 += __shfl_xor_sync(0xffffffffu, Z1, 2);
    float i0 = 1.f / Z0, i1 = 1.f / Z1;

#pragma unroll
    for (int dn = 0; dn < 8; ++dn) {
        int d = h * kHD + dn * 8 + tig2;
        size_t r0 = (size_t)(b * kS + qr0) * kD + d;
        size_t r1 = (size_t)(b * kS + qr1) * kD + d;
        float2 p0 = *(const float2*)&aio[r0];
        float2 p1 = *(const float2*)&aio[r1];
        *(uint32_t*)&g_ah[r0] =
            packround(p0.x + o[dn][0] * i0, p0.y + o[dn][1] * i0);
        *(uint32_t*)&g_ah[r1] =
            packround(p1.x + o[dn][2] * i1, p1.y + o[dn][3] * i1);
    }
}

// ---------------------------------------------------------------------------
extern "C" void kernel_launch(void* const* d_in, const int* in_sizes, int n_in,
                              void* d_out, int out_size)
{
    const float* x       = (const float*)d_in[0];
    const float* w_attn  = (const float*)d_in[1];
    const float* b_attn  = (const float*)d_in[2];
    const float* w_proj  = (const float*)d_in[3];
    const float* b_proj  = (const float*)d_in[4];
    const float* ov      = (const float*)d_in[5];
    const void*  msk     = (const void*)d_in[6];

    float* out = (float*)d_out;
    float* presentK = out + (size_t)kM * kD;
    float* presentV = presentK + (size_t)kB * kH * kS * kHD;

    float* aptr = nullptr;
    __half *xh, *ah, *wth, *pth;
    cudaGetSymbolAddress((void**)&aptr, g_a);
    cudaGetSymbolAddress((void**)&xh, g_xh);
    cudaGetSymbolAddress((void**)&ah, g_ah);
    cudaGetSymbolAddress((void**)&wth, g_wth);
    cudaGetSymbolAddress((void**)&pth, g_pth);

    cudaFuncSetAttribute(flash_kernel,
                         cudaFuncAttributeMaxDynamicSharedMemorySize,
                         FLASH_SMEM_BYTES);
    cudaFuncSetAttribute(ov_kernel,
                         cudaFuncAttributeMaxDynamicSharedMemorySize,
                         OV_SMEM_BYTES);

    // 0) mask classification + bit-pack + operand prep
    detect_mask_kind_kernel<<<1, 256>>>((const unsigned int*)msk);
    pack_mask_kernel<<<(kH * kS * kS) / 256, 256>>>(msk);
    round_kernel<<<kM * kD / 256, 256>>>(x, xh, kM * kD);
    transpose_h_kernel<<<dim3(3 * kD / 32, kD / 32), dim3(32, 8)>>>(
        w_attn, wth, kD, 3 * kD);
    transpose_h_kernel<<<dim3(kD / 32, kD / 32), dim3(32, 8)>>>(
        w_proj, pth, kD, kD);

    // 1) QKV GEMM -> present fp32 + q/k fp16 + V transposed fp16 (fused)
    mma_gemm_kernel<<<dim3(3 * kD / 128, kM / 128), 256>>>(
        xh, wth, b_attn, nullptr, kM, 3 * kD, kD, 1, presentK, presentV);

    // 2) override term -> g_a (batch-shared)
    ov_kernel<<<dim3(kS / 64, kH), 256, OV_SMEM_BYTES>>>(ov, aptr);

    // 3) flash: adds softmax term, writes fp16 a directly
    flash_kernel<<<dim3(kS / 128, kH, kB), 256, FLASH_SMEM_BYTES>>>(aptr);

    // 4) output projection
    mma_gemm_kernel<<<dim3(kD / 128, kM / 128), 256>>>(
        ah, pth, b_proj, out, kM, kD, kD, 0, nullptr, nullptr);
}

// round 15
// speedup vs baseline: 4.3816x; 1.0807x over previous
#include <cuda_runtime.h>
#include <cuda_fp16.h>
#include <cstdint>

// ---------------------------------------------------------------------------
// AttentionOverride, round 15: R14 + f16x2 ex2 softmax (half the MUFU ops,
// no packround) + GEMM BK=64 (half the syncs/stages).
// Output layout: [ a (4M floats) | presentK (4M) | presentV (4M) ]
// ---------------------------------------------------------------------------

namespace {
constexpr int kB  = 4;
constexpr int kS  = 1024;
constexpr int kD  = 1024;
constexpr int kH  = 16;
constexpr int kHD = 64;
constexpr int kM  = kB * kS;  // 4096

constexpr int GKSTR = 72;           // GEMM smem stride (half), BK=64
constexpr int GT2   = 128 * GKSTR;  // one GEMM tile in halves (9216)
constexpr int GEMM_SMEM_BYTES = 4 * GT2 * 2;  // 73728

// flash smem (half elems): K double buffer [2][128][72], V double [2][64][136]
constexpr int F_KT = 9216;
constexpr int F_VT = 8704;
constexpr int F_V0 = 2 * F_KT;
constexpr int FLASH_SMEM_BYTES = (2 * F_KT + 2 * F_VT) * 2;  // 71680

constexpr int OV_VT = 8704;
constexpr int OV_SMEM_BYTES = 4 * OV_VT * 2;   // 69632
}  // namespace

// scratch (device globals; no allocation allowed)
__device__ float g_a[(size_t)kM * kD];          // ov term (fp32)
__device__ int   g_mask_kind;
__device__ uint32_t g_mpack[(size_t)kH * kS * (kS / 32)];
__device__ __half g_qh[(size_t)kM * kD];
__device__ __half g_kh[(size_t)kM * kD];
__device__ __half g_vth[(size_t)kM * kD];       // [BH][64][S]
__device__ __half g_xh[(size_t)kM * kD];
__device__ __half g_ah[(size_t)kM * kD];        // a (fp16) for proj
__device__ __half g_wth[(size_t)3 * kD * kD];
__device__ __half g_pth[(size_t)kD * kD];

// ---------------------------------------------------------------------------
__device__ __forceinline__ void mma16816(float* c, const uint32_t* a,
                                         uint32_t b0, uint32_t b1) {
    asm volatile(
        "mma.sync.aligned.m16n8k16.row.col.f32.f16.f16.f32 "
        "{%0,%1,%2,%3}, {%4,%5,%6,%7}, {%8,%9}, {%0,%1,%2,%3};"
        : "+f"(c[0]), "+f"(c[1]), "+f"(c[2]), "+f"(c[3])
        : "r"(a[0]), "r"(a[1]), "r"(a[2]), "r"(a[3]), "r"(b0), "r"(b1));
}

__device__ __forceinline__ void ldsm_x4(uint32_t& r0, uint32_t& r1,
                                        uint32_t& r2, uint32_t& r3,
                                        uint32_t saddr) {
    asm volatile(
        "ldmatrix.sync.aligned.m8n8.x4.shared.b16 {%0,%1,%2,%3}, [%4];"
        : "=r"(r0), "=r"(r1), "=r"(r2), "=r"(r3) : "r"(saddr));
}

__device__ __forceinline__ uint32_t ex2_h2(uint32_t t) {
    uint32_t r;
    asm volatile("ex2.approx.f16x2 %0, %1;" : "=r"(r) : "r"(t));
    return r;
}

#define CP_ASYNC16(saddr, gptr)                                          \
    asm volatile("cp.async.cg.shared.global [%0], [%1], 16;"             \
                 :: "r"(saddr), "l"(gptr) : "memory")
#define CP_COMMIT() asm volatile("cp.async.commit_group;" ::: "memory")
#define CP_WAIT0()  asm volatile("cp.async.wait_group 0;" ::: "memory")
#define CP_WAIT1()  asm volatile("cp.async.wait_group 1;" ::: "memory")

__device__ __forceinline__ uint32_t smem_u32(const void* p) {
    return (uint32_t)__cvta_generic_to_shared(p);
}

__device__ __forceinline__ uint32_t packh(__half a, __half b) {
    __half2 t = __halves2half2(a, b);
    return *(uint32_t*)&t;
}
__device__ __forceinline__ uint32_t packround(float x, float y) {
    return packh(__float2half_rn(x), __float2half_rn(y));
}

// ---------------------------------------------------------------------------
__global__ void round_kernel(const float* __restrict__ X,
                             __half* __restrict__ H, int n) {
    int i = blockIdx.x * 256 + threadIdx.x;
    if (i < n) H[i] = __float2half_rn(X[i]);
}

__global__ void transpose_h_kernel(const float* __restrict__ W,
                                   __half* __restrict__ Th, int K, int N) {
    __shared__ float t[32][33];
    int n0 = blockIdx.x * 32, k0 = blockIdx.y * 32;
    int tx = threadIdx.x, ty = threadIdx.y;
#pragma unroll
    for (int j = 0; j < 4; ++j)
        t[ty + j * 8][tx] = W[(size_t)(k0 + ty + j * 8) * N + n0 + tx];
    __syncthreads();
#pragma unroll
    for (int j = 0; j < 4; ++j)
        Th[(size_t)(n0 + ty + j * 8) * K + k0 + tx] =
            __float2half_rn(t[tx][ty + j * 8]);
}

__global__ void detect_mask_kind_kernel(const unsigned int* __restrict__ m) {
    __shared__ int any_gt1, any_not_f32;
    if (threadIdx.x == 0) { any_gt1 = 0; any_not_f32 = 0; }
    __syncthreads();
    int gt1 = 0, nf32 = 0;
    for (int i = threadIdx.x; i < 16384; i += 256) {
        unsigned int w = m[i];
        if (w > 1u) gt1 = 1;
        if (w != 0u && w != 0x3F800000u) nf32 = 1;
    }
    if (gt1)  atomicOr(&any_gt1, 1);
    if (nf32) atomicOr(&any_not_f32, 1);
    __syncthreads();
    if (threadIdx.x == 0)
        g_mask_kind = (!any_gt1) ? 1 : ((!any_not_f32) ? 2 : 0);
}

__global__ void pack_mask_kernel(const void* __restrict__ m) {
    size_t i = (size_t)blockIdx.x * 256 + threadIdx.x;
    const int kind = g_mask_kind;
    bool v;
    if (kind == 0) v = ((const unsigned char*)m)[i] != 0;
    else           v = ((const unsigned int*)m)[i] != 0;
    unsigned int w = __ballot_sync(0xffffffffu, v);
    if ((threadIdx.x & 31) == 0) g_mpack[i >> 5] = w;
}

// ---------------------------------------------------------------------------
// HMMA GEMM, fp16 1-product, BK=64, cp.async double-buffered, ldmatrix.
// mode 1 epilogue also writes V transposed (vtrans fused).
// ---------------------------------------------------------------------------
__global__ __launch_bounds__(256, 2) void mma_gemm_kernel(
    const __half* __restrict__ Ah, const __half* __restrict__ Bh,
    const float* __restrict__ bias, float* __restrict__ C,
    int M, int N, int K, int mode,
    float* __restrict__ kout, float* __restrict__ vout)
{
    extern __shared__ __half gsm[];
    __half* sA = gsm;             // [2][128][72]
    __half* sB = gsm + 2 * GT2;   // [2][128][72]

    const int tid = threadIdx.x;
    const int lane = tid & 31;
    const int wid = tid >> 5;
    const int wm = (wid & 3) * 32;
    const int wn = (wid >> 2) * 64;
    const int m0 = blockIdx.y * 128;
    const int n0 = blockIdx.x * 128;
    const int gID = lane >> 2;
    const int tig2 = (lane & 3) * 2;
    const int lt = lane >> 3;
    const int lr = lane & 7;

    const uint32_t sbA = smem_u32(sA);
    const uint32_t sbB = smem_u32(sB);

    auto stage = [&](int c, int buf) {
        size_t ka = (size_t)c * 64;
#pragma unroll
        for (int it = 0; it < 4; ++it) {
            int unit = tid + it * 256;       // 0..1023
            int row = unit >> 3, u = unit & 7;
            uint32_t so = (uint32_t)(row * 144 + u * 16) + buf * (GT2 * 2);
            CP_ASYNC16(sbA + so, Ah + (size_t)(m0 + row) * K + ka + u * 8);
            CP_ASYNC16(sbB + so, Bh + (size_t)(n0 + row) * K + ka + u * 8);
        }
        CP_COMMIT();
    };

    float acc[2][8][4] = {};
    const int nchunks = K / 64;

    stage(0, 0);
    for (int c = 0; c < nchunks; ++c) {
        if (c + 1 < nchunks) {
            stage(c + 1, (c + 1) & 1);
            CP_WAIT1();
        } else {
            CP_WAIT0();
        }
        __syncthreads();

        const uint32_t tAb = sbA + (c & 1) * (GT2 * 2);
        const uint32_t tBb = sbB + (c & 1) * (GT2 * 2);
#pragma unroll
        for (int ks = 0; ks < 4; ++ks) {
            const int k0 = ks * 16;
            uint32_t ah[2][4];
#pragma unroll
            for (int mi = 0; mi < 2; ++mi) {
                uint32_t addr = tAb + (uint32_t)(
                    ((wm + mi * 16 + (lt & 1) * 8 + lr) * GKSTR +
                     k0 + (lt >> 1) * 8) * 2);
                ldsm_x4(ah[mi][0], ah[mi][1], ah[mi][2], ah[mi][3], addr);
            }
#pragma unroll
            for (int ntp = 0; ntp < 4; ++ntp) {
                uint32_t addr = tBb + (uint32_t)(
                    ((wn + ntp * 16 + (lt >> 1) * 8 + lr) * GKSTR +
                     k0 + (lt & 1) * 8) * 2);
                uint32_t b00, b01, b10, b11;
                ldsm_x4(b00, b01, b10, b11, addr);
                mma16816(acc[0][2 * ntp],     ah[0], b00, b01);
                mma16816(acc[1][2 * ntp],     ah[1], b00, b01);
                mma16816(acc[0][2 * ntp + 1], ah[0], b10, b11);
                mma16816(acc[1][2 * ntp + 1], ah[1], b10, b11);
            }
        }
        __syncthreads();
    }

#pragma unroll
    for (int mi = 0; mi < 2; ++mi) {
#pragma unroll
        for (int nt = 0; nt < 8; ++nt) {
            int m = m0 + wm + mi * 16 + gID;
            int n = n0 + wn + nt * 8 + tig2;
            float b0 = bias[n], b1 = bias[n + 1];
            float v0 = acc[mi][nt][0] + b0;
            float v1 = acc[mi][nt][1] + b1;
            float v2 = acc[mi][nt][2] + b0;
            float v3 = acc[mi][nt][3] + b1;
            if (mode == 0) {
                *(float2*)&C[(size_t)m * N + n] = make_float2(v0, v1);
                *(float2*)&C[(size_t)(m + 8) * N + n] = make_float2(v2, v3);
            } else {
                int sec = n >> 10;
                int e = n & 1023;
                int h = e >> 6;
                int d = e & 63;
#pragma unroll
                for (int rr = 0; rr < 2; ++rr) {
                    int mm = m + rr * 8;
                    int bb = mm >> 10;
                    int s = mm & 1023;
                    size_t idx = (((size_t)(bb * kH + h)) * kS + s) * kHD + d;
                    float p0 = rr ? v2 : v0, p1 = rr ? v3 : v1;
                    if (sec == 0) {
                        *(uint32_t*)&g_qh[idx] = packround(p0, p1);
                    } else if (sec == 1) {
                        *(float2*)&kout[idx] = make_float2(p0, p1);
                        *(uint32_t*)&g_kh[idx] = packround(p0, p1);
                    } else {
                        *(float2*)&vout[idx] = make_float2(p0, p1);
                        size_t tb = ((size_t)(bb * kH + h) * kHD + d) * kS + s;
                        g_vth[tb] = __float2half_rn(p0);
                        g_vth[tb + kS] = __float2half_rn(p1);
                    }
                }
            }
        }
    }
}

// ---------------------------------------------------------------------------
// OV kernel (batch-shared, bit-packed mask, ldmatrix V fragments)
// ---------------------------------------------------------------------------
__global__ __launch_bounds__(256, 2) void ov_kernel(
    const float* __restrict__ ov, float* __restrict__ out)
{
    extern __shared__ __half sV[];
    const int tid = threadIdx.x, lane = tid & 31, wid = tid >> 5;
    const int gID = lane >> 2, tig2 = (lane & 3) * 2;
    const int lt = lane >> 3, lr = lane & 7;
    const int h = blockIdx.y, q0 = blockIdx.x * 64;
    const int qsub = wid & 3;
    const int dhalf = wid >> 2;
    const int qr0 = q0 + qsub * 16 + gID, qr1 = qr0 + 8;
    const size_t mr0 = ((size_t)h * kS + qr0) * kS;
    const size_t mr1 = ((size_t)h * kS + qr1) * kS;
    const size_t wb0 = ((size_t)h * kS + qr0) * 32;
    const size_t wb1 = ((size_t)h * kS + qr1) * 32;
    const uint32_t sbV = smem_u32(sV);

    float o[4][4][4] = {};

    for (int kc = 0; kc < 8; ++kc) {
#pragma unroll
        for (int bb = 0; bb < 4; ++bb) {
            const size_t bhT = (size_t)(bb * kH + h) * kHD;
#pragma unroll
            for (int it = 0; it < 2; ++it) {
                int unit = tid + it * 256;
                int row = unit >> 3, u = (unit & 7) * 16;
                *(float4*)&sV[bb * OV_VT + row * 136 + u] =
                    *(const float4*)&g_vth[(bhT + row) * kS + kc * 128 + u];
                *(float4*)&sV[bb * OV_VT + row * 136 + u + 8] =
                    *(const float4*)&g_vth[(bhT + row) * kS + kc * 128 + u + 8];
            }
        }
        __syncthreads();

        uint32_t w0[4], w1[4];
#pragma unroll
        for (int j = 0; j < 4; ++j) {
            w0[j] = g_mpack[wb0 + kc * 4 + j];
            w1[j] = g_mpack[wb1 + kc * 4 + j];
        }

#pragma unroll
        for (int ks = 0; ks < 8; ++ks) {
            size_t kg = (size_t)kc * 128 + ks * 16 + tig2;
            int wd = ks >> 1;
            int bp = (ks & 1) * 16 + tig2;
            float2 v00 = *(const float2*)&ov[mr0 + kg];
            float2 v02 = *(const float2*)&ov[mr0 + kg + 8];
            float2 v10 = *(const float2*)&ov[mr1 + kg];
            float2 v12 = *(const float2*)&ov[mr1 + kg + 8];
            uint32_t ah[4];
            ah[0] = packround(((w0[wd] >> bp) & 1) ? v00.x : 0.f,
                              ((w0[wd] >> (bp + 1)) & 1) ? v00.y : 0.f);
            ah[1] = packround(((w1[wd] >> bp) & 1) ? v10.x : 0.f,
                              ((w1[wd] >> (bp + 1)) & 1) ? v10.y : 0.f);
            ah[2] = packround(((w0[wd] >> (bp + 8)) & 1) ? v02.x : 0.f,
                              ((w0[wd] >> (bp + 9)) & 1) ? v02.y : 0.f);
            ah[3] = packround(((w1[wd] >> (bp + 8)) & 1) ? v12.x : 0.f,
                              ((w1[wd] >> (bp + 9)) & 1) ? v12.y : 0.f);
#pragma unroll
            for (int bb = 0; bb < 4; ++bb)
#pragma unroll
                for (int dnp = 0; dnp < 2; ++dnp) {
                    uint32_t addr = sbV + (uint32_t)((bb * OV_VT +
                        (dhalf * 32 + dnp * 16 + (lt >> 1) * 8 + lr) * 136 +
                        ks * 16 + (lt & 1) * 8) * 2);
                    uint32_t b00, b01, b10, b11;
                    ldsm_x4(b00, b01, b10, b11, addr);
                    mma16816(o[bb][2 * dnp],     ah, b00, b01);
                    mma16816(o[bb][2 * dnp + 1], ah, b10, b11);
                }
        }
        __syncthreads();
    }

#pragma unroll
    for (int bb = 0; bb < 4; ++bb)
#pragma unroll
        for (int dn = 0; dn < 4; ++dn) {
            int d = h * kHD + dhalf * 32 + dn * 8 + tig2;
            *(float2*)&out[(size_t)(bb * kS + qr0) * kD + d] =
                make_float2(o[bb][dn][0], o[bb][dn][1]);
            *(float2*)&out[(size_t)(bb * kS + qr1) * kD + d] =
                make_float2(o[bb][dn][2], o[bb][dn][3]);
        }
}

// ---------------------------------------------------------------------------
// Flash kernel: 1-product QK^T; f16x2 ex2 softmax; K+V double-buffered;
// ldmatrix fragments; heavy-first q-tiles; writes fp16 a directly.
// ---------------------------------------------------------------------------
__global__ __launch_bounds__(256, 2) void flash_kernel(
    const float* __restrict__ aio)
{
    extern __shared__ __half fsm[];
    __half* sK = fsm;              // [2][128][72]
    __half* sV = fsm + F_V0;       // [2][64][136]

    const int tid = threadIdx.x, lane = tid & 31, wid = tid >> 5;
    const int gID = lane >> 2, tig2 = (lane & 3) * 2;
    const int lt = lane >> 3, lr = lane & 7;
    const int b = blockIdx.z, h = blockIdx.y;
    const int qt = (int)gridDim.x - 1 - (int)blockIdx.x;
    const int q0 = qt * 128;
    const int wq = wid * 16;
    const size_t bh = (size_t)(b * kH + h) * kS * kHD;
    const size_t bhT = (size_t)(b * kH + h) * kHD;
    const uint32_t sbK = smem_u32(sK);
    const uint32_t sbV = smem_u32(sV);
    const float CEXP = 0.18033688f;  // log2(e)/8

    auto stageKV = [&](int c, int buf) {
#pragma unroll
        for (int it = 0; it < 4; ++it) {
            int unit = tid + it * 256;
            int row = unit >> 3, u = unit & 7;
            uint32_t so = (uint32_t)(row * 144 + u * 16) + buf * (F_KT * 2);
            CP_ASYNC16(sbK + so,
                       g_kh + bh + (size_t)(c * 128 + row) * kHD + u * 8);
        }
#pragma unroll
        for (int it = 0; it < 4; ++it) {
            int unit = tid + it * 256;
            int row = unit >> 4, u16 = unit & 15;
            uint32_t so = (uint32_t)(row * 272 + u16 * 16) + buf * (F_VT * 2);
            CP_ASYNC16(sbV + so,
                       g_vth + (bhT + row) * kS + (size_t)c * 128 + u16 * 8);
        }
        CP_COMMIT();
    };

    // stage Q synchronously (borrow K buffer 0), grab fragments
#pragma unroll
    for (int it = 0; it < 4; ++it) {
        int unit = tid + it * 256;
        int row = unit >> 3, u = (unit & 7) * 8;
        *(float4*)&sK[row * 72 + u] =
            *(const float4*)&g_qh[bh + (size_t)(q0 + row) * kHD + u];
    }
    __syncthreads();
    uint32_t qf[4][4];
#pragma unroll
    for (int ks = 0; ks < 4; ++ks) {
        uint32_t addr = sbK + (uint32_t)(
            ((wq + (lt & 1) * 8 + lr) * 72 + ks * 16 + (lt >> 1) * 8) * 2);
        ldsm_x4(qf[ks][0], qf[ks][1], qf[ks][2], qf[ks][3], addr);
    }
    __syncthreads();

    stageKV(0, 0);

    float o[8][4] = {};
    float Z0 = 0.f, Z1 = 0.f;
    const int qr0 = q0 + wq + gID, qr1 = qr0 + 8;
    const size_t wb0 = ((size_t)h * kS + qr0) * 32;
    const size_t wb1 = ((size_t)h * kS + qr1) * 32;

    for (int kc = 0; kc <= qt; ++kc) {
        if (kc + 1 <= qt) {
            stageKV(kc + 1, (kc + 1) & 1);
            CP_WAIT1();
        } else {
            CP_WAIT0();
        }
        __syncthreads();

        const uint32_t tKb = sbK + (kc & 1) * (F_KT * 2);
        const uint32_t tVb = sbV + (kc & 1) * (F_VT * 2);

        for (int qq = 0; qq < 4; ++qq) {
            float sa[4][4] = {};
#pragma unroll
            for (int ks = 0; ks < 4; ++ks)
#pragma unroll
                for (int ntp = 0; ntp < 2; ++ntp) {
                    uint32_t addr = tKb + (uint32_t)(
                        ((qq * 32 + ntp * 16 + (lt >> 1) * 8 + lr) * 72 +
                         ks * 16 + (lt & 1) * 8) * 2);
                    uint32_t b00, b01, b10, b11;
                    ldsm_x4(b00, b01, b10, b11, addr);
                    mma16816(sa[2 * ntp],     qf[ks], b00, b01);
                    mma16816(sa[2 * ntp + 1], qf[ks], b10, b11);
                }

            uint32_t mw0 = g_mpack[wb0 + kc * 4 + qq];
            uint32_t mw1 = g_mpack[wb1 + kc * 4 + qq];
            uint32_t ehr0[4], ehr1[4];
#pragma unroll
            for (int nt = 0; nt < 4; ++nt) {
                int kg = kc * 128 + qq * 32 + nt * 8 + tig2;
                int bp = nt * 8 + tig2;
                // e = 2^(s*log2e/8) on fp16 pairs
                __half2 t0 = __floats2half2_rn(sa[nt][0] * CEXP,
                                               sa[nt][1] * CEXP);
                __half2 t1 = __floats2half2_rn(sa[nt][2] * CEXP,
                                               sa[nt][3] * CEXP);
                uint32_t e0 = ex2_h2(*(uint32_t*)&t0);
                uint32_t e1 = ex2_h2(*(uint32_t*)&t1);
                // causal zeroing (lanes: lo=kg, hi=kg+1)
                uint32_t ca0 = (kg <= qr0 ? 0x0000FFFFu : 0u) |
                               (kg + 1 <= qr0 ? 0xFFFF0000u : 0u);
                uint32_t ca1 = (kg <= qr1 ? 0x0000FFFFu : 0u) |
                               (kg + 1 <= qr1 ? 0xFFFF0000u : 0u);
                e0 &= ca0;
                e1 &= ca1;
                float2 f0 = __half22float2(*(__half2*)&e0);
                float2 f1 = __half22float2(*(__half2*)&e1);
                Z0 += f0.x + f0.y;
                Z1 += f1.x + f1.y;
                // override-mask zeroing
                uint32_t mm0 = (((mw0 >> bp) & 1) ? 0x0000FFFFu : 0u) |
                               (((mw0 >> (bp + 1)) & 1) ? 0xFFFF0000u : 0u);
                uint32_t mm1 = (((mw1 >> bp) & 1) ? 0x0000FFFFu : 0u) |
                               (((mw1 >> (bp + 1)) & 1) ? 0xFFFF0000u : 0u);
                ehr0[nt] = e0 & ~mm0;
                ehr1[nt] = e1 & ~mm1;
            }
#pragma unroll
            for (int k2 = 0; k2 < 2; ++k2) {
                uint32_t ah[4] = {ehr0[2 * k2], ehr1[2 * k2],
                                  ehr0[2 * k2 + 1], ehr1[2 * k2 + 1]};
#pragma unroll
                for (int dnp = 0; dnp < 4; ++dnp) {
                    uint32_t addr = tVb + (uint32_t)(
                        ((dnp * 16 + (lt >> 1) * 8 + lr) * 136 +
                         qq * 32 + k2 * 16 + (lt & 1) * 8) * 2);
                    uint32_t b00, b01, b10, b11;
                    ldsm_x4(b00, b01, b10, b11, addr);
                    mma16816(o[2 * dnp],     ah, b00, b01);
                    mma16816(o[2 * dnp + 1], ah, b10, b11);
                }
            }
        }
        __syncthreads();
    }

    Z0 += __shfl_xor_sync(0xffffffffu, Z0, 1);
    Z0 += __shfl_xor_sync(0xffffffffu, Z0, 2);
    Z1 += __shfl_xor_sync(0xffffffffu, Z1, 1);
    Z1 += __shfl_xor_sync(0xffffffffu, Z1, 2);
    float i0 = 1.f / Z0, i1 = 1.f / Z1;

#pragma unroll
    for (int dn = 0; dn < 8; ++dn) {
        int d = h * kHD + dn * 8 + tig2;
        size_t r0 = (size_t)(b * kS + qr0) * kD + d;
        size_t r1 = (size_t)(b * kS + qr1) * kD + d;
        float2 p0 = *(const float2*)&aio[r0];
        float2 p1 = *(const float2*)&aio[r1];
        *(uint32_t*)&g_ah[r0] =
            packround(p0.x + o[dn][0] * i0, p0.y + o[dn][1] * i0);
        *(uint32_t*)&g_ah[r1] =
            packround(p1.x + o[dn][2] * i1, p1.y + o[dn][3] * i1);
    }
}

// ---------------------------------------------------------------------------
extern "C" void kernel_launch(void* const* d_in, const int* in_sizes, int n_in,
                              void* d_out, int out_size)
{
    const float* x       = (const float*)d_in[0];
    const float* w_attn  = (const float*)d_in[1];
    const float* b_attn  = (const float*)d_in[2];
    const float* w_proj  = (const float*)d_in[3];
    const float* b_proj  = (const float*)d_in[4];
    const float* ov      = (const float*)d_in[5];
    const void*  msk     = (const void*)d_in[6];

    float* out = (float*)d_out;
    float* presentK = out + (size_t)kM * kD;
    float* presentV = presentK + (size_t)kB * kH * kS * kHD;

    float* aptr = nullptr;
    __half *xh, *ah, *wth, *pth;
    cudaGetSymbolAddress((void**)&aptr, g_a);
    cudaGetSymbolAddress((void**)&xh, g_xh);
    cudaGetSymbolAddress((void**)&ah, g_ah);
    cudaGetSymbolAddress((void**)&wth, g_wth);
    cudaGetSymbolAddress((void**)&pth, g_pth);

    cudaFuncSetAttribute(mma_gemm_kernel,
                         cudaFuncAttributeMaxDynamicSharedMemorySize,
                         GEMM_SMEM_BYTES);
    cudaFuncSetAttribute(flash_kernel,
                         cudaFuncAttributeMaxDynamicSharedMemorySize,
                         FLASH_SMEM_BYTES);
    cudaFuncSetAttribute(ov_kernel,
                         cudaFuncAttributeMaxDynamicSharedMemorySize,
                         OV_SMEM_BYTES);

    // 0) mask classification + bit-pack + operand prep
    detect_mask_kind_kernel<<<1, 256>>>((const unsigned int*)msk);
    pack_mask_kernel<<<(kH * kS * kS) / 256, 256>>>(msk);
    round_kernel<<<kM * kD / 256, 256>>>(x, xh, kM * kD);
    transpose_h_kernel<<<dim3(3 * kD / 32, kD / 32), dim3(32, 8)>>>(
        w_attn, wth, kD, 3 * kD);
    transpose_h_kernel<<<dim3(kD / 32, kD / 32), dim3(32, 8)>>>(
        w_proj, pth, kD, kD);

    // 1) QKV GEMM -> present fp32 + q/k fp16 + V transposed fp16 (fused)
    mma_gemm_kernel<<<dim3(3 * kD / 128, kM / 128), 256, GEMM_SMEM_BYTES>>>(
        xh, wth, b_attn, nullptr, kM, 3 * kD, kD, 1, presentK, presentV);

    // 2) override term -> g_a (batch-shared)
    ov_kernel<<<dim3(kS / 64, kH), 256, OV_SMEM_BYTES>>>(ov, aptr);

    // 3) flash: adds softmax term, writes fp16 a directly
    flash_kernel<<<dim3(kS / 128, kH, kB), 256, FLASH_SMEM_BYTES>>>(aptr);

    // 4) output projection
    mma_gemm_kernel<<<dim3(kD / 128, kM / 128), 256, GEMM_SMEM_BYTES>>>(
        ah, pth, b_proj, out, kM, kD, kD, 0, nullptr, nullptr);
}

// round 16
// speedup vs baseline: 4.4841x; 1.0234x over previous
#include <cuda_runtime.h>
#include <cuda_fp16.h>
#include <cstdint>

// ---------------------------------------------------------------------------
// AttentionOverride, round 16: R15 + diagonal/off-diagonal flash split,
// scalar-hadd Z accumulation, fp16 ov->flash handoff, fused prep kernel.
// Output layout: [ a (4M floats) | presentK (4M) | presentV (4M) ]
// ---------------------------------------------------------------------------

namespace {
constexpr int kB  = 4;
constexpr int kS  = 1024;
constexpr int kD  = 1024;
constexpr int kH  = 16;
constexpr int kHD = 64;
constexpr int kM  = kB * kS;  // 4096

constexpr int GKSTR = 72;           // GEMM smem stride (half), BK=64
constexpr int GT2   = 128 * GKSTR;  // one GEMM tile in halves (9216)
constexpr int GEMM_SMEM_BYTES = 4 * GT2 * 2;  // 73728

constexpr int F_KT = 9216;
constexpr int F_VT = 8704;
constexpr int F_V0 = 2 * F_KT;
constexpr int FLASH_SMEM_BYTES = (2 * F_KT + 2 * F_VT) * 2;  // 71680

constexpr int OV_VT = 8704;
constexpr int OV_SMEM_BYTES = 4 * OV_VT * 2;   // 69632

// prep kernel block ranges
constexpr int PREP_ROUND = kM * kD / 256;            // 16384
constexpr int PREP_WA    = (3 * kD / 32) * (kD / 32); // 3072
constexpr int PREP_WP    = (kD / 32) * (kD / 32);     // 1024
}  // namespace

// scratch (device globals; no allocation allowed)
__device__ int   g_mask_kind;
__device__ uint32_t g_mpack[(size_t)kH * kS * (kS / 32)];
__device__ __half g_qh[(size_t)kM * kD];
__device__ __half g_kh[(size_t)kM * kD];
__device__ __half g_vth[(size_t)kM * kD];       // [BH][64][S]
__device__ __half g_xh[(size_t)kM * kD];
__device__ __half g_oh[(size_t)kM * kD];        // ov term (fp16)
__device__ __half g_ah[(size_t)kM * kD];        // a (fp16) for proj
__device__ __half g_wth[(size_t)3 * kD * kD];
__device__ __half g_pth[(size_t)kD * kD];

// ---------------------------------------------------------------------------
__device__ __forceinline__ void mma16816(float* c, const uint32_t* a,
                                         uint32_t b0, uint32_t b1) {
    asm volatile(
        "mma.sync.aligned.m16n8k16.row.col.f32.f16.f16.f32 "
        "{%0,%1,%2,%3}, {%4,%5,%6,%7}, {%8,%9}, {%0,%1,%2,%3};"
        : "+f"(c[0]), "+f"(c[1]), "+f"(c[2]), "+f"(c[3])
        : "r"(a[0]), "r"(a[1]), "r"(a[2]), "r"(a[3]), "r"(b0), "r"(b1));
}

__device__ __forceinline__ void ldsm_x4(uint32_t& r0, uint32_t& r1,
                                        uint32_t& r2, uint32_t& r3,
                                        uint32_t saddr) {
    asm volatile(
        "ldmatrix.sync.aligned.m8n8.x4.shared.b16 {%0,%1,%2,%3}, [%4];"
        : "=r"(r0), "=r"(r1), "=r"(r2), "=r"(r3) : "r"(saddr));
}

__device__ __forceinline__ uint32_t ex2_h2(uint32_t t) {
    uint32_t r;
    asm volatile("ex2.approx.f16x2 %0, %1;" : "=r"(r) : "r"(t));
    return r;
}

#define CP_ASYNC16(saddr, gptr)                                          \
    asm volatile("cp.async.cg.shared.global [%0], [%1], 16;"             \
                 :: "r"(saddr), "l"(gptr) : "memory")
#define CP_COMMIT() asm volatile("cp.async.commit_group;" ::: "memory")
#define CP_WAIT0()  asm volatile("cp.async.wait_group 0;" ::: "memory")
#define CP_WAIT1()  asm volatile("cp.async.wait_group 1;" ::: "memory")

__device__ __forceinline__ uint32_t smem_u32(const void* p) {
    return (uint32_t)__cvta_generic_to_shared(p);
}

__device__ __forceinline__ uint32_t packh(__half a, __half b) {
    __half2 t = __halves2half2(a, b);
    return *(uint32_t*)&t;
}
__device__ __forceinline__ uint32_t packround(float x, float y) {
    return packh(__float2half_rn(x), __float2half_rn(y));
}
__device__ __forceinline__ float zsum2(uint32_t e) {
    __half2 h = *(__half2*)&e;
    return __half2float(__hadd(h.x, h.y));
}

// ---------------------------------------------------------------------------
// Fused prep: [0,16384) round x; [16384,19456) transpose w_attn;
// [19456,20480) transpose w_proj.
// ---------------------------------------------------------------------------
__global__ void prep_kernel(const float* __restrict__ x,
                            const float* __restrict__ wa,
                            const float* __restrict__ wp) {
    __shared__ float t[32][33];
    int bid = blockIdx.x;
    int tid = threadIdx.x;
    if (bid < PREP_ROUND) {
        int i = bid * 256 + tid;
        g_xh[i] = __float2half_rn(x[i]);
        return;
    }
    const float* W;
    __half* Th;
    int N, b2;
    if (bid < PREP_ROUND + PREP_WA) {
        b2 = bid - PREP_ROUND;
        W = wa; Th = g_wth; N = 3 * kD;
    } else {
        b2 = bid - PREP_ROUND - PREP_WA;
        W = wp; Th = g_pth; N = kD;
    }
    const int K = kD;
    int nblk = N / 32;
    int n0 = (b2 % nblk) * 32, k0 = (b2 / nblk) * 32;
    int tx = tid & 31, ty = tid >> 5;
#pragma unroll
    for (int j = 0; j < 4; ++j)
        t[ty + j * 8][tx] = W[(size_t)(k0 + ty + j * 8) * N + n0 + tx];
    __syncthreads();
#pragma unroll
    for (int j = 0; j < 4; ++j)
        Th[(size_t)(n0 + ty + j * 8) * K + k0 + tx] =
            __float2half_rn(t[tx][ty + j * 8]);
}

__global__ void detect_mask_kind_kernel(const unsigned int* __restrict__ m) {
    __shared__ int any_gt1, any_not_f32;
    if (threadIdx.x == 0) { any_gt1 = 0; any_not_f32 = 0; }
    __syncthreads();
    int gt1 = 0, nf32 = 0;
    for (int i = threadIdx.x; i < 16384; i += 256) {
        unsigned int w = m[i];
        if (w > 1u) gt1 = 1;
        if (w != 0u && w != 0x3F800000u) nf32 = 1;
    }
    if (gt1)  atomicOr(&any_gt1, 1);
    if (nf32) atomicOr(&any_not_f32, 1);
    __syncthreads();
    if (threadIdx.x == 0)
        g_mask_kind = (!any_gt1) ? 1 : ((!any_not_f32) ? 2 : 0);
}

__global__ void pack_mask_kernel(const void* __restrict__ m) {
    size_t i = (size_t)blockIdx.x * 256 + threadIdx.x;
    const int kind = g_mask_kind;
    bool v;
    if (kind == 0) v = ((const unsigned char*)m)[i] != 0;
    else           v = ((const unsigned int*)m)[i] != 0;
    unsigned int w = __ballot_sync(0xffffffffu, v);
    if ((threadIdx.x & 31) == 0) g_mpack[i >> 5] = w;
}

// ---------------------------------------------------------------------------
// HMMA GEMM, fp16 1-product, BK=64, cp.async double-buffered, ldmatrix.
// mode 1 epilogue also writes V transposed (vtrans fused).
// ---------------------------------------------------------------------------
__global__ __launch_bounds__(256, 2) void mma_gemm_kernel(
    const __half* __restrict__ Ah, const __half* __restrict__ Bh,
    const float* __restrict__ bias, float* __restrict__ C,
    int M, int N, int K, int mode,
    float* __restrict__ kout, float* __restrict__ vout)
{
    extern __shared__ __half gsm[];
    __half* sA = gsm;
    __half* sB = gsm + 2 * GT2;

    const int tid = threadIdx.x;
    const int lane = tid & 31;
    const int wid = tid >> 5;
    const int wm = (wid & 3) * 32;
    const int wn = (wid >> 2) * 64;
    const int m0 = blockIdx.y * 128;
    const int n0 = blockIdx.x * 128;
    const int gID = lane >> 2;
    const int tig2 = (lane & 3) * 2;
    const int lt = lane >> 3;
    const int lr = lane & 7;

    const uint32_t sbA = smem_u32(sA);
    const uint32_t sbB = smem_u32(sB);

    auto stage = [&](int c, int buf) {
        size_t ka = (size_t)c * 64;
#pragma unroll
        for (int it = 0; it < 4; ++it) {
            int unit = tid + it * 256;
            int row = unit >> 3, u = unit & 7;
            uint32_t so = (uint32_t)(row * 144 + u * 16) + buf * (GT2 * 2);
            CP_ASYNC16(sbA + so, Ah + (size_t)(m0 + row) * K + ka + u * 8);
            CP_ASYNC16(sbB + so, Bh + (size_t)(n0 + row) * K + ka + u * 8);
        }
        CP_COMMIT();
    };

    float acc[2][8][4] = {};
    const int nchunks = K / 64;

    stage(0, 0);
    for (int c = 0; c < nchunks; ++c) {
        if (c + 1 < nchunks) {
            stage(c + 1, (c + 1) & 1);
            CP_WAIT1();
        } else {
            CP_WAIT0();
        }
        __syncthreads();

        const uint32_t tAb = sbA + (c & 1) * (GT2 * 2);
        const uint32_t tBb = sbB + (c & 1) * (GT2 * 2);
#pragma unroll
        for (int ks = 0; ks < 4; ++ks) {
            const int k0 = ks * 16;
            uint32_t ah[2][4];
#pragma unroll
            for (int mi = 0; mi < 2; ++mi) {
                uint32_t addr = tAb + (uint32_t)(
                    ((wm + mi * 16 + (lt & 1) * 8 + lr) * GKSTR +
                     k0 + (lt >> 1) * 8) * 2);
                ldsm_x4(ah[mi][0], ah[mi][1], ah[mi][2], ah[mi][3], addr);
            }
#pragma unroll
            for (int ntp = 0; ntp < 4; ++ntp) {
                uint32_t addr = tBb + (uint32_t)(
                    ((wn + ntp * 16 + (lt >> 1) * 8 + lr) * GKSTR +
                     k0 + (lt & 1) * 8) * 2);
                uint32_t b00, b01, b10, b11;
                ldsm_x4(b00, b01, b10, b11, addr);
                mma16816(acc[0][2 * ntp],     ah[0], b00, b01);
                mma16816(acc[1][2 * ntp],     ah[1], b00, b01);
                mma16816(acc[0][2 * ntp + 1], ah[0], b10, b11);
                mma16816(acc[1][2 * ntp + 1], ah[1], b10, b11);
            }
        }
        __syncthreads();
    }

#pragma unroll
    for (int mi = 0; mi < 2; ++mi) {
#pragma unroll
        for (int nt = 0; nt < 8; ++nt) {
            int m = m0 + wm + mi * 16 + gID;
            int n = n0 + wn + nt * 8 + tig2;
            float b0 = bias[n], b1 = bias[n + 1];
            float v0 = acc[mi][nt][0] + b0;
            float v1 = acc[mi][nt][1] + b1;
            float v2 = acc[mi][nt][2] + b0;
            float v3 = acc[mi][nt][3] + b1;
            if (mode == 0) {
                *(float2*)&C[(size_t)m * N + n] = make_float2(v0, v1);
                *(float2*)&C[(size_t)(m + 8) * N + n] = make_float2(v2, v3);
            } else {
                int sec = n >> 10;
                int e = n & 1023;
                int h = e >> 6;
                int d = e & 63;
#pragma unroll
                for (int rr = 0; rr < 2; ++rr) {
                    int mm = m + rr * 8;
                    int bb = mm >> 10;
                    int s = mm & 1023;
                    size_t idx = (((size_t)(bb * kH + h)) * kS + s) * kHD + d;
                    float p0 = rr ? v2 : v0, p1 = rr ? v3 : v1;
                    if (sec == 0) {
                        *(uint32_t*)&g_qh[idx] = packround(p0, p1);
                    } else if (sec == 1) {
                        *(float2*)&kout[idx] = make_float2(p0, p1);
                        *(uint32_t*)&g_kh[idx] = packround(p0, p1);
                    } else {
                        *(float2*)&vout[idx] = make_float2(p0, p1);
                        size_t tb = ((size_t)(bb * kH + h) * kHD + d) * kS + s;
                        g_vth[tb] = __float2half_rn(p0);
                        g_vth[tb + kS] = __float2half_rn(p1);
                    }
                }
            }
        }
    }
}

// ---------------------------------------------------------------------------
// OV kernel (batch-shared, bit-packed mask, ldmatrix); writes fp16 g_oh.
// ---------------------------------------------------------------------------
__global__ __launch_bounds__(256, 2) void ov_kernel(
    const float* __restrict__ ov)
{
    extern __shared__ __half sV[];
    const int tid = threadIdx.x, lane = tid & 31, wid = tid >> 5;
    const int gID = lane >> 2, tig2 = (lane & 3) * 2;
    const int lt = lane >> 3, lr = lane & 7;
    const int h = blockIdx.y, q0 = blockIdx.x * 64;
    const int qsub = wid & 3;
    const int dhalf = wid >> 2;
    const int qr0 = q0 + qsub * 16 + gID, qr1 = qr0 + 8;
    const size_t mr0 = ((size_t)h * kS + qr0) * kS;
    const size_t mr1 = ((size_t)h * kS + qr1) * kS;
    const size_t wb0 = ((size_t)h * kS + qr0) * 32;
    const size_t wb1 = ((size_t)h * kS + qr1) * 32;
    const uint32_t sbV = smem_u32(sV);

    float o[4][4][4] = {};

    for (int kc = 0; kc < 8; ++kc) {
#pragma unroll
        for (int bb = 0; bb < 4; ++bb) {
            const size_t bhT = (size_t)(bb * kH + h) * kHD;
#pragma unroll
            for (int it = 0; it < 2; ++it) {
                int unit = tid + it * 256;
                int row = unit >> 3, u = (unit & 7) * 16;
                *(float4*)&sV[bb * OV_VT + row * 136 + u] =
                    *(const float4*)&g_vth[(bhT + row) * kS + kc * 128 + u];
                *(float4*)&sV[bb * OV_VT + row * 136 + u + 8] =
                    *(const float4*)&g_vth[(bhT + row) * kS + kc * 128 + u + 8];
            }
        }
        __syncthreads();

        uint32_t w0[4], w1[4];
#pragma unroll
        for (int j = 0; j < 4; ++j) {
            w0[j] = g_mpack[wb0 + kc * 4 + j];
            w1[j] = g_mpack[wb1 + kc * 4 + j];
        }

#pragma unroll
        for (int ks = 0; ks < 8; ++ks) {
            size_t kg = (size_t)kc * 128 + ks * 16 + tig2;
            int wd = ks >> 1;
            int bp = (ks & 1) * 16 + tig2;
            float2 v00 = *(const float2*)&ov[mr0 + kg];
            float2 v02 = *(const float2*)&ov[mr0 + kg + 8];
            float2 v10 = *(const float2*)&ov[mr1 + kg];
            float2 v12 = *(const float2*)&ov[mr1 + kg + 8];
            uint32_t ah[4];
            ah[0] = packround(((w0[wd] >> bp) & 1) ? v00.x : 0.f,
                              ((w0[wd] >> (bp + 1)) & 1) ? v00.y : 0.f);
            ah[1] = packround(((w1[wd] >> bp) & 1) ? v10.x : 0.f,
                              ((w1[wd] >> (bp + 1)) & 1) ? v10.y : 0.f);
            ah[2] = packround(((w0[wd] >> (bp + 8)) & 1) ? v02.x : 0.f,
                              ((w0[wd] >> (bp + 9)) & 1) ? v02.y : 0.f);
            ah[3] = packround(((w1[wd] >> (bp + 8)) & 1) ? v12.x : 0.f,
                              ((w1[wd] >> (bp + 9)) & 1) ? v12.y : 0.f);
#pragma unroll
            for (int bb = 0; bb < 4; ++bb)
#pragma unroll
                for (int dnp = 0; dnp < 2; ++dnp) {
                    uint32_t addr = sbV + (uint32_t)((bb * OV_VT +
                        (dhalf * 32 + dnp * 16 + (lt >> 1) * 8 + lr) * 136 +
                        ks * 16 + (lt & 1) * 8) * 2);
                    uint32_t b00, b01, b10, b11;
                    ldsm_x4(b00, b01, b10, b11, addr);
                    mma16816(o[bb][2 * dnp],     ah, b00, b01);
                    mma16816(o[bb][2 * dnp + 1], ah, b10, b11);
                }
        }
        __syncthreads();
    }

#pragma unroll
    for (int bb = 0; bb < 4; ++bb)
#pragma unroll
        for (int dn = 0; dn < 4; ++dn) {
            int d = h * kHD + dhalf * 32 + dn * 8 + tig2;
            *(uint32_t*)&g_oh[(size_t)(bb * kS + qr0) * kD + d] =
                packround(o[bb][dn][0], o[bb][dn][1]);
            *(uint32_t*)&g_oh[(size_t)(bb * kS + qr1) * kD + d] =
                packround(o[bb][dn][2], o[bb][dn][3]);
        }
}

// ---------------------------------------------------------------------------
// Flash kernel: 1-product QK^T; f16x2 ex2 softmax; diagonal/off-diagonal
// split; K+V double-buffered; heavy-first; reads g_oh, writes g_ah.
// ---------------------------------------------------------------------------
__global__ __launch_bounds__(256, 2) void flash_kernel()
{
    extern __shared__ __half fsm[];
    __half* sK = fsm;
    __half* sV = fsm + F_V0;

    const int tid = threadIdx.x, lane = tid & 31, wid = tid >> 5;
    const int gID = lane >> 2, tig2 = (lane & 3) * 2;
    const int lt = lane >> 3, lr = lane & 7;
    const int b = blockIdx.z, h = blockIdx.y;
    const int qt = (int)gridDim.x - 1 - (int)blockIdx.x;
    const int q0 = qt * 128;
    const int wq = wid * 16;
    const size_t bh = (size_t)(b * kH + h) * kS * kHD;
    const size_t bhT = (size_t)(b * kH + h) * kHD;
    const uint32_t sbK = smem_u32(sK);
    const uint32_t sbV = smem_u32(sV);
    const float CEXP = 0.18033688f;  // log2(e)/8

    auto stageKV = [&](int c, int buf) {
#pragma unroll
        for (int it = 0; it < 4; ++it) {
            int unit = tid + it * 256;
            int row = unit >> 3, u = unit & 7;
            uint32_t so = (uint32_t)(row * 144 + u * 16) + buf * (F_KT * 2);
            CP_ASYNC16(sbK + so,
                       g_kh + bh + (size_t)(c * 128 + row) * kHD + u * 8);
        }
#pragma unroll
        for (int it = 0; it < 4; ++it) {
            int unit = tid + it * 256;
            int row = unit >> 4, u16 = unit & 15;
            uint32_t so = (uint32_t)(row * 272 + u16 * 16) + buf * (F_VT * 2);
            CP_ASYNC16(sbV + so,
                       g_vth + (bhT + row) * kS + (size_t)c * 128 + u16 * 8);
        }
        CP_COMMIT();
    };

#pragma unroll
    for (int it = 0; it < 4; ++it) {
        int unit = tid + it * 256;
        int row = unit >> 3, u = (unit & 7) * 8;
        *(float4*)&sK[row * 72 + u] =
            *(const float4*)&g_qh[bh + (size_t)(q0 + row) * kHD + u];
    }
    __syncthreads();
    uint32_t qf[4][4];
#pragma unroll
    for (int ks = 0; ks < 4; ++ks) {
        uint32_t addr = sbK + (uint32_t)(
            ((wq + (lt & 1) * 8 + lr) * 72 + ks * 16 + (lt >> 1) * 8) * 2);
        ldsm_x4(qf[ks][0], qf[ks][1], qf[ks][2], qf[ks][3], addr);
    }
    __syncthreads();

    stageKV(0, 0);

    float o[8][4] = {};
    float Z0 = 0.f, Z1 = 0.f;
    const int qr0 = q0 + wq + gID, qr1 = qr0 + 8;
    const size_t wb0 = ((size_t)h * kS + qr0) * 32;
    const size_t wb1 = ((size_t)h * kS + qr1) * 32;

    for (int kc = 0; kc <= qt; ++kc) {
        if (kc + 1 <= qt) {
            stageKV(kc + 1, (kc + 1) & 1);
            CP_WAIT1();
        } else {
            CP_WAIT0();
        }
        __syncthreads();

        const uint32_t tKb = sbK + (kc & 1) * (F_KT * 2);
        const uint32_t tVb = sbV + (kc & 1) * (F_VT * 2);
        const bool diag = (kc == qt);

        for (int qq = 0; qq < 4; ++qq) {
            float sa[4][4] = {};
#pragma unroll
            for (int ks = 0; ks < 4; ++ks)
#pragma unroll
                for (int ntp = 0; ntp < 2; ++ntp) {
                    uint32_t addr = tKb + (uint32_t)(
                        ((qq * 32 + ntp * 16 + (lt >> 1) * 8 + lr) * 72 +
                         ks * 16 + (lt & 1) * 8) * 2);
                    uint32_t b00, b01, b10, b11;
                    ldsm_x4(b00, b01, b10, b11, addr);
                    mma16816(sa[2 * ntp],     qf[ks], b00, b01);
                    mma16816(sa[2 * ntp + 1], qf[ks], b10, b11);
                }

            uint32_t mw0 = g_mpack[wb0 + kc * 4 + qq];
            uint32_t mw1 = g_mpack[wb1 + kc * 4 + qq];
            uint32_t ehr0[4], ehr1[4];
            if (diag) {
#pragma unroll
                for (int nt = 0; nt < 4; ++nt) {
                    int kg = kc * 128 + qq * 32 + nt * 8 + tig2;
                    int bp = nt * 8 + tig2;
                    __half2 t0 = __floats2half2_rn(sa[nt][0] * CEXP,
                                                   sa[nt][1] * CEXP);
                    __half2 t1 = __floats2half2_rn(sa[nt][2] * CEXP,
                                                   sa[nt][3] * CEXP);
                    uint32_t e0 = ex2_h2(*(uint32_t*)&t0);
                    uint32_t e1 = ex2_h2(*(uint32_t*)&t1);
                    uint32_t ca0 = (kg <= qr0 ? 0x0000FFFFu : 0u) |
                                   (kg + 1 <= qr0 ? 0xFFFF0000u : 0u);
                    uint32_t ca1 = (kg <= qr1 ? 0x0000FFFFu : 0u) |
                                   (kg + 1 <= qr1 ? 0xFFFF0000u : 0u);
                    e0 &= ca0;
                    e1 &= ca1;
                    Z0 += zsum2(e0);
                    Z1 += zsum2(e1);
                    uint32_t mm0 = (((mw0 >> bp) & 1) ? 0x0000FFFFu : 0u) |
                                   (((mw0 >> (bp + 1)) & 1) ? 0xFFFF0000u : 0u);
                    uint32_t mm1 = (((mw1 >> bp) & 1) ? 0x0000FFFFu : 0u) |
                                   (((mw1 >> (bp + 1)) & 1) ? 0xFFFF0000u : 0u);
                    ehr0[nt] = e0 & ~mm0;
                    ehr1[nt] = e1 & ~mm1;
                }
            } else {
#pragma unroll
                for (int nt = 0; nt < 4; ++nt) {
                    int bp = nt * 8 + tig2;
                    __half2 t0 = __floats2half2_rn(sa[nt][0] * CEXP,
                                                   sa[nt][1] * CEXP);
                    __half2 t1 = __floats2half2_rn(sa[nt][2] * CEXP,
                                                   sa[nt][3] * CEXP);
                    uint32_t e0 = ex2_h2(*(uint32_t*)&t0);
                    uint32_t e1 = ex2_h2(*(uint32_t*)&t1);
                    Z0 += zsum2(e0);
                    Z1 += zsum2(e1);
                    uint32_t mm0 = (((mw0 >> bp) & 1) ? 0x0000FFFFu : 0u) |
                                   (((mw0 >> (bp + 1)) & 1) ? 0xFFFF0000u : 0u);
                    uint32_t mm1 = (((mw1 >> bp) & 1) ? 0x0000FFFFu : 0u) |
                                   (((mw1 >> (bp + 1)) & 1) ? 0xFFFF0000u : 0u);
                    ehr0[nt] = e0 & ~mm0;
                    ehr1[nt] = e1 & ~mm1;
                }
            }
#pragma unroll
            for (int k2 = 0; k2 < 2; ++k2) {
                uint32_t ah[4] = {ehr0[2 * k2], ehr1[2 * k2],
                                  ehr0[2 * k2 + 1], ehr1[2 * k2 + 1]};
#pragma unroll
                for (int dnp = 0; dnp < 4; ++dnp) {
                    uint32_t addr = tVb + (uint32_t)(
                        ((dnp * 16 + (lt >> 1) * 8 + lr) * 136 +
                         qq * 32 + k2 * 16 + (lt & 1) * 8) * 2);
                    uint32_t b00, b01, b10, b11;
                    ldsm_x4(b00, b01, b10, b11, addr);
                    mma16816(o[2 * dnp],     ah, b00, b01);
                    mma16816(o[2 * dnp + 1], ah, b10, b11);
                }
            }
        }
        __syncthreads();
    }

    Z0 += __shfl_xor_sync(0xffffffffu, Z0, 1);
    Z0 += __shfl_xor_sync(0xffffffffu, Z0, 2);
    Z1 += __shfl_xor_sync(0xffffffffu, Z1, 1);
    Z1 += __shfl_xor_sync(0xffffffffu, Z1, 2);
    float i0 = 1.f / Z0, i1 = 1.f / Z1;

#pragma unroll
    for (int dn = 0; dn < 8; ++dn) {
        int d = h * kHD + dn * 8 + tig2;
        size_t r0 = (size_t)(b * kS + qr0) * kD + d;
        size_t r1 = (size_t)(b * kS + qr1) * kD + d;
        uint32_t pw0 = *(const uint32_t*)&g_oh[r0];
        uint32_t pw1 = *(const uint32_t*)&g_oh[r1];
        float2 p0 = __half22float2(*(__half2*)&pw0);
        float2 p1 = __half22float2(*(__half2*)&pw1);
        *(uint32_t*)&g_ah[r0] =
            packround(p0.x + o[dn][0] * i0, p0.y + o[dn][1] * i0);
        *(uint32_t*)&g_ah[r1] =
            packround(p1.x + o[dn][2] * i1, p1.y + o[dn][3] * i1);
    }
}

// ---------------------------------------------------------------------------
extern "C" void kernel_launch(void* const* d_in, const int* in_sizes, int n_in,
                              void* d_out, int out_size)
{
    const float* x       = (const float*)d_in[0];
    const float* w_attn  = (const float*)d_in[1];
    const float* b_attn  = (const float*)d_in[2];
    const float* w_proj  = (const float*)d_in[3];
    const float* b_proj  = (const float*)d_in[4];
    const float* ov      = (const float*)d_in[5];
    const void*  msk     = (const void*)d_in[6];

    float* out = (float*)d_out;
    float* presentK = out + (size_t)kM * kD;
    float* presentV = presentK + (size_t)kB * kH * kS * kHD;

    __half *xh, *ah, *wth, *pth;
    cudaGetSymbolAddress((void**)&xh, g_xh);
    cudaGetSymbolAddress((void**)&ah, g_ah);
    cudaGetSymbolAddress((void**)&wth, g_wth);
    cudaGetSymbolAddress((void**)&pth, g_pth);

    cudaFuncSetAttribute(mma_gemm_kernel,
                         cudaFuncAttributeMaxDynamicSharedMemorySize,
                         GEMM_SMEM_BYTES);
    cudaFuncSetAttribute(flash_kernel,
                         cudaFuncAttributeMaxDynamicSharedMemorySize,
                         FLASH_SMEM_BYTES);
    cudaFuncSetAttribute(ov_kernel,
                         cudaFuncAttributeMaxDynamicSharedMemorySize,
                         OV_SMEM_BYTES);

    // 0) mask classification + bit-pack + fused operand prep
    detect_mask_kind_kernel<<<1, 256>>>((const unsigned int*)msk);
    pack_mask_kernel<<<(kH * kS * kS) / 256, 256>>>(msk);
    prep_kernel<<<PREP_ROUND + PREP_WA + PREP_WP, 256>>>(x, w_attn, w_proj);

    // 1) QKV GEMM -> present fp32 + q/k fp16 + V transposed fp16 (fused)
    mma_gemm_kernel<<<dim3(3 * kD / 128, kM / 128), 256, GEMM_SMEM_BYTES>>>(
        xh, wth, b_attn, nullptr, kM, 3 * kD, kD, 1, presentK, presentV);

    // 2) override term -> g_oh (fp16, batch-shared)
    ov_kernel<<<dim3(kS / 64, kH), 256, OV_SMEM_BYTES>>>(ov);

    // 3) flash: adds softmax term, writes fp16 a directly
    flash_kernel<<<dim3(kS / 128, kH, kB), 256, FLASH_SMEM_BYTES>>>();

    // 4) output projection
    mma_gemm_kernel<<<dim3(kD / 128, kM / 128), 256, GEMM_SMEM_BYTES>>>(
        ah, pth, b_proj, out, kM, kD, kD, 0, nullptr, nullptr);
}